// round 10
// baseline (speedup 1.0000x reference)
#include <cuda_runtime.h>
#include <cuda_fp16.h>
#include <math.h>
#include <stdint.h>

#define NSEQ 2048
#define HID  2048
#define NH   32
#define DK   128
#define PROJ 4096
#define QKVN (3 * PROJ)
#define QSCALE 0.08838834764831843f     // 128^-0.5

#define NS_COMB   288                    // Wfa(128) + Wga(128) + Wb(32)
#define NS_PAD    384

// ---- GEMM tiling ----
#define BM 128
#define BN 128
#define BK 32
#define MATB   (128 * 64)                // one matrix tile: 128 rows x 64B = 8KB
#define STAGEB (3 * MATB)                // Ah,Al,Bh = 24KB
#define NSTG   4
#define SMEMB  (NSTG * STAGEB)           // 96KB -> 2 CTAs/SM

// ---------------- scratch (device globals; no allocation allowed) ----------------
__device__ __align__(256) float g_QKVp[NSEQ * QKVN];
__device__ __align__(256) float g_Qc[NSEQ * PROJ];
__device__ __align__(256) float g_Kc[NSEQ * PROJ];
__device__ __align__(256) float g_Vc[NSEQ * PROJ];
__device__ __align__(256) float g_F[NSEQ * PROJ];      // exp(g) written by GEMM epilogue
__device__ __align__(256) float g_GATE[NSEQ * PROJ];
__device__ __align__(256) float g_CORE[NSEQ * PROJ];
__device__ __align__(256) float g_BETA[NSEQ * 32];     // raw beta logits (compact)

__device__ __align__(256) __half g_hsh[NSEQ * HID];
__device__ __align__(256) __half g_hsl[NSEQ * HID];
__device__ __align__(256) __half g_Wqkvh[QKVN * HID];
__device__ __align__(256) __half g_Woh[HID * PROJ];
__device__ __align__(256) __half g_Wfbh[PROJ * DK];
__device__ __align__(256) __half g_Wgbh[PROJ * DK];
__device__ __align__(256) __half g_WSh[NS_PAD * HID];
__device__ __align__(256) __half g_FAh[NSEQ * DK];
__device__ __align__(256) __half g_FAl[NSEQ * DK];
__device__ __align__(256) __half g_GAh[NSEQ * DK];
__device__ __align__(256) __half g_GAl[NSEQ * DK];
__device__ __align__(256) __half g_COREh[NSEQ * PROJ];
__device__ __align__(256) __half g_COREl[NSEQ * PROJ];

// ============================ helpers (sm_80-portable PTX only) ============================
__device__ __forceinline__ uint32_t smem_u32(const void* p) {
  return (uint32_t)__cvta_generic_to_shared(p);
}
__device__ __forceinline__ void cp_async16(uint32_t dst, const void* src) {
  asm volatile("cp.async.cg.shared.global [%0], [%1], 16;" :: "r"(dst), "l"(src) : "memory");
}
__device__ __forceinline__ void cp_commit() {
  asm volatile("cp.async.commit_group;" ::: "memory");
}
template<int N> __device__ __forceinline__ void cp_wait() {
  asm volatile("cp.async.wait_group %0;" :: "n"(N) : "memory");
}
__device__ __forceinline__ void ldm_x4(uint32_t* r, uint32_t addr) {
  asm volatile("ldmatrix.sync.aligned.m8n8.x4.shared.b16 {%0,%1,%2,%3}, [%4];"
               : "=r"(r[0]), "=r"(r[1]), "=r"(r[2]), "=r"(r[3]) : "r"(addr));
}
__device__ __forceinline__ void mma16816(float* c, const uint32_t* a,
                                         uint32_t b0, uint32_t b1) {
  asm volatile(
      "mma.sync.aligned.m16n8k16.row.col.f32.f16.f16.f32 "
      "{%0,%1,%2,%3}, {%4,%5,%6,%7}, {%8,%9}, {%0,%1,%2,%3};"
      : "+f"(c[0]), "+f"(c[1]), "+f"(c[2]), "+f"(c[3])
      : "r"(a[0]), "r"(a[1]), "r"(a[2]), "r"(a[3]), "r"(b0), "r"(b1));
}
__device__ __forceinline__ uint16_t h_bits(__half h) {
  return *reinterpret_cast<uint16_t*>(&h);
}
__device__ __forceinline__ uint32_t pack_f16x2(float a, float b) {
  __half ha = __float2half_rn(a), hb = __float2half_rn(b);
  return (uint32_t)h_bits(ha) | ((uint32_t)h_bits(hb) << 16);
}
// 64B-row swizzle for GEMM smem
__device__ __forceinline__ uint32_t sw64(int row, int kc) {
  return (uint32_t)(row * 64 + ((kc ^ ((row >> 1) & 3)) << 4));
}

// ======================= fp16 hi/lo 2-pass GEMM (mma.sync + ldmatrix) =======================
// C = A*B^T ; 2 passes Ah*Bh + Al*Bh.
// EPI: 0 plain fp32, 1 decay-gate fp32, 2 fused FA/GA fp16-split + compact beta.
__device__ __forceinline__ void ld_stage(uint32_t sb, int slot, int kt, int tid,
                                         const char* a_h, const char* a_l,
                                         const char* b_h, size_t kbytes) {
  const uint32_t st = sb + (uint32_t)slot * STAGEB;
#pragma unroll
  for (int i = 0; i < 2; i++) {
    const int chunk = i * 256 + tid;
    const int row = chunk >> 2, kc = chunk & 3;
    const uint32_t so = sw64(row, kc);
    const size_t go = (size_t)row * kbytes + (size_t)kt * 64 + (size_t)(kc << 4);
    cp_async16(st + so,            a_h + go);
    cp_async16(st + MATB + so,     a_l + go);
    cp_async16(st + 2 * MATB + so, b_h + go);
  }
  cp_commit();
}

template <int EPI>
__global__ void __launch_bounds__(256, 2) gemm_f16s(
    const __half* __restrict__ Ah, const __half* __restrict__ Al,
    const __half* __restrict__ Bh,
    float* __restrict__ C, int Nn, int K, int ldc,
    const float* __restrict__ dt_bias, const float* __restrict__ A_log,
    __half* __restrict__ h1, __half* __restrict__ l1,
    __half* __restrict__ h2, __half* __restrict__ l2) {
  extern __shared__ char sm[];
  const int tid = threadIdx.x;
  const int bm = blockIdx.y * BM, bn = blockIdx.x * BN;
  const uint32_t sb = smem_u32(sm);

  const int lane = tid & 31, warp = tid >> 5;
  const int l16 = lane & 15, lh = lane >> 4;
  const int wR = warp >> 2;
  const int wC = warp & 3;

  const size_t kbytes = (size_t)K * 2;
  const char* a_h = (const char*)Ah + (size_t)bm * kbytes;
  const char* a_l = (const char*)Al + (size_t)bm * kbytes;
  const char* b_h = (const char*)Bh + (size_t)bn * kbytes;

  float acc[4][4][4];
#pragma unroll
  for (int i = 0; i < 4; i++)
#pragma unroll
    for (int j = 0; j < 4; j++)
#pragma unroll
      for (int r = 0; r < 4; r++) acc[i][j][r] = 0.f;

  const int KT = K / BK;
  for (int s = 0; s < NSTG - 1 && s < KT; s++)
    ld_stage(sb, s, s, tid, a_h, a_l, b_h, kbytes);

#pragma unroll 1
  for (int kt = 0; kt < KT; kt++) {
    const int slot = kt % NSTG;
    int pend = KT - 1 - kt; if (pend > NSTG - 2) pend = NSTG - 2;
    if (pend >= 2) cp_wait<2>(); else if (pend == 1) cp_wait<1>(); else cp_wait<0>();
    __syncthreads();

    const int nk = kt + NSTG - 1;
    if (nk < KT) ld_stage(sb, nk % NSTG, nk, tid, a_h, a_l, b_h, kbytes);

    const uint32_t st = sb + (uint32_t)slot * STAGEB;
#pragma unroll
    for (int kk = 0; kk < 2; kk++) {
      const int kc = kk * 2 + lh;
      uint32_t afh[4][4], afl[4][4];
#pragma unroll
      for (int mt = 0; mt < 4; mt++) {
        const int arow = wR * 64 + mt * 16 + l16;
        const uint32_t ao = st + sw64(arow, kc);
        ldm_x4(afh[mt], ao);
        ldm_x4(afl[mt], ao + MATB);
      }
      uint32_t bfh[2][4];
#pragma unroll
      for (int p = 0; p < 2; p++) {
        const int brow = wC * 32 + p * 16 + l16;
        ldm_x4(bfh[p], st + 2 * MATB + sw64(brow, kc));
      }
#pragma unroll
      for (int p = 0; p < 2; p++) {
#pragma unroll
        for (int mt = 0; mt < 4; mt++) {
          mma16816(acc[mt][2 * p],     afh[mt], bfh[p][0], bfh[p][2]);
          mma16816(acc[mt][2 * p],     afl[mt], bfh[p][0], bfh[p][2]);
          mma16816(acc[mt][2 * p + 1], afh[mt], bfh[p][1], bfh[p][3]);
          mma16816(acc[mt][2 * p + 1], afl[mt], bfh[p][1], bfh[p][3]);
        }
      }
    }
  }

  // epilogue
  const int gid = lane >> 2, tig = lane & 3;
#pragma unroll
  for (int mt = 0; mt < 4; mt++) {
    const int row = bm + wR * 64 + mt * 16 + gid;
#pragma unroll
    for (int nt = 0; nt < 4; nt++) {
      const int col = bn + wC * 32 + nt * 8 + tig * 2;
      if (col >= Nn) continue;
      float v[4] = {acc[mt][nt][0], acc[mt][nt][1], acc[mt][nt][2], acc[mt][nt][3]};
      if (EPI == 1) {
        const float d0 = dt_bias[col], d1 = dt_bias[col + 1];
        const float na = -expf(A_log[col >> 7]);
#pragma unroll
        for (int r = 0; r < 4; r++) {
          float x = v[r] + ((r & 1) ? d1 : d0);
          float sp = (x > 20.f) ? x : log1pf(expf(x));
          v[r] = expf(na * sp);
        }
        *reinterpret_cast<float2*>(C + (size_t)row * ldc + col) = make_float2(v[0], v[1]);
        *reinterpret_cast<float2*>(C + (size_t)(row + 8) * ldc + col) = make_float2(v[2], v[3]);
      } else if (EPI == 2) {
        if (col < 256) {
          __half* hb = (col < 128) ? h1 : h2;
          __half* lb = (col < 128) ? l1 : l2;
          const int cc = col & 127;
#pragma unroll
          for (int r = 0; r < 4; r += 2) {
            const size_t o = (size_t)(row + (r ? 8 : 0)) * 128 + cc;
            float hi0f = __half2float(__float2half_rn(v[r]));
            float hi1f = __half2float(__float2half_rn(v[r + 1]));
            *reinterpret_cast<uint32_t*>(hb + o) = pack_f16x2(v[r], v[r + 1]);
            *reinterpret_cast<uint32_t*>(lb + o) = pack_f16x2(v[r] - hi0f, v[r + 1] - hi1f);
          }
        } else {
          const int cc = col - 256;
          *reinterpret_cast<float2*>(C + (size_t)row * 32 + cc) = make_float2(v[0], v[1]);
          *reinterpret_cast<float2*>(C + (size_t)(row + 8) * 32 + cc) = make_float2(v[2], v[3]);
        }
      } else {
        *reinterpret_cast<float2*>(C + (size_t)row * ldc + col) = make_float2(v[0], v[1]);
        *reinterpret_cast<float2*>(C + (size_t)(row + 8) * ldc + col) = make_float2(v[2], v[3]);
      }
    }
  }
}

// ======================= fp32 -> fp16 hi/lo split (vectorized x4; lo optional) =======================
__global__ void __launch_bounds__(256) split_f16_kernel(
    const float* __restrict__ src,
    __half* __restrict__ hi, __half* __restrict__ lo, int total4) {
  int i = blockIdx.x * 256 + threadIdx.x;
  if (i >= total4) return;
  const int idx = i * 4;
  const float4 x = *reinterpret_cast<const float4*>(src + idx);
  uint2 hw;
  hw.x = pack_f16x2(x.x, x.y);
  hw.y = pack_f16x2(x.z, x.w);
  *reinterpret_cast<uint2*>(hi + idx) = hw;
  if (lo) {
    __half h0 = __float2half_rn(x.x), h1 = __float2half_rn(x.y);
    __half h2 = __float2half_rn(x.z), h3 = __float2half_rn(x.w);
    uint2 lw;
    lw.x = pack_f16x2(x.x - __half2float(h0), x.y - __half2float(h1));
    lw.y = pack_f16x2(x.z - __half2float(h2), x.w - __half2float(h3));
    *reinterpret_cast<uint2*>(lo + idx) = lw;
  }
}

// stacked small-weight matrix [Wfa;Wga;Wb;zeros] -> fp16 hi [384, HID]
__global__ void __launch_bounds__(256) ws_build_kernel(
    const float* __restrict__ Wfa, const float* __restrict__ Wga,
    const float* __restrict__ Wb, __half* __restrict__ hi) {
  int idx = blockIdx.x * 256 + threadIdx.x;
  if (idx >= NS_PAD * HID) return;
  int r = idx / HID, c = idx - r * HID;
  float x = 0.f;
  if (r < 128) x = Wfa[r * HID + c];
  else if (r < 256) x = Wga[(r - 128) * HID + c];
  else if (r < NS_COMB) x = Wb[(r - 256) * HID + c];
  hi[idx] = __float2half_rn(x);
}

// -------- fused depthwise causal conv(K=4) + SiLU for Q,K,V in one launch --------
__global__ void __launch_bounds__(128) conv_silu_fused_kernel(
    const float* __restrict__ QKV,
    const float* __restrict__ Wq, const float* __restrict__ Wk, const float* __restrict__ Wv,
    float* __restrict__ Qc, float* __restrict__ Kc, float* __restrict__ Vc) {
  const int type = blockIdx.x >> 5;
  const int h = blockIdx.x & 31;
  const int n = blockIdx.y;
  const int tid = threadIdx.x;
  const int c = h * DK + tid;
  const float* W = (type == 0) ? Wq : (type == 1) ? Wk : Wv;
  float* Y = (type == 0) ? Qc : (type == 1) ? Kc : Vc;
  const float* X = QKV + type * PROJ;

  float y = 0.f;
#pragma unroll
  for (int i = 0; i < 4; i++) {
    int nn = n - 3 + i;
    if (nn >= 0) y = fmaf(X[(size_t)nn * QKVN + c], W[c * 4 + i], y);
  }
  y = y / (1.f + expf(-y));  // SiLU
  if (type < 2) {
    __shared__ float red[4];
    float ss = y * y;
#pragma unroll
    for (int o = 16; o > 0; o >>= 1) ss += __shfl_xor_sync(0xffffffffu, ss, o);
    if ((tid & 31) == 0) red[tid >> 5] = ss;
    __syncthreads();
    float tot = red[0] + red[1] + red[2] + red[3];
    y *= rsqrtf(tot + 1e-6f) * ((type == 0) ? QSCALE : 1.0f);
  }
  Y[(size_t)n * PROJ + c] = y;
}

// ---------------- sequential delta-rule scan (vectorized LDS, single reduce) ----------------
// Shared layout: arr[kc*20 + j] (stride-20 rows -> conflict-free LDS.128 across 8 kc lanes).
// o_t = q.S_dec + (q.k)*delta ; S_new = S_dec + k (x) delta
__global__ void __launch_bounds__(256, 1) scan_kernel(
    const float* __restrict__ Q, const float* __restrict__ K,
    const float* __restrict__ V, const float* __restrict__ EG,
    const float* __restrict__ BRAW, int bstride, float* __restrict__ O) {
  const int h = blockIdx.x >> 2;
  const int vbase = (blockIdx.x & 3) << 5;
  const int tid = threadIdx.x;
  const int vloc = tid >> 3;
  const int kc = tid & 7;

  __shared__ __align__(16) float k_sh[2][160], q_sh[2][160], e_sh[2][160];
  __shared__ float v_sh[2][32];
  __shared__ float b_sh[2];

  float S[16];
#pragma unroll
  for (int j = 0; j < 16; j++) S[j] = 0.f;

  const size_t hb = (size_t)h * DK;
  float pk = 0.f, pe = 0.f, pq = 0.f, pv = 0.f, pb = 0.f;
  const int wslot = (tid >> 4) * 20 + (tid & 15);      // stride-20 row layout
  const int uslot = ((tid - 128) >> 4) * 20 + ((tid - 128) & 15);

  if (tid < 128) {
    pk = K[hb + tid];
    pe = EG[hb + tid];
  } else {
    int u = tid - 128;
    pq = Q[hb + u];
    if (u < 32) pv = V[hb + vbase + u];
    if (u == 127) pb = BRAW[h];
  }

  for (int t = 0; t < NSEQ; t++) {
    const int buf = t & 1;
    if (tid < 128) {
      k_sh[buf][wslot] = pk;
      e_sh[buf][wslot] = pe;
    } else {
      int u = tid - 128;
      q_sh[buf][uslot] = pq;
      if (u < 32) v_sh[buf][u] = pv;
      if (u == 127) b_sh[buf] = 1.f / (1.f + expf(-pb));
    }
    __syncthreads();

    if (t + 1 < NSEQ) {
      size_t off = (size_t)(t + 1) * PROJ + hb;
      if (tid < 128) {
        pk = K[off + tid];
        pe = EG[off + tid];
      } else {
        int u = tid - 128;
        pq = Q[off + u];
        if (u < 32) pv = V[off + vbase + u];
        if (u == 127) pb = BRAW[(size_t)(t + 1) * bstride + h];
      }
    }

    // vectorized fragment loads: 4x LDS.128 per array
    float4 kc4[4], ec4[4], qc4[4];
    const int rb = kc * 20;
#pragma unroll
    for (int c = 0; c < 4; c++) {
      kc4[c] = *reinterpret_cast<const float4*>(&k_sh[buf][rb + c * 4]);
      ec4[c] = *reinterpret_cast<const float4*>(&e_sh[buf][rb + c * 4]);
      qc4[c] = *reinterpret_cast<const float4*>(&q_sh[buf][rb + c * 4]);
    }
    const float* kf = reinterpret_cast<const float*>(kc4);
    const float* ef = reinterpret_cast<const float*>(ec4);
    const float* qf = reinterpret_cast<const float*>(qc4);

    float kv0 = 0.f, kv1 = 0.f, qs0 = 0.f, qs1 = 0.f, qk0 = 0.f, qk1 = 0.f;
#pragma unroll
    for (int j = 0; j < 16; j++) {
      const float s = S[j] * ef[j];
      S[j] = s;
      if (j & 1) {
        kv1 = fmaf(kf[j], s, kv1); qs1 = fmaf(qf[j], s, qs1); qk1 = fmaf(qf[j], kf[j], qk1);
      } else {
        kv0 = fmaf(kf[j], s, kv0); qs0 = fmaf(qf[j], s, qs0); qk0 = fmaf(qf[j], kf[j], qk0);
      }
    }
    float kv = kv0 + kv1, qs = qs0 + qs1, qk = qk0 + qk1;
#pragma unroll
    for (int o = 1; o < 8; o <<= 1) {
      kv += __shfl_xor_sync(0xffffffffu, kv, o);
      qs += __shfl_xor_sync(0xffffffffu, qs, o);
      qk += __shfl_xor_sync(0xffffffffu, qk, o);
    }

    const float delta = (v_sh[buf][vloc] - kv) * b_sh[buf];
    if (kc == 0) O[(size_t)t * PROJ + hb + vbase + vloc] = fmaf(qk, delta, qs);

#pragma unroll
    for (int j = 0; j < 16; j++) S[j] = fmaf(kf[j], delta, S[j]);
    __syncthreads();
  }
}

// -------- gated RMSNorm -> fp16 hi/lo directly (paired 4B stores) --------
__global__ void __launch_bounds__(128) out_gate_kernel(
    const float* __restrict__ CORE, const float* __restrict__ GATE,
    const float* __restrict__ onorm_w,
    __half* __restrict__ hi, __half* __restrict__ lo) {
  const int h = blockIdx.x;
  const int n = blockIdx.y;
  const int tid = threadIdx.x;
  const size_t idx = (size_t)n * PROJ + h * DK + tid;
  float cv = CORE[idx];
  float ss = cv * cv;
#pragma unroll
  for (int o = 16; o > 0; o >>= 1) ss += __shfl_xor_sync(0xffffffffu, ss, o);
  __shared__ float red[4];
  if ((tid & 31) == 0) red[tid >> 5] = ss;
  __syncthreads();
  float tot = red[0] + red[1] + red[2] + red[3];
  float r = rsqrtf(tot * (1.f / 128.f) + 1e-5f);
  float gt = GATE[idx];
  float v = cv * r * onorm_w[tid] / (1.f + expf(-gt));
  __half hh = __float2half_rn(v);
  float vl = v - __half2float(hh);
  uint32_t hw = h_bits(hh), lw = h_bits(__float2half_rn(vl));
  uint32_t hn = __shfl_down_sync(0xffffffffu, hw, 1);
  uint32_t ln = __shfl_down_sync(0xffffffffu, lw, 1);
  if ((tid & 1) == 0) {
    *reinterpret_cast<uint32_t*>(hi + idx) = hw | (hn << 16);
    *reinterpret_cast<uint32_t*>(lo + idx) = lw | (ln << 16);
  }
}

// ---------------- launch ----------------
extern "C" void kernel_launch(void* const* d_in, const int* in_sizes, int n_in,
                              void* d_out, int out_size) {
  const float* hs      = (const float*)d_in[0];
  const float* Wq      = (const float*)d_in[1];
  const float* Wk      = (const float*)d_in[2];
  const float* Wv      = (const float*)d_in[3];
  const float* conv_q  = (const float*)d_in[4];
  const float* conv_k  = (const float*)d_in[5];
  const float* conv_v  = (const float*)d_in[6];
  const float* Wfa     = (const float*)d_in[7];
  const float* Wfb     = (const float*)d_in[8];
  const float* dt_bias = (const float*)d_in[9];
  const float* Wb      = (const float*)d_in[10];
  const float* A_log   = (const float*)d_in[11];
  const float* Wga     = (const float*)d_in[12];
  const float* Wgb     = (const float*)d_in[13];
  const float* onorm_w = (const float*)d_in[14];
  const float* Wo      = (const float*)d_in[15];
  float* out = (float*)d_out;

  float *QKVp, *Qc, *Kc, *Vc, *F, *GATE, *CORE, *BETA;
  __half *hsh, *hsl, *Wqkvh, *Woh, *Wfbh, *Wgbh, *WSh;
  __half *FAh, *FAl, *GAh, *GAl, *COREh, *COREl;
  cudaGetSymbolAddress((void**)&QKVp,  g_QKVp);
  cudaGetSymbolAddress((void**)&Qc,    g_Qc);
  cudaGetSymbolAddress((void**)&Kc,    g_Kc);
  cudaGetSymbolAddress((void**)&Vc,    g_Vc);
  cudaGetSymbolAddress((void**)&F,     g_F);
  cudaGetSymbolAddress((void**)&GATE,  g_GATE);
  cudaGetSymbolAddress((void**)&CORE,  g_CORE);
  cudaGetSymbolAddress((void**)&BETA,  g_BETA);
  cudaGetSymbolAddress((void**)&hsh,   g_hsh);
  cudaGetSymbolAddress((void**)&hsl,   g_hsl);
  cudaGetSymbolAddress((void**)&Wqkvh, g_Wqkvh);
  cudaGetSymbolAddress((void**)&Woh,   g_Woh);
  cudaGetSymbolAddress((void**)&Wfbh,  g_Wfbh);
  cudaGetSymbolAddress((void**)&Wgbh,  g_Wgbh);
  cudaGetSymbolAddress((void**)&WSh,   g_WSh);
  cudaGetSymbolAddress((void**)&FAh,   g_FAh);
  cudaGetSymbolAddress((void**)&FAl,   g_FAl);
  cudaGetSymbolAddress((void**)&GAh,   g_GAh);
  cudaGetSymbolAddress((void**)&GAl,   g_GAl);
  cudaGetSymbolAddress((void**)&COREh, g_COREh);
  cudaGetSymbolAddress((void**)&COREl, g_COREl);

  cudaFuncSetAttribute(gemm_f16s<0>, cudaFuncAttributeMaxDynamicSharedMemorySize, SMEMB);
  cudaFuncSetAttribute(gemm_f16s<1>, cudaFuncAttributeMaxDynamicSharedMemorySize, SMEMB);
  cudaFuncSetAttribute(gemm_f16s<2>, cudaFuncAttributeMaxDynamicSharedMemorySize, SMEMB);

  // ---- split conversions (vectorized x4) ----
  int T4;
  T4 = NSEQ * HID / 4;
  split_f16_kernel<<<(T4 + 255) / 256, 256>>>(hs, hsh, hsl, T4);
  T4 = PROJ * HID / 4;
  split_f16_kernel<<<(T4 + 255) / 256, 256>>>(Wq, Wqkvh, nullptr, T4);
  split_f16_kernel<<<(T4 + 255) / 256, 256>>>(Wk, Wqkvh + (size_t)PROJ * HID, nullptr, T4);
  split_f16_kernel<<<(T4 + 255) / 256, 256>>>(Wv, Wqkvh + (size_t)2 * PROJ * HID, nullptr, T4);
  T4 = HID * PROJ / 4;
  split_f16_kernel<<<(T4 + 255) / 256, 256>>>(Wo, Woh, nullptr, T4);
  T4 = PROJ * DK / 4;
  split_f16_kernel<<<(T4 + 255) / 256, 256>>>(Wfb, Wfbh, nullptr, T4);
  split_f16_kernel<<<(T4 + 255) / 256, 256>>>(Wgb, Wgbh, nullptr, T4);
  ws_build_kernel<<<(NS_PAD * HID + 255) / 256, 256>>>(Wfa, Wga, Wb, WSh);

  // ---- tensor-core GEMMs: fused QKV + fused small (FA|GA|beta with split epilogue) ----
  gemm_f16s<0><<<dim3(QKVN / 128, NSEQ / 128), 256, SMEMB>>>(
      hsh, hsl, Wqkvh, QKVp, QKVN, HID, QKVN, nullptr, nullptr,
      nullptr, nullptr, nullptr, nullptr);
  gemm_f16s<2><<<dim3(3, NSEQ / 128), 256, SMEMB>>>(
      hsh, hsl, WSh, BETA, NS_COMB, HID, 32, nullptr, nullptr,
      FAh, FAl, GAh, GAl);

  // ---- fused conv + silu (+ l2 norm for q,k) ----
  conv_silu_fused_kernel<<<dim3(3 * NH, NSEQ), 128>>>(QKVp, conv_q, conv_k, conv_v, Qc, Kc, Vc);

  // ---- low-rank second projections (K=128), F with fused decay epilogue ----
  gemm_f16s<1><<<dim3(PROJ / 128, NSEQ / 128), 256, SMEMB>>>(
      FAh, FAl, Wfbh, F, PROJ, DK, PROJ, dt_bias, A_log,
      nullptr, nullptr, nullptr, nullptr);
  gemm_f16s<0><<<dim3(PROJ / 128, NSEQ / 128), 256, SMEMB>>>(
      GAh, GAl, Wgbh, GATE, PROJ, DK, PROJ, nullptr, nullptr,
      nullptr, nullptr, nullptr, nullptr);

  // ---- recurrent scan ----
  scan_kernel<<<NH * 4, 256>>>(Qc, Kc, Vc, F, BETA, 32, CORE);

  // ---- gated rmsnorm -> fp16 hi/lo directly ----
  dim3 gConv(NH, NSEQ);
  out_gate_kernel<<<gConv, 128>>>(CORE, GATE, onorm_w, COREh, COREl);

  // ---- output projection ----
  gemm_f16s<0><<<dim3(HID / 128, NSEQ / 128), 256, SMEMB>>>(
      COREh, COREl, Woh, out, HID, PROJ, HID, nullptr, nullptr,
      nullptr, nullptr, nullptr, nullptr);
}

// round 11
// speedup vs baseline: 1.1345x; 1.1345x over previous
#include <cuda_runtime.h>
#include <cuda_fp16.h>
#include <math.h>
#include <stdint.h>

#define NSEQ 2048
#define HID  2048
#define NH   32
#define DK   128
#define PROJ 4096
#define QKVN (3 * PROJ)
#define QSCALE 0.08838834764831843f     // 128^-0.5

#define NS_COMB   288                    // Wfa(128) + Wga(128) + Wb(32)
#define NS_PAD    384

// ---- GEMM tiling ----
#define BM 128
#define BN 128
#define BK 32
#define MATB   (128 * 64)                // one matrix tile: 128 rows x 64B = 8KB
#define STAGEB (3 * MATB)                // Ah,Al,Bh = 24KB
#define NSTG   4
#define SMEMB  (NSTG * STAGEB)           // 96KB -> 2 CTAs/SM

// ---------------- scratch (device globals; no allocation allowed) ----------------
__device__ __align__(256) float g_QKVp[NSEQ * QKVN];
__device__ __align__(256) float g_Qc[NSEQ * PROJ];
__device__ __align__(256) float g_Kc[NSEQ * PROJ];
__device__ __align__(256) float g_Vc[NSEQ * PROJ];
__device__ __align__(256) float g_F[NSEQ * PROJ];      // exp(g) written by GEMM epilogue
__device__ __align__(256) float g_GATE[NSEQ * PROJ];
__device__ __align__(256) float g_CORE[NSEQ * PROJ];
__device__ __align__(256) float g_BETA[NSEQ * 32];     // raw beta logits (compact)

__device__ __align__(256) __half g_hsh[NSEQ * HID];
__device__ __align__(256) __half g_hsl[NSEQ * HID];
__device__ __align__(256) __half g_Wqkvh[QKVN * HID];
__device__ __align__(256) __half g_Woh[HID * PROJ];
__device__ __align__(256) __half g_Wfbh[PROJ * DK];
__device__ __align__(256) __half g_Wgbh[PROJ * DK];
__device__ __align__(256) __half g_WSh[NS_PAD * HID];
__device__ __align__(256) __half g_FAh[NSEQ * DK];
__device__ __align__(256) __half g_FAl[NSEQ * DK];
__device__ __align__(256) __half g_GAh[NSEQ * DK];
__device__ __align__(256) __half g_GAl[NSEQ * DK];
__device__ __align__(256) __half g_COREh[NSEQ * PROJ];
__device__ __align__(256) __half g_COREl[NSEQ * PROJ];

// ============================ helpers (sm_80-portable PTX only) ============================
__device__ __forceinline__ uint32_t smem_u32(const void* p) {
  return (uint32_t)__cvta_generic_to_shared(p);
}
__device__ __forceinline__ void cp_async16(uint32_t dst, const void* src) {
  asm volatile("cp.async.cg.shared.global [%0], [%1], 16;" :: "r"(dst), "l"(src) : "memory");
}
__device__ __forceinline__ void cp_commit() {
  asm volatile("cp.async.commit_group;" ::: "memory");
}
template<int N> __device__ __forceinline__ void cp_wait() {
  asm volatile("cp.async.wait_group %0;" :: "n"(N) : "memory");
}
__device__ __forceinline__ void ldm_x4(uint32_t* r, uint32_t addr) {
  asm volatile("ldmatrix.sync.aligned.m8n8.x4.shared.b16 {%0,%1,%2,%3}, [%4];"
               : "=r"(r[0]), "=r"(r[1]), "=r"(r[2]), "=r"(r[3]) : "r"(addr));
}
__device__ __forceinline__ void mma16816(float* c, const uint32_t* a,
                                         uint32_t b0, uint32_t b1) {
  asm volatile(
      "mma.sync.aligned.m16n8k16.row.col.f32.f16.f16.f32 "
      "{%0,%1,%2,%3}, {%4,%5,%6,%7}, {%8,%9}, {%0,%1,%2,%3};"
      : "+f"(c[0]), "+f"(c[1]), "+f"(c[2]), "+f"(c[3])
      : "r"(a[0]), "r"(a[1]), "r"(a[2]), "r"(a[3]), "r"(b0), "r"(b1));
}
__device__ __forceinline__ uint16_t h_bits(__half h) {
  return *reinterpret_cast<uint16_t*>(&h);
}
__device__ __forceinline__ uint32_t pack_f16x2(float a, float b) {
  __half ha = __float2half_rn(a), hb = __float2half_rn(b);
  return (uint32_t)h_bits(ha) | ((uint32_t)h_bits(hb) << 16);
}
// 64B-row swizzle for GEMM smem
__device__ __forceinline__ uint32_t sw64(int row, int kc) {
  return (uint32_t)(row * 64 + ((kc ^ ((row >> 1) & 3)) << 4));
}

// ======================= fp16 hi/lo 2-pass GEMM (mma.sync + ldmatrix) =======================
// C = A*B^T ; 2 passes Ah*Bh + Al*Bh.
// EPI: 0 plain fp32, 1 decay-gate fp32, 2 fused FA/GA fp16-split + compact beta.
__device__ __forceinline__ void ld_stage(uint32_t sb, int slot, int kt, int tid,
                                         const char* a_h, const char* a_l,
                                         const char* b_h, size_t kbytes) {
  const uint32_t st = sb + (uint32_t)slot * STAGEB;
#pragma unroll
  for (int i = 0; i < 2; i++) {
    const int chunk = i * 256 + tid;
    const int row = chunk >> 2, kc = chunk & 3;
    const uint32_t so = sw64(row, kc);
    const size_t go = (size_t)row * kbytes + (size_t)kt * 64 + (size_t)(kc << 4);
    cp_async16(st + so,            a_h + go);
    cp_async16(st + MATB + so,     a_l + go);
    cp_async16(st + 2 * MATB + so, b_h + go);
  }
  cp_commit();
}

template <int EPI>
__global__ void __launch_bounds__(256, 2) gemm_f16s(
    const __half* __restrict__ Ah, const __half* __restrict__ Al,
    const __half* __restrict__ Bh,
    float* __restrict__ C, int Nn, int K, int ldc,
    const float* __restrict__ dt_bias, const float* __restrict__ A_log,
    __half* __restrict__ h1, __half* __restrict__ l1,
    __half* __restrict__ h2, __half* __restrict__ l2) {
  extern __shared__ char sm[];
  const int tid = threadIdx.x;
  const int bm = blockIdx.y * BM, bn = blockIdx.x * BN;
  const uint32_t sb = smem_u32(sm);

  const int lane = tid & 31, warp = tid >> 5;
  const int l16 = lane & 15, lh = lane >> 4;
  const int wR = warp >> 2;
  const int wC = warp & 3;

  const size_t kbytes = (size_t)K * 2;
  const char* a_h = (const char*)Ah + (size_t)bm * kbytes;
  const char* a_l = (const char*)Al + (size_t)bm * kbytes;
  const char* b_h = (const char*)Bh + (size_t)bn * kbytes;

  float acc[4][4][4];
#pragma unroll
  for (int i = 0; i < 4; i++)
#pragma unroll
    for (int j = 0; j < 4; j++)
#pragma unroll
      for (int r = 0; r < 4; r++) acc[i][j][r] = 0.f;

  const int KT = K / BK;
  for (int s = 0; s < NSTG - 1 && s < KT; s++)
    ld_stage(sb, s, s, tid, a_h, a_l, b_h, kbytes);

#pragma unroll 1
  for (int kt = 0; kt < KT; kt++) {
    const int slot = kt % NSTG;
    int pend = KT - 1 - kt; if (pend > NSTG - 2) pend = NSTG - 2;
    if (pend >= 2) cp_wait<2>(); else if (pend == 1) cp_wait<1>(); else cp_wait<0>();
    __syncthreads();

    const int nk = kt + NSTG - 1;
    if (nk < KT) ld_stage(sb, nk % NSTG, nk, tid, a_h, a_l, b_h, kbytes);

    const uint32_t st = sb + (uint32_t)slot * STAGEB;
#pragma unroll
    for (int kk = 0; kk < 2; kk++) {
      const int kc = kk * 2 + lh;
      uint32_t afh[4][4], afl[4][4];
#pragma unroll
      for (int mt = 0; mt < 4; mt++) {
        const int arow = wR * 64 + mt * 16 + l16;
        const uint32_t ao = st + sw64(arow, kc);
        ldm_x4(afh[mt], ao);
        ldm_x4(afl[mt], ao + MATB);
      }
      uint32_t bfh[2][4];
#pragma unroll
      for (int p = 0; p < 2; p++) {
        const int brow = wC * 32 + p * 16 + l16;
        ldm_x4(bfh[p], st + 2 * MATB + sw64(brow, kc));
      }
#pragma unroll
      for (int p = 0; p < 2; p++) {
#pragma unroll
        for (int mt = 0; mt < 4; mt++) {
          mma16816(acc[mt][2 * p],     afh[mt], bfh[p][0], bfh[p][2]);
          mma16816(acc[mt][2 * p],     afl[mt], bfh[p][0], bfh[p][2]);
          mma16816(acc[mt][2 * p + 1], afh[mt], bfh[p][1], bfh[p][3]);
          mma16816(acc[mt][2 * p + 1], afl[mt], bfh[p][1], bfh[p][3]);
        }
      }
    }
  }

  // epilogue
  const int gid = lane >> 2, tig = lane & 3;
#pragma unroll
  for (int mt = 0; mt < 4; mt++) {
    const int row = bm + wR * 64 + mt * 16 + gid;
#pragma unroll
    for (int nt = 0; nt < 4; nt++) {
      const int col = bn + wC * 32 + nt * 8 + tig * 2;
      if (col >= Nn) continue;
      float v[4] = {acc[mt][nt][0], acc[mt][nt][1], acc[mt][nt][2], acc[mt][nt][3]};
      if (EPI == 1) {
        const float d0 = dt_bias[col], d1 = dt_bias[col + 1];
        const float na = -expf(A_log[col >> 7]);
#pragma unroll
        for (int r = 0; r < 4; r++) {
          float x = v[r] + ((r & 1) ? d1 : d0);
          float sp = (x > 20.f) ? x : log1pf(expf(x));
          v[r] = expf(na * sp);
        }
        *reinterpret_cast<float2*>(C + (size_t)row * ldc + col) = make_float2(v[0], v[1]);
        *reinterpret_cast<float2*>(C + (size_t)(row + 8) * ldc + col) = make_float2(v[2], v[3]);
      } else if (EPI == 2) {
        if (col < 256) {
          __half* hb = (col < 128) ? h1 : h2;
          __half* lb = (col < 128) ? l1 : l2;
          const int cc = col & 127;
#pragma unroll
          for (int r = 0; r < 4; r += 2) {
            const size_t o = (size_t)(row + (r ? 8 : 0)) * 128 + cc;
            float hi0f = __half2float(__float2half_rn(v[r]));
            float hi1f = __half2float(__float2half_rn(v[r + 1]));
            *reinterpret_cast<uint32_t*>(hb + o) = pack_f16x2(v[r], v[r + 1]);
            *reinterpret_cast<uint32_t*>(lb + o) = pack_f16x2(v[r] - hi0f, v[r + 1] - hi1f);
          }
        } else {
          const int cc = col - 256;
          *reinterpret_cast<float2*>(C + (size_t)row * 32 + cc) = make_float2(v[0], v[1]);
          *reinterpret_cast<float2*>(C + (size_t)(row + 8) * 32 + cc) = make_float2(v[2], v[3]);
        }
      } else {
        *reinterpret_cast<float2*>(C + (size_t)row * ldc + col) = make_float2(v[0], v[1]);
        *reinterpret_cast<float2*>(C + (size_t)(row + 8) * ldc + col) = make_float2(v[2], v[3]);
      }
    }
  }
}

// ======================= fp32 -> fp16 hi/lo split (vectorized x4; lo optional) =======================
__global__ void __launch_bounds__(256) split_f16_kernel(
    const float* __restrict__ src,
    __half* __restrict__ hi, __half* __restrict__ lo, int total4) {
  int i = blockIdx.x * 256 + threadIdx.x;
  if (i >= total4) return;
  const int idx = i * 4;
  const float4 x = *reinterpret_cast<const float4*>(src + idx);
  uint2 hw;
  hw.x = pack_f16x2(x.x, x.y);
  hw.y = pack_f16x2(x.z, x.w);
  *reinterpret_cast<uint2*>(hi + idx) = hw;
  if (lo) {
    __half h0 = __float2half_rn(x.x), h1 = __float2half_rn(x.y);
    __half h2 = __float2half_rn(x.z), h3 = __float2half_rn(x.w);
    uint2 lw;
    lw.x = pack_f16x2(x.x - __half2float(h0), x.y - __half2float(h1));
    lw.y = pack_f16x2(x.z - __half2float(h2), x.w - __half2float(h3));
    *reinterpret_cast<uint2*>(lo + idx) = lw;
  }
}

// stacked small-weight matrix [Wfa;Wga;Wb;zeros] -> fp16 hi [384, HID]
__global__ void __launch_bounds__(256) ws_build_kernel(
    const float* __restrict__ Wfa, const float* __restrict__ Wga,
    const float* __restrict__ Wb, __half* __restrict__ hi) {
  int idx = blockIdx.x * 256 + threadIdx.x;
  if (idx >= NS_PAD * HID) return;
  int r = idx / HID, c = idx - r * HID;
  float x = 0.f;
  if (r < 128) x = Wfa[r * HID + c];
  else if (r < 256) x = Wga[(r - 128) * HID + c];
  else if (r < NS_COMB) x = Wb[(r - 256) * HID + c];
  hi[idx] = __float2half_rn(x);
}

// -------- fused depthwise causal conv(K=4) + SiLU for Q,K,V in one launch --------
__global__ void __launch_bounds__(128) conv_silu_fused_kernel(
    const float* __restrict__ QKV,
    const float* __restrict__ Wq, const float* __restrict__ Wk, const float* __restrict__ Wv,
    float* __restrict__ Qc, float* __restrict__ Kc, float* __restrict__ Vc) {
  const int type = blockIdx.x >> 5;
  const int h = blockIdx.x & 31;
  const int n = blockIdx.y;
  const int tid = threadIdx.x;
  const int c = h * DK + tid;
  const float* W = (type == 0) ? Wq : (type == 1) ? Wk : Wv;
  float* Y = (type == 0) ? Qc : (type == 1) ? Kc : Vc;
  const float* X = QKV + type * PROJ;

  float y = 0.f;
#pragma unroll
  for (int i = 0; i < 4; i++) {
    int nn = n - 3 + i;
    if (nn >= 0) y = fmaf(X[(size_t)nn * QKVN + c], W[c * 4 + i], y);
  }
  y = y / (1.f + expf(-y));  // SiLU
  if (type < 2) {
    __shared__ float red[4];
    float ss = y * y;
#pragma unroll
    for (int o = 16; o > 0; o >>= 1) ss += __shfl_xor_sync(0xffffffffu, ss, o);
    if ((tid & 31) == 0) red[tid >> 5] = ss;
    __syncthreads();
    float tot = red[0] + red[1] + red[2] + red[3];
    y *= rsqrtf(tot + 1e-6f) * ((type == 0) ? QSCALE : 1.0f);
  }
  Y[(size_t)n * PROJ + c] = y;
}

// ---------------- sequential delta-rule scan ----------------
// Depth-4 register prefetch (loop unrolled x4 -> compile-time slots), double-buffered
// shared with a SINGLE __syncthreads per step.
// o_t = q.S_dec + (q.k)*delta ; S_new = S_dec + k (x) delta
__global__ void __launch_bounds__(256, 1) scan_kernel(
    const float* __restrict__ Q, const float* __restrict__ K,
    const float* __restrict__ V, const float* __restrict__ EG,
    const float* __restrict__ BRAW, int bstride, float* __restrict__ O) {
  const int h = blockIdx.x >> 2;
  const int vbase = (blockIdx.x & 3) << 5;
  const int tid = threadIdx.x;
  const int vloc = tid >> 3;
  const int kc = tid & 7;

  __shared__ __align__(16) float k_sh[2][160], q_sh[2][160], e_sh[2][160];
  __shared__ float v_sh[2][32];
  __shared__ float b_sh[2];

  float S[16];
#pragma unroll
  for (int j = 0; j < 16; j++) S[j] = 0.f;

  const size_t hb = (size_t)h * DK;
  const int wslot = (tid >> 4) * 20 + (tid & 15);          // stride-20 row layout
  const int u = tid - 128;
  const int uslot = (u >> 4) * 20 + (u & 15);

  float pk[4], pe[4], pq[4], pv[4], pb[4];
#pragma unroll
  for (int d = 0; d < 4; d++) {
    const size_t off = (size_t)d * PROJ + hb;
    if (tid < 128) {
      pk[d] = K[off + tid];
      pe[d] = EG[off + tid];
    } else {
      pq[d] = Q[off + u];
      if (u < 32) pv[d] = V[off + vbase + u];
      if (u == 127) pb[d] = BRAW[(size_t)d * bstride + h];
    }
  }

#pragma unroll 1
  for (int t = 0; t < NSEQ; t += 4) {
#pragma unroll
    for (int j4 = 0; j4 < 4; j4++) {
      const int tt = t + j4;
      const int buf = j4 & 1;

      // publish step tt into smem buffer
      if (tid < 128) {
        k_sh[buf][wslot] = pk[j4];
        e_sh[buf][wslot] = pe[j4];
      } else {
        q_sh[buf][uslot] = pq[j4];
        if (u < 32) v_sh[buf][u] = pv[j4];
        if (u == 127) b_sh[buf] = 1.f / (1.f + expf(-pb[j4]));
      }
      __syncthreads();     // single barrier per step (double-buffered smem)

      // prefetch step tt+4 into the freed register slot
      if (tt + 4 < NSEQ) {
        const size_t off = (size_t)(tt + 4) * PROJ + hb;
        if (tid < 128) {
          pk[j4] = K[off + tid];
          pe[j4] = EG[off + tid];
        } else {
          pq[j4] = Q[off + u];
          if (u < 32) pv[j4] = V[off + vbase + u];
          if (u == 127) pb[j4] = BRAW[(size_t)(tt + 4) * bstride + h];
        }
      }

      // compute step tt
      float4 kc4[4], ec4[4], qc4[4];
      const int rb = kc * 20;
#pragma unroll
      for (int c = 0; c < 4; c++) {
        kc4[c] = *reinterpret_cast<const float4*>(&k_sh[buf][rb + c * 4]);
        ec4[c] = *reinterpret_cast<const float4*>(&e_sh[buf][rb + c * 4]);
        qc4[c] = *reinterpret_cast<const float4*>(&q_sh[buf][rb + c * 4]);
      }
      const float* kf = reinterpret_cast<const float*>(kc4);
      const float* ef = reinterpret_cast<const float*>(ec4);
      const float* qf = reinterpret_cast<const float*>(qc4);

      float kv0 = 0.f, kv1 = 0.f, qs0 = 0.f, qs1 = 0.f, qk0 = 0.f, qk1 = 0.f;
#pragma unroll
      for (int j = 0; j < 16; j++) {
        const float s = S[j] * ef[j];
        S[j] = s;
        if (j & 1) {
          kv1 = fmaf(kf[j], s, kv1); qs1 = fmaf(qf[j], s, qs1); qk1 = fmaf(qf[j], kf[j], qk1);
        } else {
          kv0 = fmaf(kf[j], s, kv0); qs0 = fmaf(qf[j], s, qs0); qk0 = fmaf(qf[j], kf[j], qk0);
        }
      }
      float kv = kv0 + kv1, qs = qs0 + qs1, qk = qk0 + qk1;
#pragma unroll
      for (int o = 1; o < 8; o <<= 1) {
        kv += __shfl_xor_sync(0xffffffffu, kv, o);
        qs += __shfl_xor_sync(0xffffffffu, qs, o);
        qk += __shfl_xor_sync(0xffffffffu, qk, o);
      }

      const float delta = (v_sh[buf][vloc] - kv) * b_sh[buf];
      if (kc == 0) O[(size_t)tt * PROJ + hb + vbase + vloc] = fmaf(qk, delta, qs);

#pragma unroll
      for (int j = 0; j < 16; j++) S[j] = fmaf(kf[j], delta, S[j]);
      // no trailing sync: next step writes the other buffer
    }
  }
}

// -------- gated RMSNorm -> fp16 hi/lo directly (paired 4B stores) --------
__global__ void __launch_bounds__(128) out_gate_kernel(
    const float* __restrict__ CORE, const float* __restrict__ GATE,
    const float* __restrict__ onorm_w,
    __half* __restrict__ hi, __half* __restrict__ lo) {
  const int h = blockIdx.x;
  const int n = blockIdx.y;
  const int tid = threadIdx.x;
  const size_t idx = (size_t)n * PROJ + h * DK + tid;
  float cv = CORE[idx];
  float ss = cv * cv;
#pragma unroll
  for (int o = 16; o > 0; o >>= 1) ss += __shfl_xor_sync(0xffffffffu, ss, o);
  __shared__ float red[4];
  if ((tid & 31) == 0) red[tid >> 5] = ss;
  __syncthreads();
  float tot = red[0] + red[1] + red[2] + red[3];
  float r = rsqrtf(tot * (1.f / 128.f) + 1e-5f);
  float gt = GATE[idx];
  float v = cv * r * onorm_w[tid] / (1.f + expf(-gt));
  __half hh = __float2half_rn(v);
  float vl = v - __half2float(hh);
  uint32_t hw = h_bits(hh), lw = h_bits(__float2half_rn(vl));
  uint32_t hn = __shfl_down_sync(0xffffffffu, hw, 1);
  uint32_t ln = __shfl_down_sync(0xffffffffu, lw, 1);
  if ((tid & 1) == 0) {
    *reinterpret_cast<uint32_t*>(hi + idx) = hw | (hn << 16);
    *reinterpret_cast<uint32_t*>(lo + idx) = lw | (ln << 16);
  }
}

// ---------------- launch ----------------
extern "C" void kernel_launch(void* const* d_in, const int* in_sizes, int n_in,
                              void* d_out, int out_size) {
  const float* hs      = (const float*)d_in[0];
  const float* Wq      = (const float*)d_in[1];
  const float* Wk      = (const float*)d_in[2];
  const float* Wv      = (const float*)d_in[3];
  const float* conv_q  = (const float*)d_in[4];
  const float* conv_k  = (const float*)d_in[5];
  const float* conv_v  = (const float*)d_in[6];
  const float* Wfa     = (const float*)d_in[7];
  const float* Wfb     = (const float*)d_in[8];
  const float* dt_bias = (const float*)d_in[9];
  const float* Wb      = (const float*)d_in[10];
  const float* A_log   = (const float*)d_in[11];
  const float* Wga     = (const float*)d_in[12];
  const float* Wgb     = (const float*)d_in[13];
  const float* onorm_w = (const float*)d_in[14];
  const float* Wo      = (const float*)d_in[15];
  float* out = (float*)d_out;

  float *QKVp, *Qc, *Kc, *Vc, *F, *GATE, *CORE, *BETA;
  __half *hsh, *hsl, *Wqkvh, *Woh, *Wfbh, *Wgbh, *WSh;
  __half *FAh, *FAl, *GAh, *GAl, *COREh, *COREl;
  cudaGetSymbolAddress((void**)&QKVp,  g_QKVp);
  cudaGetSymbolAddress((void**)&Qc,    g_Qc);
  cudaGetSymbolAddress((void**)&Kc,    g_Kc);
  cudaGetSymbolAddress((void**)&Vc,    g_Vc);
  cudaGetSymbolAddress((void**)&F,     g_F);
  cudaGetSymbolAddress((void**)&GATE,  g_GATE);
  cudaGetSymbolAddress((void**)&CORE,  g_CORE);
  cudaGetSymbolAddress((void**)&BETA,  g_BETA);
  cudaGetSymbolAddress((void**)&hsh,   g_hsh);
  cudaGetSymbolAddress((void**)&hsl,   g_hsl);
  cudaGetSymbolAddress((void**)&Wqkvh, g_Wqkvh);
  cudaGetSymbolAddress((void**)&Woh,   g_Woh);
  cudaGetSymbolAddress((void**)&Wfbh,  g_Wfbh);
  cudaGetSymbolAddress((void**)&Wgbh,  g_Wgbh);
  cudaGetSymbolAddress((void**)&WSh,   g_WSh);
  cudaGetSymbolAddress((void**)&FAh,   g_FAh);
  cudaGetSymbolAddress((void**)&FAl,   g_FAl);
  cudaGetSymbolAddress((void**)&GAh,   g_GAh);
  cudaGetSymbolAddress((void**)&GAl,   g_GAl);
  cudaGetSymbolAddress((void**)&COREh, g_COREh);
  cudaGetSymbolAddress((void**)&COREl, g_COREl);

  cudaFuncSetAttribute(gemm_f16s<0>, cudaFuncAttributeMaxDynamicSharedMemorySize, SMEMB);
  cudaFuncSetAttribute(gemm_f16s<1>, cudaFuncAttributeMaxDynamicSharedMemorySize, SMEMB);
  cudaFuncSetAttribute(gemm_f16s<2>, cudaFuncAttributeMaxDynamicSharedMemorySize, SMEMB);

  // ---- split conversions (vectorized x4) ----
  int T4;
  T4 = NSEQ * HID / 4;
  split_f16_kernel<<<(T4 + 255) / 256, 256>>>(hs, hsh, hsl, T4);
  T4 = PROJ * HID / 4;
  split_f16_kernel<<<(T4 + 255) / 256, 256>>>(Wq, Wqkvh, nullptr, T4);
  split_f16_kernel<<<(T4 + 255) / 256, 256>>>(Wk, Wqkvh + (size_t)PROJ * HID, nullptr, T4);
  split_f16_kernel<<<(T4 + 255) / 256, 256>>>(Wv, Wqkvh + (size_t)2 * PROJ * HID, nullptr, T4);
  T4 = HID * PROJ / 4;
  split_f16_kernel<<<(T4 + 255) / 256, 256>>>(Wo, Woh, nullptr, T4);
  T4 = PROJ * DK / 4;
  split_f16_kernel<<<(T4 + 255) / 256, 256>>>(Wfb, Wfbh, nullptr, T4);
  split_f16_kernel<<<(T4 + 255) / 256, 256>>>(Wgb, Wgbh, nullptr, T4);
  ws_build_kernel<<<(NS_PAD * HID + 255) / 256, 256>>>(Wfa, Wga, Wb, WSh);

  // ---- tensor-core GEMMs: fused QKV + fused small (FA|GA|beta with split epilogue) ----
  gemm_f16s<0><<<dim3(QKVN / 128, NSEQ / 128), 256, SMEMB>>>(
      hsh, hsl, Wqkvh, QKVp, QKVN, HID, QKVN, nullptr, nullptr,
      nullptr, nullptr, nullptr, nullptr);
  gemm_f16s<2><<<dim3(3, NSEQ / 128), 256, SMEMB>>>(
      hsh, hsl, WSh, BETA, NS_COMB, HID, 32, nullptr, nullptr,
      FAh, FAl, GAh, GAl);

  // ---- fused conv + silu (+ l2 norm for q,k) ----
  conv_silu_fused_kernel<<<dim3(3 * NH, NSEQ), 128>>>(QKVp, conv_q, conv_k, conv_v, Qc, Kc, Vc);

  // ---- low-rank second projections (K=128), F with fused decay epilogue ----
  gemm_f16s<1><<<dim3(PROJ / 128, NSEQ / 128), 256, SMEMB>>>(
      FAh, FAl, Wfbh, F, PROJ, DK, PROJ, dt_bias, A_log,
      nullptr, nullptr, nullptr, nullptr);
  gemm_f16s<0><<<dim3(PROJ / 128, NSEQ / 128), 256, SMEMB>>>(
      GAh, GAl, Wgbh, GATE, PROJ, DK, PROJ, nullptr, nullptr,
      nullptr, nullptr, nullptr, nullptr);

  // ---- recurrent scan ----
  scan_kernel<<<NH * 4, 256>>>(Qc, Kc, Vc, F, BETA, 32, CORE);

  // ---- gated rmsnorm -> fp16 hi/lo directly ----
  dim3 gConv(NH, NSEQ);
  out_gate_kernel<<<gConv, 128>>>(CORE, GATE, onorm_w, COREh, COREl);

  // ---- output projection ----
  gemm_f16s<0><<<dim3(HID / 128, NSEQ / 128), 256, SMEMB>>>(
      COREh, COREl, Woh, out, HID, PROJ, HID, nullptr, nullptr,
      nullptr, nullptr, nullptr, nullptr);
}

// round 12
// speedup vs baseline: 1.2159x; 1.0717x over previous
#include <cuda_runtime.h>
#include <cuda_fp16.h>
#include <math.h>
#include <stdint.h>

#define NSEQ 2048
#define HID  2048
#define NH   32
#define DK   128
#define PROJ 4096
#define QKVN (3 * PROJ)
#define QSCALE 0.08838834764831843f     // 128^-0.5

#define NS_COMB   288                    // Wfa(128) + Wga(128) + Wb(32)
#define NS_PAD    384

// ---- GEMM tiling ----
#define BM 128
#define BN 128
#define BK 32
#define MATB   (128 * 64)                // one matrix tile: 128 rows x 64B = 8KB
#define STAGEB (3 * MATB)                // Ah,Al,Bh = 24KB
#define NSTG   4
#define SMEMB  (NSTG * STAGEB)           // 96KB -> 2 CTAs/SM

// ---- scan staging ----
#define SCAN_STG   8
#define SSTRIDE    520                   // floats per stage (16B aligned)
#define SK_OFF     0
#define SE_OFF     160
#define SQ_OFF     320
#define SV_OFF     480
#define SB_OFF     512

// ---------------- scratch (device globals; no allocation allowed) ----------------
__device__ __align__(256) float g_QKVp[NSEQ * QKVN];
__device__ __align__(256) float g_Qc[NSEQ * PROJ];
__device__ __align__(256) float g_Kc[NSEQ * PROJ];
__device__ __align__(256) float g_Vc[NSEQ * PROJ];
__device__ __align__(256) float g_F[NSEQ * PROJ];      // exp(g) written by GEMM epilogue
__device__ __align__(256) float g_GATE[NSEQ * PROJ];
__device__ __align__(256) float g_CORE[NSEQ * PROJ];
__device__ __align__(256) float g_BETA[NSEQ * 32];     // raw beta logits (compact)

__device__ __align__(256) __half g_hsh[NSEQ * HID];
__device__ __align__(256) __half g_hsl[NSEQ * HID];
__device__ __align__(256) __half g_Wqkvh[QKVN * HID];
__device__ __align__(256) __half g_Woh[HID * PROJ];
__device__ __align__(256) __half g_Wfbh[PROJ * DK];
__device__ __align__(256) __half g_Wgbh[PROJ * DK];
__device__ __align__(256) __half g_WSh[NS_PAD * HID];
__device__ __align__(256) __half g_FAh[NSEQ * DK];
__device__ __align__(256) __half g_FAl[NSEQ * DK];
__device__ __align__(256) __half g_GAh[NSEQ * DK];
__device__ __align__(256) __half g_GAl[NSEQ * DK];
__device__ __align__(256) __half g_COREh[NSEQ * PROJ];
__device__ __align__(256) __half g_COREl[NSEQ * PROJ];

// ============================ helpers (sm_80-portable PTX only) ============================
__device__ __forceinline__ uint32_t smem_u32(const void* p) {
  return (uint32_t)__cvta_generic_to_shared(p);
}
__device__ __forceinline__ void cp_async16(uint32_t dst, const void* src) {
  asm volatile("cp.async.cg.shared.global [%0], [%1], 16;" :: "r"(dst), "l"(src) : "memory");
}
__device__ __forceinline__ void cp_async4(uint32_t dst, const void* src) {
  asm volatile("cp.async.ca.shared.global [%0], [%1], 4;" :: "r"(dst), "l"(src) : "memory");
}
__device__ __forceinline__ void cp_commit() {
  asm volatile("cp.async.commit_group;" ::: "memory");
}
template<int N> __device__ __forceinline__ void cp_wait() {
  asm volatile("cp.async.wait_group %0;" :: "n"(N) : "memory");
}
__device__ __forceinline__ void ldm_x4(uint32_t* r, uint32_t addr) {
  asm volatile("ldmatrix.sync.aligned.m8n8.x4.shared.b16 {%0,%1,%2,%3}, [%4];"
               : "=r"(r[0]), "=r"(r[1]), "=r"(r[2]), "=r"(r[3]) : "r"(addr));
}
__device__ __forceinline__ void mma16816(float* c, const uint32_t* a,
                                         uint32_t b0, uint32_t b1) {
  asm volatile(
      "mma.sync.aligned.m16n8k16.row.col.f32.f16.f16.f32 "
      "{%0,%1,%2,%3}, {%4,%5,%6,%7}, {%8,%9}, {%0,%1,%2,%3};"
      : "+f"(c[0]), "+f"(c[1]), "+f"(c[2]), "+f"(c[3])
      : "r"(a[0]), "r"(a[1]), "r"(a[2]), "r"(a[3]), "r"(b0), "r"(b1));
}
__device__ __forceinline__ uint16_t h_bits(__half h) {
  return *reinterpret_cast<uint16_t*>(&h);
}
__device__ __forceinline__ uint32_t pack_f16x2(float a, float b) {
  __half ha = __float2half_rn(a), hb = __float2half_rn(b);
  return (uint32_t)h_bits(ha) | ((uint32_t)h_bits(hb) << 16);
}
// 64B-row swizzle for GEMM smem
__device__ __forceinline__ uint32_t sw64(int row, int kc) {
  return (uint32_t)(row * 64 + ((kc ^ ((row >> 1) & 3)) << 4));
}

// ======================= fp16 hi/lo 2-pass GEMM (mma.sync + ldmatrix) =======================
// C = A*B^T ; 2 passes Ah*Bh + Al*Bh.
// EPI: 0 plain fp32, 1 decay-gate fp32, 2 fused FA/GA fp16-split + compact beta.
__device__ __forceinline__ void ld_stage(uint32_t sb, int slot, int kt, int tid,
                                         const char* a_h, const char* a_l,
                                         const char* b_h, size_t kbytes) {
  const uint32_t st = sb + (uint32_t)slot * STAGEB;
#pragma unroll
  for (int i = 0; i < 2; i++) {
    const int chunk = i * 256 + tid;
    const int row = chunk >> 2, kc = chunk & 3;
    const uint32_t so = sw64(row, kc);
    const size_t go = (size_t)row * kbytes + (size_t)kt * 64 + (size_t)(kc << 4);
    cp_async16(st + so,            a_h + go);
    cp_async16(st + MATB + so,     a_l + go);
    cp_async16(st + 2 * MATB + so, b_h + go);
  }
  cp_commit();
}

template <int EPI>
__global__ void __launch_bounds__(256, 2) gemm_f16s(
    const __half* __restrict__ Ah, const __half* __restrict__ Al,
    const __half* __restrict__ Bh,
    float* __restrict__ C, int Nn, int K, int ldc,
    const float* __restrict__ dt_bias, const float* __restrict__ A_log,
    __half* __restrict__ h1, __half* __restrict__ l1,
    __half* __restrict__ h2, __half* __restrict__ l2) {
  extern __shared__ char sm[];
  const int tid = threadIdx.x;
  const int bm = blockIdx.y * BM, bn = blockIdx.x * BN;
  const uint32_t sb = smem_u32(sm);

  const int lane = tid & 31, warp = tid >> 5;
  const int l16 = lane & 15, lh = lane >> 4;
  const int wR = warp >> 2;
  const int wC = warp & 3;

  const size_t kbytes = (size_t)K * 2;
  const char* a_h = (const char*)Ah + (size_t)bm * kbytes;
  const char* a_l = (const char*)Al + (size_t)bm * kbytes;
  const char* b_h = (const char*)Bh + (size_t)bn * kbytes;

  float acc[4][4][4];
#pragma unroll
  for (int i = 0; i < 4; i++)
#pragma unroll
    for (int j = 0; j < 4; j++)
#pragma unroll
      for (int r = 0; r < 4; r++) acc[i][j][r] = 0.f;

  const int KT = K / BK;
  for (int s = 0; s < NSTG - 1 && s < KT; s++)
    ld_stage(sb, s, s, tid, a_h, a_l, b_h, kbytes);

#pragma unroll 1
  for (int kt = 0; kt < KT; kt++) {
    const int slot = kt % NSTG;
    int pend = KT - 1 - kt; if (pend > NSTG - 2) pend = NSTG - 2;
    if (pend >= 2) cp_wait<2>(); else if (pend == 1) cp_wait<1>(); else cp_wait<0>();
    __syncthreads();

    const int nk = kt + NSTG - 1;
    if (nk < KT) ld_stage(sb, nk % NSTG, nk, tid, a_h, a_l, b_h, kbytes);

    const uint32_t st = sb + (uint32_t)slot * STAGEB;
#pragma unroll
    for (int kk = 0; kk < 2; kk++) {
      const int kc = kk * 2 + lh;
      uint32_t afh[4][4], afl[4][4];
#pragma unroll
      for (int mt = 0; mt < 4; mt++) {
        const int arow = wR * 64 + mt * 16 + l16;
        const uint32_t ao = st + sw64(arow, kc);
        ldm_x4(afh[mt], ao);
        ldm_x4(afl[mt], ao + MATB);
      }
      uint32_t bfh[2][4];
#pragma unroll
      for (int p = 0; p < 2; p++) {
        const int brow = wC * 32 + p * 16 + l16;
        ldm_x4(bfh[p], st + 2 * MATB + sw64(brow, kc));
      }
#pragma unroll
      for (int p = 0; p < 2; p++) {
#pragma unroll
        for (int mt = 0; mt < 4; mt++) {
          mma16816(acc[mt][2 * p],     afh[mt], bfh[p][0], bfh[p][2]);
          mma16816(acc[mt][2 * p],     afl[mt], bfh[p][0], bfh[p][2]);
          mma16816(acc[mt][2 * p + 1], afh[mt], bfh[p][1], bfh[p][3]);
          mma16816(acc[mt][2 * p + 1], afl[mt], bfh[p][1], bfh[p][3]);
        }
      }
    }
  }

  // epilogue
  const int gid = lane >> 2, tig = lane & 3;
#pragma unroll
  for (int mt = 0; mt < 4; mt++) {
    const int row = bm + wR * 64 + mt * 16 + gid;
#pragma unroll
    for (int nt = 0; nt < 4; nt++) {
      const int col = bn + wC * 32 + nt * 8 + tig * 2;
      if (col >= Nn) continue;
      float v[4] = {acc[mt][nt][0], acc[mt][nt][1], acc[mt][nt][2], acc[mt][nt][3]};
      if (EPI == 1) {
        const float d0 = dt_bias[col], d1 = dt_bias[col + 1];
        const float na = -expf(A_log[col >> 7]);
#pragma unroll
        for (int r = 0; r < 4; r++) {
          float x = v[r] + ((r & 1) ? d1 : d0);
          float sp = (x > 20.f) ? x : log1pf(expf(x));
          v[r] = expf(na * sp);
        }
        *reinterpret_cast<float2*>(C + (size_t)row * ldc + col) = make_float2(v[0], v[1]);
        *reinterpret_cast<float2*>(C + (size_t)(row + 8) * ldc + col) = make_float2(v[2], v[3]);
      } else if (EPI == 2) {
        if (col < 256) {
          __half* hb = (col < 128) ? h1 : h2;
          __half* lb = (col < 128) ? l1 : l2;
          const int cc = col & 127;
#pragma unroll
          for (int r = 0; r < 4; r += 2) {
            const size_t o = (size_t)(row + (r ? 8 : 0)) * 128 + cc;
            float hi0f = __half2float(__float2half_rn(v[r]));
            float hi1f = __half2float(__float2half_rn(v[r + 1]));
            *reinterpret_cast<uint32_t*>(hb + o) = pack_f16x2(v[r], v[r + 1]);
            *reinterpret_cast<uint32_t*>(lb + o) = pack_f16x2(v[r] - hi0f, v[r + 1] - hi1f);
          }
        } else {
          const int cc = col - 256;
          *reinterpret_cast<float2*>(C + (size_t)row * 32 + cc) = make_float2(v[0], v[1]);
          *reinterpret_cast<float2*>(C + (size_t)(row + 8) * 32 + cc) = make_float2(v[2], v[3]);
        }
      } else {
        *reinterpret_cast<float2*>(C + (size_t)row * ldc + col) = make_float2(v[0], v[1]);
        *reinterpret_cast<float2*>(C + (size_t)(row + 8) * ldc + col) = make_float2(v[2], v[3]);
      }
    }
  }
}

// ======================= fp32 -> fp16 hi/lo split (vectorized x4; lo optional) =======================
__global__ void __launch_bounds__(256) split_f16_kernel(
    const float* __restrict__ src,
    __half* __restrict__ hi, __half* __restrict__ lo, int total4) {
  int i = blockIdx.x * 256 + threadIdx.x;
  if (i >= total4) return;
  const int idx = i * 4;
  const float4 x = *reinterpret_cast<const float4*>(src + idx);
  uint2 hw;
  hw.x = pack_f16x2(x.x, x.y);
  hw.y = pack_f16x2(x.z, x.w);
  *reinterpret_cast<uint2*>(hi + idx) = hw;
  if (lo) {
    __half h0 = __float2half_rn(x.x), h1 = __float2half_rn(x.y);
    __half h2 = __float2half_rn(x.z), h3 = __float2half_rn(x.w);
    uint2 lw;
    lw.x = pack_f16x2(x.x - __half2float(h0), x.y - __half2float(h1));
    lw.y = pack_f16x2(x.z - __half2float(h2), x.w - __half2float(h3));
    *reinterpret_cast<uint2*>(lo + idx) = lw;
  }
}

// stacked small-weight matrix [Wfa;Wga;Wb;zeros] -> fp16 hi [384, HID]
__global__ void __launch_bounds__(256) ws_build_kernel(
    const float* __restrict__ Wfa, const float* __restrict__ Wga,
    const float* __restrict__ Wb, __half* __restrict__ hi) {
  int idx = blockIdx.x * 256 + threadIdx.x;
  if (idx >= NS_PAD * HID) return;
  int r = idx / HID, c = idx - r * HID;
  float x = 0.f;
  if (r < 128) x = Wfa[r * HID + c];
  else if (r < 256) x = Wga[(r - 128) * HID + c];
  else if (r < NS_COMB) x = Wb[(r - 256) * HID + c];
  hi[idx] = __float2half_rn(x);
}

// -------- fused depthwise causal conv(K=4) + SiLU for Q,K,V in one launch --------
__global__ void __launch_bounds__(128) conv_silu_fused_kernel(
    const float* __restrict__ QKV,
    const float* __restrict__ Wq, const float* __restrict__ Wk, const float* __restrict__ Wv,
    float* __restrict__ Qc, float* __restrict__ Kc, float* __restrict__ Vc) {
  const int type = blockIdx.x >> 5;
  const int h = blockIdx.x & 31;
  const int n = blockIdx.y;
  const int tid = threadIdx.x;
  const int c = h * DK + tid;
  const float* W = (type == 0) ? Wq : (type == 1) ? Wk : Wv;
  float* Y = (type == 0) ? Qc : (type == 1) ? Kc : Vc;
  const float* X = QKV + type * PROJ;

  float y = 0.f;
#pragma unroll
  for (int i = 0; i < 4; i++) {
    int nn = n - 3 + i;
    if (nn >= 0) y = fmaf(X[(size_t)nn * QKVN + c], W[c * 4 + i], y);
  }
  y = y / (1.f + expf(-y));  // SiLU
  if (type < 2) {
    __shared__ float red[4];
    float ss = y * y;
#pragma unroll
    for (int o = 16; o > 0; o >>= 1) ss += __shfl_xor_sync(0xffffffffu, ss, o);
    if ((tid & 31) == 0) red[tid >> 5] = ss;
    __syncthreads();
    float tot = red[0] + red[1] + red[2] + red[3];
    y *= rsqrtf(tot + 1e-6f) * ((type == 0) ? QSCALE : 1.0f);
  }
  Y[(size_t)n * PROJ + c] = y;
}

// ---------------- sequential delta-rule scan (cp.async staged, depth 8) ----------------
// o_t = q.S_dec + (q.k)*delta ; S_new = S_dec + k (x) delta
__device__ __forceinline__ void scan_issue(
    float* stg, int t, int warp, int lane,
    const float* K, const float* Q, const float* V, const float* EG,
    const float* BRAW, int bstride, size_t hb, int vbase, int h) {
  const size_t off = (size_t)t * PROJ + hb;
  if (warp < 3) {
    const int r = lane >> 2, c = lane & 3;
    const uint32_t dst = smem_u32(stg + r * 20 + c * 4);
    if (warp == 0)      cp_async16(dst,                    K  + off + r * 16 + c * 4);
    else if (warp == 1) cp_async16(dst + SE_OFF * 4,       EG + off + r * 16 + c * 4);
    else                cp_async16(dst + SQ_OFF * 4,       Q  + off + r * 16 + c * 4);
  } else if (warp == 3) {
    if (lane < 8)       cp_async16(smem_u32(stg + SV_OFF + lane * 4), V + off + vbase + lane * 4);
    else if (lane == 8) cp_async4(smem_u32(stg + SB_OFF), BRAW + (size_t)t * bstride + h);
  }
  cp_commit();   // every thread commits (possibly empty) -> uniform group counts
}

__global__ void __launch_bounds__(256, 1) scan_kernel(
    const float* __restrict__ Q, const float* __restrict__ K,
    const float* __restrict__ V, const float* __restrict__ EG,
    const float* __restrict__ BRAW, int bstride, float* __restrict__ O) {
  const int h = blockIdx.x >> 2;
  const int vbase = (blockIdx.x & 3) << 5;
  const int tid = threadIdx.x;
  const int vloc = tid >> 3;
  const int kc = tid & 7;
  const int warp = tid >> 5, lane = tid & 31;

  __shared__ __align__(16) float stg[SCAN_STG][SSTRIDE];

  float S[16];
#pragma unroll
  for (int j = 0; j < 16; j++) S[j] = 0.f;

  const size_t hb = (size_t)h * DK;

  // prologue: stages 0..6
#pragma unroll
  for (int s = 0; s < SCAN_STG - 1; s++)
    scan_issue(stg[s], s, warp, lane, K, Q, V, EG, BRAW, bstride, hb, vbase, h);

#pragma unroll 1
  for (int t = 0; t < NSEQ; t++) {
    cp_wait<6>();           // stage t complete (7th newest of <=13 in flight... exact: groups=7+t, all but 6 newest done)
    __syncthreads();        // make async stores block-visible; also guards ring overwrite

    const int nt = t + SCAN_STG - 1;
    if (nt < NSEQ)
      scan_issue(stg[nt & (SCAN_STG - 1)], nt, warp, lane, K, Q, V, EG, BRAW, bstride, hb, vbase, h);
    else
      cp_commit();          // keep per-thread group counts uniform in the tail

    const float* base = stg[t & (SCAN_STG - 1)];
    float4 kc4[4], ec4[4], qc4[4];
    const int rb = kc * 20;
#pragma unroll
    for (int c = 0; c < 4; c++) {
      kc4[c] = *reinterpret_cast<const float4*>(base + rb + c * 4);
      ec4[c] = *reinterpret_cast<const float4*>(base + SE_OFF + rb + c * 4);
      qc4[c] = *reinterpret_cast<const float4*>(base + SQ_OFF + rb + c * 4);
    }
    const float* kf = reinterpret_cast<const float*>(kc4);
    const float* ef = reinterpret_cast<const float*>(ec4);
    const float* qf = reinterpret_cast<const float*>(qc4);

    float kv0 = 0.f, kv1 = 0.f, qs0 = 0.f, qs1 = 0.f, qk0 = 0.f, qk1 = 0.f;
#pragma unroll
    for (int j = 0; j < 16; j++) {
      const float s = S[j] * ef[j];
      S[j] = s;
      if (j & 1) {
        kv1 = fmaf(kf[j], s, kv1); qs1 = fmaf(qf[j], s, qs1); qk1 = fmaf(qf[j], kf[j], qk1);
      } else {
        kv0 = fmaf(kf[j], s, kv0); qs0 = fmaf(qf[j], s, qs0); qk0 = fmaf(qf[j], kf[j], qk0);
      }
    }
    float kv = kv0 + kv1, qs = qs0 + qs1, qk = qk0 + qk1;
#pragma unroll
    for (int o = 1; o < 8; o <<= 1) {
      kv += __shfl_xor_sync(0xffffffffu, kv, o);
      qs += __shfl_xor_sync(0xffffffffu, qs, o);
      qk += __shfl_xor_sync(0xffffffffu, qk, o);
    }

    const float b = 1.f / (1.f + expf(-base[SB_OFF]));
    const float delta = (base[SV_OFF + vloc] - kv) * b;
    if (kc == 0) O[(size_t)t * PROJ + hb + vbase + vloc] = fmaf(qk, delta, qs);

#pragma unroll
    for (int j = 0; j < 16; j++) S[j] = fmaf(kf[j], delta, S[j]);
  }
}

// -------- gated RMSNorm -> fp16 hi/lo directly (paired 4B stores) --------
__global__ void __launch_bounds__(128) out_gate_kernel(
    const float* __restrict__ CORE, const float* __restrict__ GATE,
    const float* __restrict__ onorm_w,
    __half* __restrict__ hi, __half* __restrict__ lo) {
  const int h = blockIdx.x;
  const int n = blockIdx.y;
  const int tid = threadIdx.x;
  const size_t idx = (size_t)n * PROJ + h * DK + tid;
  float cv = CORE[idx];
  float ss = cv * cv;
#pragma unroll
  for (int o = 16; o > 0; o >>= 1) ss += __shfl_xor_sync(0xffffffffu, ss, o);
  __shared__ float red[4];
  if ((tid & 31) == 0) red[tid >> 5] = ss;
  __syncthreads();
  float tot = red[0] + red[1] + red[2] + red[3];
  float r = rsqrtf(tot * (1.f / 128.f) + 1e-5f);
  float gt = GATE[idx];
  float v = cv * r * onorm_w[tid] / (1.f + expf(-gt));
  __half hh = __float2half_rn(v);
  float vl = v - __half2float(hh);
  uint32_t hw = h_bits(hh), lw = h_bits(__float2half_rn(vl));
  uint32_t hn = __shfl_down_sync(0xffffffffu, hw, 1);
  uint32_t ln = __shfl_down_sync(0xffffffffu, lw, 1);
  if ((tid & 1) == 0) {
    *reinterpret_cast<uint32_t*>(hi + idx) = hw | (hn << 16);
    *reinterpret_cast<uint32_t*>(lo + idx) = lw | (ln << 16);
  }
}

// ---------------- launch ----------------
extern "C" void kernel_launch(void* const* d_in, const int* in_sizes, int n_in,
                              void* d_out, int out_size) {
  const float* hs      = (const float*)d_in[0];
  const float* Wq      = (const float*)d_in[1];
  const float* Wk      = (const float*)d_in[2];
  const float* Wv      = (const float*)d_in[3];
  const float* conv_q  = (const float*)d_in[4];
  const float* conv_k  = (const float*)d_in[5];
  const float* conv_v  = (const float*)d_in[6];
  const float* Wfa     = (const float*)d_in[7];
  const float* Wfb     = (const float*)d_in[8];
  const float* dt_bias = (const float*)d_in[9];
  const float* Wb      = (const float*)d_in[10];
  const float* A_log   = (const float*)d_in[11];
  const float* Wga     = (const float*)d_in[12];
  const float* Wgb     = (const float*)d_in[13];
  const float* onorm_w = (const float*)d_in[14];
  const float* Wo      = (const float*)d_in[15];
  float* out = (float*)d_out;

  float *QKVp, *Qc, *Kc, *Vc, *F, *GATE, *CORE, *BETA;
  __half *hsh, *hsl, *Wqkvh, *Woh, *Wfbh, *Wgbh, *WSh;
  __half *FAh, *FAl, *GAh, *GAl, *COREh, *COREl;
  cudaGetSymbolAddress((void**)&QKVp,  g_QKVp);
  cudaGetSymbolAddress((void**)&Qc,    g_Qc);
  cudaGetSymbolAddress((void**)&Kc,    g_Kc);
  cudaGetSymbolAddress((void**)&Vc,    g_Vc);
  cudaGetSymbolAddress((void**)&F,     g_F);
  cudaGetSymbolAddress((void**)&GATE,  g_GATE);
  cudaGetSymbolAddress((void**)&CORE,  g_CORE);
  cudaGetSymbolAddress((void**)&BETA,  g_BETA);
  cudaGetSymbolAddress((void**)&hsh,   g_hsh);
  cudaGetSymbolAddress((void**)&hsl,   g_hsl);
  cudaGetSymbolAddress((void**)&Wqkvh, g_Wqkvh);
  cudaGetSymbolAddress((void**)&Woh,   g_Woh);
  cudaGetSymbolAddress((void**)&Wfbh,  g_Wfbh);
  cudaGetSymbolAddress((void**)&Wgbh,  g_Wgbh);
  cudaGetSymbolAddress((void**)&WSh,   g_WSh);
  cudaGetSymbolAddress((void**)&FAh,   g_FAh);
  cudaGetSymbolAddress((void**)&FAl,   g_FAl);
  cudaGetSymbolAddress((void**)&GAh,   g_GAh);
  cudaGetSymbolAddress((void**)&GAl,   g_GAl);
  cudaGetSymbolAddress((void**)&COREh, g_COREh);
  cudaGetSymbolAddress((void**)&COREl, g_COREl);

  cudaFuncSetAttribute(gemm_f16s<0>, cudaFuncAttributeMaxDynamicSharedMemorySize, SMEMB);
  cudaFuncSetAttribute(gemm_f16s<1>, cudaFuncAttributeMaxDynamicSharedMemorySize, SMEMB);
  cudaFuncSetAttribute(gemm_f16s<2>, cudaFuncAttributeMaxDynamicSharedMemorySize, SMEMB);

  // ---- split conversions (vectorized x4) ----
  int T4;
  T4 = NSEQ * HID / 4;
  split_f16_kernel<<<(T4 + 255) / 256, 256>>>(hs, hsh, hsl, T4);
  T4 = PROJ * HID / 4;
  split_f16_kernel<<<(T4 + 255) / 256, 256>>>(Wq, Wqkvh, nullptr, T4);
  split_f16_kernel<<<(T4 + 255) / 256, 256>>>(Wk, Wqkvh + (size_t)PROJ * HID, nullptr, T4);
  split_f16_kernel<<<(T4 + 255) / 256, 256>>>(Wv, Wqkvh + (size_t)2 * PROJ * HID, nullptr, T4);
  T4 = HID * PROJ / 4;
  split_f16_kernel<<<(T4 + 255) / 256, 256>>>(Wo, Woh, nullptr, T4);
  T4 = PROJ * DK / 4;
  split_f16_kernel<<<(T4 + 255) / 256, 256>>>(Wfb, Wfbh, nullptr, T4);
  split_f16_kernel<<<(T4 + 255) / 256, 256>>>(Wgb, Wgbh, nullptr, T4);
  ws_build_kernel<<<(NS_PAD * HID + 255) / 256, 256>>>(Wfa, Wga, Wb, WSh);

  // ---- tensor-core GEMMs: fused QKV + fused small (FA|GA|beta with split epilogue) ----
  gemm_f16s<0><<<dim3(QKVN / 128, NSEQ / 128), 256, SMEMB>>>(
      hsh, hsl, Wqkvh, QKVp, QKVN, HID, QKVN, nullptr, nullptr,
      nullptr, nullptr, nullptr, nullptr);
  gemm_f16s<2><<<dim3(3, NSEQ / 128), 256, SMEMB>>>(
      hsh, hsl, WSh, BETA, NS_COMB, HID, 32, nullptr, nullptr,
      FAh, FAl, GAh, GAl);

  // ---- fused conv + silu (+ l2 norm for q,k) ----
  conv_silu_fused_kernel<<<dim3(3 * NH, NSEQ), 128>>>(QKVp, conv_q, conv_k, conv_v, Qc, Kc, Vc);

  // ---- low-rank second projections (K=128), F with fused decay epilogue ----
  gemm_f16s<1><<<dim3(PROJ / 128, NSEQ / 128), 256, SMEMB>>>(
      FAh, FAl, Wfbh, F, PROJ, DK, PROJ, dt_bias, A_log,
      nullptr, nullptr, nullptr, nullptr);
  gemm_f16s<0><<<dim3(PROJ / 128, NSEQ / 128), 256, SMEMB>>>(
      GAh, GAl, Wgbh, GATE, PROJ, DK, PROJ, nullptr, nullptr,
      nullptr, nullptr, nullptr, nullptr);

  // ---- recurrent scan ----
  scan_kernel<<<NH * 4, 256>>>(Qc, Kc, Vc, F, BETA, 32, CORE);

  // ---- gated rmsnorm -> fp16 hi/lo directly ----
  dim3 gConv(NH, NSEQ);
  out_gate_kernel<<<gConv, 128>>>(CORE, GATE, onorm_w, COREh, COREl);

  // ---- output projection ----
  gemm_f16s<0><<<dim3(HID / 128, NSEQ / 128), 256, SMEMB>>>(
      COREh, COREl, Woh, out, HID, PROJ, HID, nullptr, nullptr,
      nullptr, nullptr, nullptr, nullptr);
}

// round 13
// speedup vs baseline: 1.2192x; 1.0028x over previous
#include <cuda_runtime.h>
#include <cuda_fp16.h>
#include <math.h>
#include <stdint.h>

#define NSEQ 2048
#define HID  2048
#define NH   32
#define DK   128
#define PROJ 4096
#define QKVN (3 * PROJ)
#define QSCALE 0.08838834764831843f     // 128^-0.5

#define NS_COMB   288                    // Wfa(128) + Wga(128) + Wb(32)
#define NS_PAD    384

// ---- GEMM tiling ----
#define BM 128
#define BN 128
#define BK 32
#define MATB   (128 * 64)                // one matrix tile: 128 rows x 64B = 8KB
#define STAGEB (3 * MATB)                // Ah,Al,Bh = 24KB
#define NSTG   4
#define SMEMB  (NSTG * STAGEB)           // 96KB -> 2 CTAs/SM

// ---- scan staging (64-thread blocks, 8 v-cols each) ----
#define SCAN_STG   8
#define SE_OFF     160
#define SQ_OFF     320
#define SV_OFF     480
#define SB_OFF     488
#define SSTRIDE    492                   // floats per stage (16B-aligned: 492*4=1968)

// ---------------- scratch (device globals; no allocation allowed) ----------------
__device__ __align__(256) float g_QKVp[NSEQ * QKVN];
__device__ __align__(256) float g_Qc[NSEQ * PROJ];
__device__ __align__(256) float g_Kc[NSEQ * PROJ];
__device__ __align__(256) float g_Vc[NSEQ * PROJ];
__device__ __align__(256) float g_F[NSEQ * PROJ];      // exp(g) written by GEMM epilogue
__device__ __align__(256) float g_GATE[NSEQ * PROJ];
__device__ __align__(256) float g_CORE[NSEQ * PROJ];
__device__ __align__(256) float g_BETA[NSEQ * 32];     // raw beta logits (compact)

__device__ __align__(256) __half g_hsh[NSEQ * HID];
__device__ __align__(256) __half g_hsl[NSEQ * HID];
__device__ __align__(256) __half g_Wqkvh[QKVN * HID];
__device__ __align__(256) __half g_Woh[HID * PROJ];
__device__ __align__(256) __half g_Wfbh[PROJ * DK];
__device__ __align__(256) __half g_Wgbh[PROJ * DK];
__device__ __align__(256) __half g_WSh[NS_PAD * HID];
__device__ __align__(256) __half g_FAh[NSEQ * DK];
__device__ __align__(256) __half g_FAl[NSEQ * DK];
__device__ __align__(256) __half g_GAh[NSEQ * DK];
__device__ __align__(256) __half g_GAl[NSEQ * DK];
__device__ __align__(256) __half g_COREh[NSEQ * PROJ];
__device__ __align__(256) __half g_COREl[NSEQ * PROJ];

// ============================ helpers (sm_80-portable PTX only) ============================
__device__ __forceinline__ uint32_t smem_u32(const void* p) {
  return (uint32_t)__cvta_generic_to_shared(p);
}
__device__ __forceinline__ void cp_async16(uint32_t dst, const void* src) {
  asm volatile("cp.async.cg.shared.global [%0], [%1], 16;" :: "r"(dst), "l"(src) : "memory");
}
__device__ __forceinline__ void cp_async4(uint32_t dst, const void* src) {
  asm volatile("cp.async.ca.shared.global [%0], [%1], 4;" :: "r"(dst), "l"(src) : "memory");
}
__device__ __forceinline__ void cp_commit() {
  asm volatile("cp.async.commit_group;" ::: "memory");
}
template<int N> __device__ __forceinline__ void cp_wait() {
  asm volatile("cp.async.wait_group %0;" :: "n"(N) : "memory");
}
__device__ __forceinline__ void ldm_x4(uint32_t* r, uint32_t addr) {
  asm volatile("ldmatrix.sync.aligned.m8n8.x4.shared.b16 {%0,%1,%2,%3}, [%4];"
               : "=r"(r[0]), "=r"(r[1]), "=r"(r[2]), "=r"(r[3]) : "r"(addr));
}
__device__ __forceinline__ void mma16816(float* c, const uint32_t* a,
                                         uint32_t b0, uint32_t b1) {
  asm volatile(
      "mma.sync.aligned.m16n8k16.row.col.f32.f16.f16.f32 "
      "{%0,%1,%2,%3}, {%4,%5,%6,%7}, {%8,%9}, {%0,%1,%2,%3};"
      : "+f"(c[0]), "+f"(c[1]), "+f"(c[2]), "+f"(c[3])
      : "r"(a[0]), "r"(a[1]), "r"(a[2]), "r"(a[3]), "r"(b0), "r"(b1));
}
__device__ __forceinline__ uint16_t h_bits(__half h) {
  return *reinterpret_cast<uint16_t*>(&h);
}
__device__ __forceinline__ uint32_t pack_f16x2(float a, float b) {
  __half ha = __float2half_rn(a), hb = __float2half_rn(b);
  return (uint32_t)h_bits(ha) | ((uint32_t)h_bits(hb) << 16);
}
// 64B-row swizzle for GEMM smem
__device__ __forceinline__ uint32_t sw64(int row, int kc) {
  return (uint32_t)(row * 64 + ((kc ^ ((row >> 1) & 3)) << 4));
}

// ======================= fp16 hi/lo 2-pass GEMM (mma.sync + ldmatrix) =======================
// C = A*B^T ; 2 passes Ah*Bh + Al*Bh.
// EPI: 0 plain fp32, 1 decay-gate fp32, 2 fused FA/GA fp16-split + compact beta.
__device__ __forceinline__ void ld_stage(uint32_t sb, int slot, int kt, int tid,
                                         const char* a_h, const char* a_l,
                                         const char* b_h, size_t kbytes) {
  const uint32_t st = sb + (uint32_t)slot * STAGEB;
#pragma unroll
  for (int i = 0; i < 2; i++) {
    const int chunk = i * 256 + tid;
    const int row = chunk >> 2, kc = chunk & 3;
    const uint32_t so = sw64(row, kc);
    const size_t go = (size_t)row * kbytes + (size_t)kt * 64 + (size_t)(kc << 4);
    cp_async16(st + so,            a_h + go);
    cp_async16(st + MATB + so,     a_l + go);
    cp_async16(st + 2 * MATB + so, b_h + go);
  }
  cp_commit();
}

template <int EPI>
__global__ void __launch_bounds__(256, 2) gemm_f16s(
    const __half* __restrict__ Ah, const __half* __restrict__ Al,
    const __half* __restrict__ Bh,
    float* __restrict__ C, int Nn, int K, int ldc,
    const float* __restrict__ dt_bias, const float* __restrict__ A_log,
    __half* __restrict__ h1, __half* __restrict__ l1,
    __half* __restrict__ h2, __half* __restrict__ l2) {
  extern __shared__ char sm[];
  const int tid = threadIdx.x;
  const int bm = blockIdx.y * BM, bn = blockIdx.x * BN;
  const uint32_t sb = smem_u32(sm);

  const int lane = tid & 31, warp = tid >> 5;
  const int l16 = lane & 15, lh = lane >> 4;
  const int wR = warp >> 2;
  const int wC = warp & 3;

  const size_t kbytes = (size_t)K * 2;
  const char* a_h = (const char*)Ah + (size_t)bm * kbytes;
  const char* a_l = (const char*)Al + (size_t)bm * kbytes;
  const char* b_h = (const char*)Bh + (size_t)bn * kbytes;

  float acc[4][4][4];
#pragma unroll
  for (int i = 0; i < 4; i++)
#pragma unroll
    for (int j = 0; j < 4; j++)
#pragma unroll
      for (int r = 0; r < 4; r++) acc[i][j][r] = 0.f;

  const int KT = K / BK;
  for (int s = 0; s < NSTG - 1 && s < KT; s++)
    ld_stage(sb, s, s, tid, a_h, a_l, b_h, kbytes);

#pragma unroll 1
  for (int kt = 0; kt < KT; kt++) {
    const int slot = kt % NSTG;
    int pend = KT - 1 - kt; if (pend > NSTG - 2) pend = NSTG - 2;
    if (pend >= 2) cp_wait<2>(); else if (pend == 1) cp_wait<1>(); else cp_wait<0>();
    __syncthreads();

    const int nk = kt + NSTG - 1;
    if (nk < KT) ld_stage(sb, nk % NSTG, nk, tid, a_h, a_l, b_h, kbytes);

    const uint32_t st = sb + (uint32_t)slot * STAGEB;
#pragma unroll
    for (int kk = 0; kk < 2; kk++) {
      const int kc = kk * 2 + lh;
      uint32_t afh[4][4], afl[4][4];
#pragma unroll
      for (int mt = 0; mt < 4; mt++) {
        const int arow = wR * 64 + mt * 16 + l16;
        const uint32_t ao = st + sw64(arow, kc);
        ldm_x4(afh[mt], ao);
        ldm_x4(afl[mt], ao + MATB);
      }
      uint32_t bfh[2][4];
#pragma unroll
      for (int p = 0; p < 2; p++) {
        const int brow = wC * 32 + p * 16 + l16;
        ldm_x4(bfh[p], st + 2 * MATB + sw64(brow, kc));
      }
#pragma unroll
      for (int p = 0; p < 2; p++) {
#pragma unroll
        for (int mt = 0; mt < 4; mt++) {
          mma16816(acc[mt][2 * p],     afh[mt], bfh[p][0], bfh[p][2]);
          mma16816(acc[mt][2 * p],     afl[mt], bfh[p][0], bfh[p][2]);
          mma16816(acc[mt][2 * p + 1], afh[mt], bfh[p][1], bfh[p][3]);
          mma16816(acc[mt][2 * p + 1], afl[mt], bfh[p][1], bfh[p][3]);
        }
      }
    }
  }

  // epilogue
  const int gid = lane >> 2, tig = lane & 3;
#pragma unroll
  for (int mt = 0; mt < 4; mt++) {
    const int row = bm + wR * 64 + mt * 16 + gid;
#pragma unroll
    for (int nt = 0; nt < 4; nt++) {
      const int col = bn + wC * 32 + nt * 8 + tig * 2;
      if (col >= Nn) continue;
      float v[4] = {acc[mt][nt][0], acc[mt][nt][1], acc[mt][nt][2], acc[mt][nt][3]};
      if (EPI == 1) {
        const float d0 = dt_bias[col], d1 = dt_bias[col + 1];
        const float na = -expf(A_log[col >> 7]);
#pragma unroll
        for (int r = 0; r < 4; r++) {
          float x = v[r] + ((r & 1) ? d1 : d0);
          float sp = (x > 20.f) ? x : log1pf(expf(x));
          v[r] = expf(na * sp);
        }
        *reinterpret_cast<float2*>(C + (size_t)row * ldc + col) = make_float2(v[0], v[1]);
        *reinterpret_cast<float2*>(C + (size_t)(row + 8) * ldc + col) = make_float2(v[2], v[3]);
      } else if (EPI == 2) {
        if (col < 256) {
          __half* hb = (col < 128) ? h1 : h2;
          __half* lb = (col < 128) ? l1 : l2;
          const int cc = col & 127;
#pragma unroll
          for (int r = 0; r < 4; r += 2) {
            const size_t o = (size_t)(row + (r ? 8 : 0)) * 128 + cc;
            float hi0f = __half2float(__float2half_rn(v[r]));
            float hi1f = __half2float(__float2half_rn(v[r + 1]));
            *reinterpret_cast<uint32_t*>(hb + o) = pack_f16x2(v[r], v[r + 1]);
            *reinterpret_cast<uint32_t*>(lb + o) = pack_f16x2(v[r] - hi0f, v[r + 1] - hi1f);
          }
        } else {
          const int cc = col - 256;
          *reinterpret_cast<float2*>(C + (size_t)row * 32 + cc) = make_float2(v[0], v[1]);
          *reinterpret_cast<float2*>(C + (size_t)(row + 8) * 32 + cc) = make_float2(v[2], v[3]);
        }
      } else {
        *reinterpret_cast<float2*>(C + (size_t)row * ldc + col) = make_float2(v[0], v[1]);
        *reinterpret_cast<float2*>(C + (size_t)(row + 8) * ldc + col) = make_float2(v[2], v[3]);
      }
    }
  }
}

// ======================= fp32 -> fp16 hi/lo split (vectorized x4; lo optional) =======================
__global__ void __launch_bounds__(256) split_f16_kernel(
    const float* __restrict__ src,
    __half* __restrict__ hi, __half* __restrict__ lo, int total4) {
  int i = blockIdx.x * 256 + threadIdx.x;
  if (i >= total4) return;
  const int idx = i * 4;
  const float4 x = *reinterpret_cast<const float4*>(src + idx);
  uint2 hw;
  hw.x = pack_f16x2(x.x, x.y);
  hw.y = pack_f16x2(x.z, x.w);
  *reinterpret_cast<uint2*>(hi + idx) = hw;
  if (lo) {
    __half h0 = __float2half_rn(x.x), h1 = __float2half_rn(x.y);
    __half h2 = __float2half_rn(x.z), h3 = __float2half_rn(x.w);
    uint2 lw;
    lw.x = pack_f16x2(x.x - __half2float(h0), x.y - __half2float(h1));
    lw.y = pack_f16x2(x.z - __half2float(h2), x.w - __half2float(h3));
    *reinterpret_cast<uint2*>(lo + idx) = lw;
  }
}

// stacked small-weight matrix [Wfa;Wga;Wb;zeros] -> fp16 hi [384, HID]
__global__ void __launch_bounds__(256) ws_build_kernel(
    const float* __restrict__ Wfa, const float* __restrict__ Wga,
    const float* __restrict__ Wb, __half* __restrict__ hi) {
  int idx = blockIdx.x * 256 + threadIdx.x;
  if (idx >= NS_PAD * HID) return;
  int r = idx / HID, c = idx - r * HID;
  float x = 0.f;
  if (r < 128) x = Wfa[r * HID + c];
  else if (r < 256) x = Wga[(r - 128) * HID + c];
  else if (r < NS_COMB) x = Wb[(r - 256) * HID + c];
  hi[idx] = __float2half_rn(x);
}

// -------- fused depthwise causal conv(K=4) + SiLU for Q,K,V in one launch --------
__global__ void __launch_bounds__(128) conv_silu_fused_kernel(
    const float* __restrict__ QKV,
    const float* __restrict__ Wq, const float* __restrict__ Wk, const float* __restrict__ Wv,
    float* __restrict__ Qc, float* __restrict__ Kc, float* __restrict__ Vc) {
  const int type = blockIdx.x >> 5;
  const int h = blockIdx.x & 31;
  const int n = blockIdx.y;
  const int tid = threadIdx.x;
  const int c = h * DK + tid;
  const float* W = (type == 0) ? Wq : (type == 1) ? Wk : Wv;
  float* Y = (type == 0) ? Qc : (type == 1) ? Kc : Vc;
  const float* X = QKV + type * PROJ;

  float y = 0.f;
#pragma unroll
  for (int i = 0; i < 4; i++) {
    int nn = n - 3 + i;
    if (nn >= 0) y = fmaf(X[(size_t)nn * QKVN + c], W[c * 4 + i], y);
  }
  y = y / (1.f + expf(-y));  // SiLU
  if (type < 2) {
    __shared__ float red[4];
    float ss = y * y;
#pragma unroll
    for (int o = 16; o > 0; o >>= 1) ss += __shfl_xor_sync(0xffffffffu, ss, o);
    if ((tid & 31) == 0) red[tid >> 5] = ss;
    __syncthreads();
    float tot = red[0] + red[1] + red[2] + red[3];
    y *= rsqrtf(tot + 1e-6f) * ((type == 0) ? QSCALE : 1.0f);
  }
  Y[(size_t)n * PROJ + c] = y;
}

// ---------------- sequential delta-rule scan (cp.async staged; 64-thr blocks, 8 v-cols) ----------------
// grid = NH*16 = 512 blocks -> ~3-4 blocks/SM overlap the per-step latency chain.
// o_t = q.S_dec + (q.k)*delta ; S_new = S_dec + k (x) delta
__device__ __forceinline__ void scan_issue(
    float* stg, int t, int warp, int lane,
    const float* K, const float* Q, const float* V, const float* EG,
    const float* BRAW, int bstride, size_t hb, int vbase, int h) {
  const size_t off = (size_t)t * PROJ + hb;
  const int r = lane >> 2, c = lane & 3;       // r 0..7, c 0..3
  const int fo = r * 20 + c * 4;                // stride-20 layout
  if (warp == 0) {
    const uint32_t dst = smem_u32(stg + fo);
    cp_async16(dst,               K + off + r * 16 + c * 4);
    cp_async16(dst + SQ_OFF * 4,  Q + off + r * 16 + c * 4);
  } else {
    cp_async16(smem_u32(stg + SE_OFF + fo), EG + off + r * 16 + c * 4);
    if (lane < 2)       cp_async16(smem_u32(stg + SV_OFF + lane * 4), V + off + vbase + lane * 4);
    else if (lane == 2) cp_async4(smem_u32(stg + SB_OFF), BRAW + (size_t)t * bstride + h);
  }
  cp_commit();   // every thread commits once -> uniform group counts
}

__global__ void __launch_bounds__(64, 6) scan_kernel(
    const float* __restrict__ Q, const float* __restrict__ K,
    const float* __restrict__ V, const float* __restrict__ EG,
    const float* __restrict__ BRAW, int bstride, float* __restrict__ O) {
  const int h = blockIdx.x >> 4;
  const int vbase = (blockIdx.x & 15) << 3;
  const int tid = threadIdx.x;
  const int vloc = tid >> 3;                 // 0..7
  const int kc = tid & 7;
  const int warp = tid >> 5, lane = tid & 31;

  __shared__ __align__(16) float stg[SCAN_STG][SSTRIDE];

  float S[16];
#pragma unroll
  for (int j = 0; j < 16; j++) S[j] = 0.f;

  const size_t hb = (size_t)h * DK;

  // prologue: stages 0..6
#pragma unroll
  for (int s = 0; s < SCAN_STG - 1; s++)
    scan_issue(stg[s], s, warp, lane, K, Q, V, EG, BRAW, bstride, hb, vbase, h);

#pragma unroll 1
  for (int t = 0; t < NSEQ; t++) {
    cp_wait<6>();
    __syncthreads();        // async stores visible block-wide; guards ring overwrite

    const int nt = t + SCAN_STG - 1;
    if (nt < NSEQ)
      scan_issue(stg[nt & (SCAN_STG - 1)], nt, warp, lane, K, Q, V, EG, BRAW, bstride, hb, vbase, h);
    else
      cp_commit();

    const float* base = stg[t & (SCAN_STG - 1)];
    float4 kc4[4], ec4[4], qc4[4];
    const int rb = kc * 20;
#pragma unroll
    for (int c = 0; c < 4; c++) {
      kc4[c] = *reinterpret_cast<const float4*>(base + rb + c * 4);
      ec4[c] = *reinterpret_cast<const float4*>(base + SE_OFF + rb + c * 4);
      qc4[c] = *reinterpret_cast<const float4*>(base + SQ_OFF + rb + c * 4);
    }
    const float* kf = reinterpret_cast<const float*>(kc4);
    const float* ef = reinterpret_cast<const float*>(ec4);
    const float* qf = reinterpret_cast<const float*>(qc4);

    float kv0 = 0.f, kv1 = 0.f, qs0 = 0.f, qs1 = 0.f, qk0 = 0.f, qk1 = 0.f;
#pragma unroll
    for (int j = 0; j < 16; j++) {
      const float s = S[j] * ef[j];
      S[j] = s;
      if (j & 1) {
        kv1 = fmaf(kf[j], s, kv1); qs1 = fmaf(qf[j], s, qs1); qk1 = fmaf(qf[j], kf[j], qk1);
      } else {
        kv0 = fmaf(kf[j], s, kv0); qs0 = fmaf(qf[j], s, qs0); qk0 = fmaf(qf[j], kf[j], qk0);
      }
    }
    // kv reduce first: it alone gates the S-carry chain
    float kv = kv0 + kv1;
    kv += __shfl_xor_sync(0xffffffffu, kv, 1);
    kv += __shfl_xor_sync(0xffffffffu, kv, 2);
    kv += __shfl_xor_sync(0xffffffffu, kv, 4);

    const float b = 1.f / (1.f + expf(-base[SB_OFF]));
    const float delta = (base[SV_OFF + vloc] - kv) * b;
#pragma unroll
    for (int j = 0; j < 16; j++) S[j] = fmaf(kf[j], delta, S[j]);

    // qs/qk reduce off the carry path
    float qs = qs0 + qs1, qk = qk0 + qk1;
#pragma unroll
    for (int o = 1; o < 8; o <<= 1) {
      qs += __shfl_xor_sync(0xffffffffu, qs, o);
      qk += __shfl_xor_sync(0xffffffffu, qk, o);
    }
    if (kc == 0) O[(size_t)t * PROJ + hb + vbase + vloc] = fmaf(qk, delta, qs);
  }
}

// -------- gated RMSNorm -> fp16 hi/lo directly (paired 4B stores) --------
__global__ void __launch_bounds__(128) out_gate_kernel(
    const float* __restrict__ CORE, const float* __restrict__ GATE,
    const float* __restrict__ onorm_w,
    __half* __restrict__ hi, __half* __restrict__ lo) {
  const int h = blockIdx.x;
  const int n = blockIdx.y;
  const int tid = threadIdx.x;
  const size_t idx = (size_t)n * PROJ + h * DK + tid;
  float cv = CORE[idx];
  float ss = cv * cv;
#pragma unroll
  for (int o = 16; o > 0; o >>= 1) ss += __shfl_xor_sync(0xffffffffu, ss, o);
  __shared__ float red[4];
  if ((tid & 31) == 0) red[tid >> 5] = ss;
  __syncthreads();
  float tot = red[0] + red[1] + red[2] + red[3];
  float r = rsqrtf(tot * (1.f / 128.f) + 1e-5f);
  float gt = GATE[idx];
  float v = cv * r * onorm_w[tid] / (1.f + expf(-gt));
  __half hh = __float2half_rn(v);
  float vl = v - __half2float(hh);
  uint32_t hw = h_bits(hh), lw = h_bits(__float2half_rn(vl));
  uint32_t hn = __shfl_down_sync(0xffffffffu, hw, 1);
  uint32_t ln = __shfl_down_sync(0xffffffffu, lw, 1);
  if ((tid & 1) == 0) {
    *reinterpret_cast<uint32_t*>(hi + idx) = hw | (hn << 16);
    *reinterpret_cast<uint32_t*>(lo + idx) = lw | (ln << 16);
  }
}

// ---------------- launch ----------------
extern "C" void kernel_launch(void* const* d_in, const int* in_sizes, int n_in,
                              void* d_out, int out_size) {
  const float* hs      = (const float*)d_in[0];
  const float* Wq      = (const float*)d_in[1];
  const float* Wk      = (const float*)d_in[2];
  const float* Wv      = (const float*)d_in[3];
  const float* conv_q  = (const float*)d_in[4];
  const float* conv_k  = (const float*)d_in[5];
  const float* conv_v  = (const float*)d_in[6];
  const float* Wfa     = (const float*)d_in[7];
  const float* Wfb     = (const float*)d_in[8];
  const float* dt_bias = (const float*)d_in[9];
  const float* Wb      = (const float*)d_in[10];
  const float* A_log   = (const float*)d_in[11];
  const float* Wga     = (const float*)d_in[12];
  const float* Wgb     = (const float*)d_in[13];
  const float* onorm_w = (const float*)d_in[14];
  const float* Wo      = (const float*)d_in[15];
  float* out = (float*)d_out;

  float *QKVp, *Qc, *Kc, *Vc, *F, *GATE, *CORE, *BETA;
  __half *hsh, *hsl, *Wqkvh, *Woh, *Wfbh, *Wgbh, *WSh;
  __half *FAh, *FAl, *GAh, *GAl, *COREh, *COREl;
  cudaGetSymbolAddress((void**)&QKVp,  g_QKVp);
  cudaGetSymbolAddress((void**)&Qc,    g_Qc);
  cudaGetSymbolAddress((void**)&Kc,    g_Kc);
  cudaGetSymbolAddress((void**)&Vc,    g_Vc);
  cudaGetSymbolAddress((void**)&F,     g_F);
  cudaGetSymbolAddress((void**)&GATE,  g_GATE);
  cudaGetSymbolAddress((void**)&CORE,  g_CORE);
  cudaGetSymbolAddress((void**)&BETA,  g_BETA);
  cudaGetSymbolAddress((void**)&hsh,   g_hsh);
  cudaGetSymbolAddress((void**)&hsl,   g_hsl);
  cudaGetSymbolAddress((void**)&Wqkvh, g_Wqkvh);
  cudaGetSymbolAddress((void**)&Woh,   g_Woh);
  cudaGetSymbolAddress((void**)&Wfbh,  g_Wfbh);
  cudaGetSymbolAddress((void**)&Wgbh,  g_Wgbh);
  cudaGetSymbolAddress((void**)&WSh,   g_WSh);
  cudaGetSymbolAddress((void**)&FAh,   g_FAh);
  cudaGetSymbolAddress((void**)&FAl,   g_FAl);
  cudaGetSymbolAddress((void**)&GAh,   g_GAh);
  cudaGetSymbolAddress((void**)&GAl,   g_GAl);
  cudaGetSymbolAddress((void**)&COREh, g_COREh);
  cudaGetSymbolAddress((void**)&COREl, g_COREl);

  cudaFuncSetAttribute(gemm_f16s<0>, cudaFuncAttributeMaxDynamicSharedMemorySize, SMEMB);
  cudaFuncSetAttribute(gemm_f16s<1>, cudaFuncAttributeMaxDynamicSharedMemorySize, SMEMB);
  cudaFuncSetAttribute(gemm_f16s<2>, cudaFuncAttributeMaxDynamicSharedMemorySize, SMEMB);

  // ---- split conversions (vectorized x4) ----
  int T4;
  T4 = NSEQ * HID / 4;
  split_f16_kernel<<<(T4 + 255) / 256, 256>>>(hs, hsh, hsl, T4);
  T4 = PROJ * HID / 4;
  split_f16_kernel<<<(T4 + 255) / 256, 256>>>(Wq, Wqkvh, nullptr, T4);
  split_f16_kernel<<<(T4 + 255) / 256, 256>>>(Wk, Wqkvh + (size_t)PROJ * HID, nullptr, T4);
  split_f16_kernel<<<(T4 + 255) / 256, 256>>>(Wv, Wqkvh + (size_t)2 * PROJ * HID, nullptr, T4);
  T4 = HID * PROJ / 4;
  split_f16_kernel<<<(T4 + 255) / 256, 256>>>(Wo, Woh, nullptr, T4);
  T4 = PROJ * DK / 4;
  split_f16_kernel<<<(T4 + 255) / 256, 256>>>(Wfb, Wfbh, nullptr, T4);
  split_f16_kernel<<<(T4 + 255) / 256, 256>>>(Wgb, Wgbh, nullptr, T4);
  ws_build_kernel<<<(NS_PAD * HID + 255) / 256, 256>>>(Wfa, Wga, Wb, WSh);

  // ---- tensor-core GEMMs: fused QKV + fused small (FA|GA|beta with split epilogue) ----
  gemm_f16s<0><<<dim3(QKVN / 128, NSEQ / 128), 256, SMEMB>>>(
      hsh, hsl, Wqkvh, QKVp, QKVN, HID, QKVN, nullptr, nullptr,
      nullptr, nullptr, nullptr, nullptr);
  gemm_f16s<2><<<dim3(3, NSEQ / 128), 256, SMEMB>>>(
      hsh, hsl, WSh, BETA, NS_COMB, HID, 32, nullptr, nullptr,
      FAh, FAl, GAh, GAl);

  // ---- fused conv + silu (+ l2 norm for q,k) ----
  conv_silu_fused_kernel<<<dim3(3 * NH, NSEQ), 128>>>(QKVp, conv_q, conv_k, conv_v, Qc, Kc, Vc);

  // ---- low-rank second projections (K=128), F with fused decay epilogue ----
  gemm_f16s<1><<<dim3(PROJ / 128, NSEQ / 128), 256, SMEMB>>>(
      FAh, FAl, Wfbh, F, PROJ, DK, PROJ, dt_bias, A_log,
      nullptr, nullptr, nullptr, nullptr);
  gemm_f16s<0><<<dim3(PROJ / 128, NSEQ / 128), 256, SMEMB>>>(
      GAh, GAl, Wgbh, GATE, PROJ, DK, PROJ, nullptr, nullptr,
      nullptr, nullptr, nullptr, nullptr);

  // ---- recurrent scan (512 small blocks for latency overlap) ----
  scan_kernel<<<NH * 16, 64>>>(Qc, Kc, Vc, F, BETA, 32, CORE);

  // ---- gated rmsnorm -> fp16 hi/lo directly ----
  dim3 gConv(NH, NSEQ);
  out_gate_kernel<<<gConv, 128>>>(CORE, GATE, onorm_w, COREh, COREl);

  // ---- output projection ----
  gemm_f16s<0><<<dim3(HID / 128, NSEQ / 128), 256, SMEMB>>>(
      COREh, COREl, Woh, out, HID, PROJ, HID, nullptr, nullptr,
      nullptr, nullptr, nullptr, nullptr);
}

// round 14
// speedup vs baseline: 1.4813x; 1.2150x over previous
#include <cuda_runtime.h>
#include <cuda_fp16.h>
#include <math.h>
#include <stdint.h>

#define NSEQ 2048
#define HID  2048
#define NH   32
#define DK   128
#define PROJ 4096
#define QKVN (3 * PROJ)
#define QSCALE 0.08838834764831843f     // 128^-0.5

#define NS_COMB   288                    // Wfa(128) + Wga(128) + Wb(32)
#define NS_PAD    384

// ---- GEMM tiling ----
#define BM 128
#define BN 128
#define BK 32
#define MATB   (128 * 64)                // one matrix tile: 128 rows x 64B = 8KB
#define NSTG   4
#define SMEMB1 (NSTG * 2 * MATB)         // 1-pass: Ah,Bh = 64KB
#define SMEMB2 (NSTG * 3 * MATB)         // 2-pass: Ah,Al,Bh = 96KB

// ---- scan staging (64-thread blocks, 8 v-cols each) ----
#define SCAN_STG   8
#define SE_OFF     160
#define SQ_OFF     320
#define SV_OFF     480
#define SB_OFF     488
#define SSTRIDE    492

// ---------------- scratch (device globals; no allocation allowed) ----------------
__device__ __align__(256) float g_QKVp[NSEQ * QKVN];
__device__ __align__(256) float g_Qc[NSEQ * PROJ];
__device__ __align__(256) float g_Kc[NSEQ * PROJ];
__device__ __align__(256) float g_Vc[NSEQ * PROJ];
__device__ __align__(256) float g_F[NSEQ * PROJ];      // exp(g) written by GEMM epilogue
__device__ __align__(256) float g_GATE[NSEQ * PROJ];
__device__ __align__(256) float g_CORE[NSEQ * PROJ];
__device__ __align__(256) float g_BETA[NSEQ * 32];     // raw beta logits (compact)

__device__ __align__(256) __half g_hsh[NSEQ * HID];
__device__ __align__(256) __half g_hsl[NSEQ * HID];
__device__ __align__(256) __half g_Wqkvh[QKVN * HID];
__device__ __align__(256) __half g_Woh[HID * PROJ];
__device__ __align__(256) __half g_Wfbh[PROJ * DK];
__device__ __align__(256) __half g_Wgbh[PROJ * DK];
__device__ __align__(256) __half g_WSh[NS_PAD * HID];
__device__ __align__(256) __half g_FAh[NSEQ * DK];
__device__ __align__(256) __half g_FAl[NSEQ * DK];
__device__ __align__(256) __half g_GAh[NSEQ * DK];
__device__ __align__(256) __half g_GAl[NSEQ * DK];
__device__ __align__(256) __half g_COREh[NSEQ * PROJ];

// ============================ helpers (sm_80-portable PTX only) ============================
__device__ __forceinline__ uint32_t smem_u32(const void* p) {
  return (uint32_t)__cvta_generic_to_shared(p);
}
__device__ __forceinline__ void cp_async16(uint32_t dst, const void* src) {
  asm volatile("cp.async.cg.shared.global [%0], [%1], 16;" :: "r"(dst), "l"(src) : "memory");
}
__device__ __forceinline__ void cp_async4(uint32_t dst, const void* src) {
  asm volatile("cp.async.ca.shared.global [%0], [%1], 4;" :: "r"(dst), "l"(src) : "memory");
}
__device__ __forceinline__ void cp_commit() {
  asm volatile("cp.async.commit_group;" ::: "memory");
}
template<int N> __device__ __forceinline__ void cp_wait() {
  asm volatile("cp.async.wait_group %0;" :: "n"(N) : "memory");
}
__device__ __forceinline__ void ldm_x4(uint32_t* r, uint32_t addr) {
  asm volatile("ldmatrix.sync.aligned.m8n8.x4.shared.b16 {%0,%1,%2,%3}, [%4];"
               : "=r"(r[0]), "=r"(r[1]), "=r"(r[2]), "=r"(r[3]) : "r"(addr));
}
__device__ __forceinline__ void mma16816(float* c, const uint32_t* a,
                                         uint32_t b0, uint32_t b1) {
  asm volatile(
      "mma.sync.aligned.m16n8k16.row.col.f32.f16.f16.f32 "
      "{%0,%1,%2,%3}, {%4,%5,%6,%7}, {%8,%9}, {%0,%1,%2,%3};"
      : "+f"(c[0]), "+f"(c[1]), "+f"(c[2]), "+f"(c[3])
      : "r"(a[0]), "r"(a[1]), "r"(a[2]), "r"(a[3]), "r"(b0), "r"(b1));
}
__device__ __forceinline__ uint16_t h_bits(__half h) {
  return *reinterpret_cast<uint16_t*>(&h);
}
__device__ __forceinline__ uint32_t pack_f16x2(float a, float b) {
  __half ha = __float2half_rn(a), hb = __float2half_rn(b);
  return (uint32_t)h_bits(ha) | ((uint32_t)h_bits(hb) << 16);
}
// 64B-row swizzle for GEMM smem
__device__ __forceinline__ uint32_t sw64(int row, int kc) {
  return (uint32_t)(row * 64 + ((kc ^ ((row >> 1) & 3)) << 4));
}

// ======================= fp16 GEMM, 1 or 2 passes (mma.sync + ldmatrix) =======================
// C = A*B^T. NPASS=2: Ah*Bh + Al*Bh (A hi/lo split). NPASS=1: Ah*Bh only.
// EPI: 0 plain fp32, 1 decay-gate fp32, 2 fused FA/GA fp16-split + compact beta.
template <int NPASS>
__device__ __forceinline__ void ld_stage(uint32_t sb, int slot, int kt, int tid,
                                         const char* a_h, const char* a_l,
                                         const char* b_h, size_t kbytes) {
  const uint32_t st = sb + (uint32_t)slot * ((NPASS + 1) * MATB);
#pragma unroll
  for (int i = 0; i < 2; i++) {
    const int chunk = i * 256 + tid;
    const int row = chunk >> 2, kc = chunk & 3;
    const uint32_t so = sw64(row, kc);
    const size_t go = (size_t)row * kbytes + (size_t)kt * 64 + (size_t)(kc << 4);
    cp_async16(st + so, a_h + go);
    if (NPASS == 2) cp_async16(st + MATB + so, a_l + go);
    cp_async16(st + NPASS * MATB + so, b_h + go);
  }
  cp_commit();
}

template <int EPI, int NPASS>
__global__ void __launch_bounds__(256, 2) gemm_f16s(
    const __half* __restrict__ Ah, const __half* __restrict__ Al,
    const __half* __restrict__ Bh,
    float* __restrict__ C, int Nn, int K, int ldc,
    const float* __restrict__ dt_bias, const float* __restrict__ A_log,
    __half* __restrict__ h1, __half* __restrict__ l1,
    __half* __restrict__ h2, __half* __restrict__ l2) {
  extern __shared__ char sm[];
  const int tid = threadIdx.x;
  const int bm = blockIdx.y * BM, bn = blockIdx.x * BN;
  const uint32_t sb = smem_u32(sm);

  const int lane = tid & 31, warp = tid >> 5;
  const int l16 = lane & 15, lh = lane >> 4;
  const int wR = warp >> 2;
  const int wC = warp & 3;

  const size_t kbytes = (size_t)K * 2;
  const char* a_h = (const char*)Ah + (size_t)bm * kbytes;
  const char* a_l = (const char*)Al + (size_t)bm * kbytes;
  const char* b_h = (const char*)Bh + (size_t)bn * kbytes;

  float acc[4][4][4];
#pragma unroll
  for (int i = 0; i < 4; i++)
#pragma unroll
    for (int j = 0; j < 4; j++)
#pragma unroll
      for (int r = 0; r < 4; r++) acc[i][j][r] = 0.f;

  const int KT = K / BK;
  for (int s = 0; s < NSTG - 1 && s < KT; s++)
    ld_stage<NPASS>(sb, s, s, tid, a_h, a_l, b_h, kbytes);

#pragma unroll 1
  for (int kt = 0; kt < KT; kt++) {
    const int slot = kt % NSTG;
    int pend = KT - 1 - kt; if (pend > NSTG - 2) pend = NSTG - 2;
    if (pend >= 2) cp_wait<2>(); else if (pend == 1) cp_wait<1>(); else cp_wait<0>();
    __syncthreads();

    const int nk = kt + NSTG - 1;
    if (nk < KT) ld_stage<NPASS>(sb, nk % NSTG, nk, tid, a_h, a_l, b_h, kbytes);

    const uint32_t st = sb + (uint32_t)slot * ((NPASS + 1) * MATB);
#pragma unroll
    for (int kk = 0; kk < 2; kk++) {
      const int kc = kk * 2 + lh;
      uint32_t afh[4][4], afl[4][4];
#pragma unroll
      for (int mt = 0; mt < 4; mt++) {
        const int arow = wR * 64 + mt * 16 + l16;
        const uint32_t ao = st + sw64(arow, kc);
        ldm_x4(afh[mt], ao);
        if (NPASS == 2) ldm_x4(afl[mt], ao + MATB);
      }
      uint32_t bfh[2][4];
#pragma unroll
      for (int p = 0; p < 2; p++) {
        const int brow = wC * 32 + p * 16 + l16;
        ldm_x4(bfh[p], st + NPASS * MATB + sw64(brow, kc));
      }
#pragma unroll
      for (int p = 0; p < 2; p++) {
#pragma unroll
        for (int mt = 0; mt < 4; mt++) {
          mma16816(acc[mt][2 * p],     afh[mt], bfh[p][0], bfh[p][2]);
          mma16816(acc[mt][2 * p + 1], afh[mt], bfh[p][1], bfh[p][3]);
          if (NPASS == 2) {
            mma16816(acc[mt][2 * p],     afl[mt], bfh[p][0], bfh[p][2]);
            mma16816(acc[mt][2 * p + 1], afl[mt], bfh[p][1], bfh[p][3]);
          }
        }
      }
    }
  }

  // epilogue
  const int gid = lane >> 2, tig = lane & 3;
#pragma unroll
  for (int mt = 0; mt < 4; mt++) {
    const int row = bm + wR * 64 + mt * 16 + gid;
#pragma unroll
    for (int nt = 0; nt < 4; nt++) {
      const int col = bn + wC * 32 + nt * 8 + tig * 2;
      if (col >= Nn) continue;
      float v[4] = {acc[mt][nt][0], acc[mt][nt][1], acc[mt][nt][2], acc[mt][nt][3]};
      if (EPI == 1) {
        const float d0 = dt_bias[col], d1 = dt_bias[col + 1];
        const float na = -expf(A_log[col >> 7]);
#pragma unroll
        for (int r = 0; r < 4; r++) {
          float x = v[r] + ((r & 1) ? d1 : d0);
          float sp = (x > 20.f) ? x : log1pf(expf(x));
          v[r] = expf(na * sp);
        }
        *reinterpret_cast<float2*>(C + (size_t)row * ldc + col) = make_float2(v[0], v[1]);
        *reinterpret_cast<float2*>(C + (size_t)(row + 8) * ldc + col) = make_float2(v[2], v[3]);
      } else if (EPI == 2) {
        if (col < 256) {
          __half* hb = (col < 128) ? h1 : h2;
          __half* lb = (col < 128) ? l1 : l2;
          const int cc = col & 127;
#pragma unroll
          for (int r = 0; r < 4; r += 2) {
            const size_t o = (size_t)(row + (r ? 8 : 0)) * 128 + cc;
            float hi0f = __half2float(__float2half_rn(v[r]));
            float hi1f = __half2float(__float2half_rn(v[r + 1]));
            *reinterpret_cast<uint32_t*>(hb + o) = pack_f16x2(v[r], v[r + 1]);
            *reinterpret_cast<uint32_t*>(lb + o) = pack_f16x2(v[r] - hi0f, v[r + 1] - hi1f);
          }
        } else {
          const int cc = col - 256;
          *reinterpret_cast<float2*>(C + (size_t)row * 32 + cc) = make_float2(v[0], v[1]);
          *reinterpret_cast<float2*>(C + (size_t)(row + 8) * 32 + cc) = make_float2(v[2], v[3]);
        }
      } else {
        *reinterpret_cast<float2*>(C + (size_t)row * ldc + col) = make_float2(v[0], v[1]);
        *reinterpret_cast<float2*>(C + (size_t)(row + 8) * ldc + col) = make_float2(v[2], v[3]);
      }
    }
  }
}

// ======================= fp32 -> fp16 hi/lo split (vectorized x4; lo optional) =======================
__global__ void __launch_bounds__(256) split_f16_kernel(
    const float* __restrict__ src,
    __half* __restrict__ hi, __half* __restrict__ lo, int total4) {
  int i = blockIdx.x * 256 + threadIdx.x;
  if (i >= total4) return;
  const int idx = i * 4;
  const float4 x = *reinterpret_cast<const float4*>(src + idx);
  uint2 hw;
  hw.x = pack_f16x2(x.x, x.y);
  hw.y = pack_f16x2(x.z, x.w);
  *reinterpret_cast<uint2*>(hi + idx) = hw;
  if (lo) {
    __half h0 = __float2half_rn(x.x), h1 = __float2half_rn(x.y);
    __half h2 = __float2half_rn(x.z), h3 = __float2half_rn(x.w);
    uint2 lw;
    lw.x = pack_f16x2(x.x - __half2float(h0), x.y - __half2float(h1));
    lw.y = pack_f16x2(x.z - __half2float(h2), x.w - __half2float(h3));
    *reinterpret_cast<uint2*>(lo + idx) = lw;
  }
}

// stacked small-weight matrix [Wfa;Wga;Wb;zeros] -> fp16 hi [384, HID]
__global__ void __launch_bounds__(256) ws_build_kernel(
    const float* __restrict__ Wfa, const float* __restrict__ Wga,
    const float* __restrict__ Wb, __half* __restrict__ hi) {
  int idx = blockIdx.x * 256 + threadIdx.x;
  if (idx >= NS_PAD * HID) return;
  int r = idx / HID, c = idx - r * HID;
  float x = 0.f;
  if (r < 128) x = Wfa[r * HID + c];
  else if (r < 256) x = Wga[(r - 128) * HID + c];
  else if (r < NS_COMB) x = Wb[(r - 256) * HID + c];
  hi[idx] = __float2half_rn(x);
}

// -------- fused depthwise causal conv(K=4) + SiLU for Q,K,V in one launch --------
__global__ void __launch_bounds__(128) conv_silu_fused_kernel(
    const float* __restrict__ QKV,
    const float* __restrict__ Wq, const float* __restrict__ Wk, const float* __restrict__ Wv,
    float* __restrict__ Qc, float* __restrict__ Kc, float* __restrict__ Vc) {
  const int type = blockIdx.x >> 5;
  const int h = blockIdx.x & 31;
  const int n = blockIdx.y;
  const int tid = threadIdx.x;
  const int c = h * DK + tid;
  const float* W = (type == 0) ? Wq : (type == 1) ? Wk : Wv;
  float* Y = (type == 0) ? Qc : (type == 1) ? Kc : Vc;
  const float* X = QKV + type * PROJ;

  float y = 0.f;
#pragma unroll
  for (int i = 0; i < 4; i++) {
    int nn = n - 3 + i;
    if (nn >= 0) y = fmaf(X[(size_t)nn * QKVN + c], W[c * 4 + i], y);
  }
  y = y / (1.f + expf(-y));  // SiLU
  if (type < 2) {
    __shared__ float red[4];
    float ss = y * y;
#pragma unroll
    for (int o = 16; o > 0; o >>= 1) ss += __shfl_xor_sync(0xffffffffu, ss, o);
    if ((tid & 31) == 0) red[tid >> 5] = ss;
    __syncthreads();
    float tot = red[0] + red[1] + red[2] + red[3];
    y *= rsqrtf(tot + 1e-6f) * ((type == 0) ? QSCALE : 1.0f);
  }
  Y[(size_t)n * PROJ + c] = y;
}

// ---------------- sequential delta-rule scan (cp.async staged; 64-thr blocks, 8 v-cols) ----------------
__device__ __forceinline__ void scan_issue(
    float* stg, int t, int warp, int lane,
    const float* K, const float* Q, const float* V, const float* EG,
    const float* BRAW, int bstride, size_t hb, int vbase, int h) {
  const size_t off = (size_t)t * PROJ + hb;
  const int r = lane >> 2, c = lane & 3;
  const int fo = r * 20 + c * 4;
  if (warp == 0) {
    const uint32_t dst = smem_u32(stg + fo);
    cp_async16(dst,               K + off + r * 16 + c * 4);
    cp_async16(dst + SQ_OFF * 4,  Q + off + r * 16 + c * 4);
  } else {
    cp_async16(smem_u32(stg + SE_OFF + fo), EG + off + r * 16 + c * 4);
    if (lane < 2)       cp_async16(smem_u32(stg + SV_OFF + lane * 4), V + off + vbase + lane * 4);
    else if (lane == 2) cp_async4(smem_u32(stg + SB_OFF), BRAW + (size_t)t * bstride + h);
  }
  cp_commit();
}

__global__ void __launch_bounds__(64, 6) scan_kernel(
    const float* __restrict__ Q, const float* __restrict__ K,
    const float* __restrict__ V, const float* __restrict__ EG,
    const float* __restrict__ BRAW, int bstride, float* __restrict__ O) {
  const int h = blockIdx.x >> 4;
  const int vbase = (blockIdx.x & 15) << 3;
  const int tid = threadIdx.x;
  const int vloc = tid >> 3;
  const int kc = tid & 7;
  const int warp = tid >> 5, lane = tid & 31;

  __shared__ __align__(16) float stg[SCAN_STG][SSTRIDE];

  float S[16];
#pragma unroll
  for (int j = 0; j < 16; j++) S[j] = 0.f;

  const size_t hb = (size_t)h * DK;

#pragma unroll
  for (int s = 0; s < SCAN_STG - 1; s++)
    scan_issue(stg[s], s, warp, lane, K, Q, V, EG, BRAW, bstride, hb, vbase, h);

#pragma unroll 1
  for (int t = 0; t < NSEQ; t++) {
    cp_wait<6>();
    __syncthreads();

    const int nt = t + SCAN_STG - 1;
    if (nt < NSEQ)
      scan_issue(stg[nt & (SCAN_STG - 1)], nt, warp, lane, K, Q, V, EG, BRAW, bstride, hb, vbase, h);
    else
      cp_commit();

    const float* base = stg[t & (SCAN_STG - 1)];
    float4 kc4[4], ec4[4], qc4[4];
    const int rb = kc * 20;
#pragma unroll
    for (int c = 0; c < 4; c++) {
      kc4[c] = *reinterpret_cast<const float4*>(base + rb + c * 4);
      ec4[c] = *reinterpret_cast<const float4*>(base + SE_OFF + rb + c * 4);
      qc4[c] = *reinterpret_cast<const float4*>(base + SQ_OFF + rb + c * 4);
    }
    const float* kf = reinterpret_cast<const float*>(kc4);
    const float* ef = reinterpret_cast<const float*>(ec4);
    const float* qf = reinterpret_cast<const float*>(qc4);

    float kv0 = 0.f, kv1 = 0.f, qs0 = 0.f, qs1 = 0.f, qk0 = 0.f, qk1 = 0.f;
#pragma unroll
    for (int j = 0; j < 16; j++) {
      const float s = S[j] * ef[j];
      S[j] = s;
      if (j & 1) {
        kv1 = fmaf(kf[j], s, kv1); qs1 = fmaf(qf[j], s, qs1); qk1 = fmaf(qf[j], kf[j], qk1);
      } else {
        kv0 = fmaf(kf[j], s, kv0); qs0 = fmaf(qf[j], s, qs0); qk0 = fmaf(qf[j], kf[j], qk0);
      }
    }
    float kv = kv0 + kv1;
    kv += __shfl_xor_sync(0xffffffffu, kv, 1);
    kv += __shfl_xor_sync(0xffffffffu, kv, 2);
    kv += __shfl_xor_sync(0xffffffffu, kv, 4);

    const float b = 1.f / (1.f + expf(-base[SB_OFF]));
    const float delta = (base[SV_OFF + vloc] - kv) * b;
#pragma unroll
    for (int j = 0; j < 16; j++) S[j] = fmaf(kf[j], delta, S[j]);

    float qs = qs0 + qs1, qk = qk0 + qk1;
#pragma unroll
    for (int o = 1; o < 8; o <<= 1) {
      qs += __shfl_xor_sync(0xffffffffu, qs, o);
      qk += __shfl_xor_sync(0xffffffffu, qk, o);
    }
    if (kc == 0) O[(size_t)t * PROJ + hb + vbase + vloc] = fmaf(qk, delta, qs);
  }
}

// -------- gated RMSNorm -> fp16 hi directly (paired 4B stores) --------
__global__ void __launch_bounds__(128) out_gate_kernel(
    const float* __restrict__ CORE, const float* __restrict__ GATE,
    const float* __restrict__ onorm_w, __half* __restrict__ hi) {
  const int h = blockIdx.x;
  const int n = blockIdx.y;
  const int tid = threadIdx.x;
  const size_t idx = (size_t)n * PROJ + h * DK + tid;
  float cv = CORE[idx];
  float ss = cv * cv;
#pragma unroll
  for (int o = 16; o > 0; o >>= 1) ss += __shfl_xor_sync(0xffffffffu, ss, o);
  __shared__ float red[4];
  if ((tid & 31) == 0) red[tid >> 5] = ss;
  __syncthreads();
  float tot = red[0] + red[1] + red[2] + red[3];
  float r = rsqrtf(tot * (1.f / 128.f) + 1e-5f);
  float gt = GATE[idx];
  float v = cv * r * onorm_w[tid] / (1.f + expf(-gt));
  uint32_t hw = h_bits(__float2half_rn(v));
  uint32_t hn = __shfl_down_sync(0xffffffffu, hw, 1);
  if ((tid & 1) == 0)
    *reinterpret_cast<uint32_t*>(hi + idx) = hw | (hn << 16);
}

// ---------------- launch ----------------
extern "C" void kernel_launch(void* const* d_in, const int* in_sizes, int n_in,
                              void* d_out, int out_size) {
  const float* hs      = (const float*)d_in[0];
  const float* Wq      = (const float*)d_in[1];
  const float* Wk      = (const float*)d_in[2];
  const float* Wv      = (const float*)d_in[3];
  const float* conv_q  = (const float*)d_in[4];
  const float* conv_k  = (const float*)d_in[5];
  const float* conv_v  = (const float*)d_in[6];
  const float* Wfa     = (const float*)d_in[7];
  const float* Wfb     = (const float*)d_in[8];
  const float* dt_bias = (const float*)d_in[9];
  const float* Wb      = (const float*)d_in[10];
  const float* A_log   = (const float*)d_in[11];
  const float* Wga     = (const float*)d_in[12];
  const float* Wgb     = (const float*)d_in[13];
  const float* onorm_w = (const float*)d_in[14];
  const float* Wo      = (const float*)d_in[15];
  float* out = (float*)d_out;

  float *QKVp, *Qc, *Kc, *Vc, *F, *GATE, *CORE, *BETA;
  __half *hsh, *hsl, *Wqkvh, *Woh, *Wfbh, *Wgbh, *WSh;
  __half *FAh, *FAl, *GAh, *GAl, *COREh;
  cudaGetSymbolAddress((void**)&QKVp,  g_QKVp);
  cudaGetSymbolAddress((void**)&Qc,    g_Qc);
  cudaGetSymbolAddress((void**)&Kc,    g_Kc);
  cudaGetSymbolAddress((void**)&Vc,    g_Vc);
  cudaGetSymbolAddress((void**)&F,     g_F);
  cudaGetSymbolAddress((void**)&GATE,  g_GATE);
  cudaGetSymbolAddress((void**)&CORE,  g_CORE);
  cudaGetSymbolAddress((void**)&BETA,  g_BETA);
  cudaGetSymbolAddress((void**)&hsh,   g_hsh);
  cudaGetSymbolAddress((void**)&hsl,   g_hsl);
  cudaGetSymbolAddress((void**)&Wqkvh, g_Wqkvh);
  cudaGetSymbolAddress((void**)&Woh,   g_Woh);
  cudaGetSymbolAddress((void**)&Wfbh,  g_Wfbh);
  cudaGetSymbolAddress((void**)&Wgbh,  g_Wgbh);
  cudaGetSymbolAddress((void**)&WSh,   g_WSh);
  cudaGetSymbolAddress((void**)&FAh,   g_FAh);
  cudaGetSymbolAddress((void**)&FAl,   g_FAl);
  cudaGetSymbolAddress((void**)&GAh,   g_GAh);
  cudaGetSymbolAddress((void**)&GAl,   g_GAl);
  cudaGetSymbolAddress((void**)&COREh, g_COREh);

  cudaFuncSetAttribute(gemm_f16s<0, 1>, cudaFuncAttributeMaxDynamicSharedMemorySize, SMEMB1);
  cudaFuncSetAttribute(gemm_f16s<2, 2>, cudaFuncAttributeMaxDynamicSharedMemorySize, SMEMB2);
  cudaFuncSetAttribute(gemm_f16s<1, 2>, cudaFuncAttributeMaxDynamicSharedMemorySize, SMEMB2);
  cudaFuncSetAttribute(gemm_f16s<0, 2>, cudaFuncAttributeMaxDynamicSharedMemorySize, SMEMB2);

  // ---- split conversions (vectorized x4) ----
  int T4;
  T4 = NSEQ * HID / 4;
  split_f16_kernel<<<(T4 + 255) / 256, 256>>>(hs, hsh, hsl, T4);
  T4 = PROJ * HID / 4;
  split_f16_kernel<<<(T4 + 255) / 256, 256>>>(Wq, Wqkvh, nullptr, T4);
  split_f16_kernel<<<(T4 + 255) / 256, 256>>>(Wk, Wqkvh + (size_t)PROJ * HID, nullptr, T4);
  split_f16_kernel<<<(T4 + 255) / 256, 256>>>(Wv, Wqkvh + (size_t)2 * PROJ * HID, nullptr, T4);
  T4 = HID * PROJ / 4;
  split_f16_kernel<<<(T4 + 255) / 256, 256>>>(Wo, Woh, nullptr, T4);
  T4 = PROJ * DK / 4;
  split_f16_kernel<<<(T4 + 255) / 256, 256>>>(Wfb, Wfbh, nullptr, T4);
  split_f16_kernel<<<(T4 + 255) / 256, 256>>>(Wgb, Wgbh, nullptr, T4);
  ws_build_kernel<<<(NS_PAD * HID + 255) / 256, 256>>>(Wfa, Wga, Wb, WSh);

  // ---- QKV: 1-pass fp16 (A hi only); COMB: 2-pass (precision for decay/gate/beta) ----
  gemm_f16s<0, 1><<<dim3(QKVN / 128, NSEQ / 128), 256, SMEMB1>>>(
      hsh, nullptr, Wqkvh, QKVp, QKVN, HID, QKVN, nullptr, nullptr,
      nullptr, nullptr, nullptr, nullptr);
  gemm_f16s<2, 2><<<dim3(3, NSEQ / 128), 256, SMEMB2>>>(
      hsh, hsl, WSh, BETA, NS_COMB, HID, 32, nullptr, nullptr,
      FAh, FAl, GAh, GAl);

  // ---- fused conv + silu (+ l2 norm for q,k) ----
  conv_silu_fused_kernel<<<dim3(3 * NH, NSEQ), 128>>>(QKVp, conv_q, conv_k, conv_v, Qc, Kc, Vc);

  // ---- low-rank second projections (K=128), 2-pass; F with fused decay epilogue ----
  gemm_f16s<1, 2><<<dim3(PROJ / 128, NSEQ / 128), 256, SMEMB2>>>(
      FAh, FAl, Wfbh, F, PROJ, DK, PROJ, dt_bias, A_log,
      nullptr, nullptr, nullptr, nullptr);
  gemm_f16s<0, 2><<<dim3(PROJ / 128, NSEQ / 128), 256, SMEMB2>>>(
      GAh, GAl, Wgbh, GATE, PROJ, DK, PROJ, nullptr, nullptr,
      nullptr, nullptr, nullptr, nullptr);

  // ---- recurrent scan ----
  scan_kernel<<<NH * 16, 64>>>(Qc, Kc, Vc, F, BETA, 32, CORE);

  // ---- gated rmsnorm -> fp16 hi ----
  dim3 gConv(NH, NSEQ);
  out_gate_kernel<<<gConv, 128>>>(CORE, GATE, onorm_w, COREh);

  // ---- output projection: 1-pass fp16 ----
  gemm_f16s<0, 1><<<dim3(HID / 128, NSEQ / 128), 256, SMEMB1>>>(
      COREh, nullptr, Woh, out, HID, PROJ, HID, nullptr, nullptr,
      nullptr, nullptr, nullptr, nullptr);
}

// round 15
// speedup vs baseline: 1.4927x; 1.0077x over previous
#include <cuda_runtime.h>
#include <cuda_fp16.h>
#include <math.h>
#include <stdint.h>

#define NSEQ 2048
#define HID  2048
#define NH   32
#define DK   128
#define PROJ 4096
#define QKVN (3 * PROJ)
#define QSCALE 0.08838834764831843f     // 128^-0.5

#define NS_COMB   288                    // Wfa(128) + Wga(128) + Wb(32)
#define NS_PAD    384

// ---- GEMM tiling ----
#define BM 128
#define BN 128
#define BK 32
#define MATB   (128 * 64)                // one matrix tile: 128 rows x 64B = 8KB
#define NSTG   4
#define SMEMB1 (NSTG * 2 * MATB)         // 1-pass: Ah,Bh = 64KB
#define SMEMB2 (NSTG * 3 * MATB)         // 2-pass: Ah,Al,Bh = 96KB

// ---- scan staging (64-thread blocks, 8 v-cols each; 16-deep cp.async ring) ----
#define SCAN_STG   16
#define SE_OFF     160
#define SQ_OFF     320
#define SV_OFF     480
#define SB_OFF     488
#define SSTRIDE    492

// ---------------- scratch (device globals; no allocation allowed) ----------------
__device__ __align__(256) float g_QKVp[NSEQ * QKVN];
__device__ __align__(256) float g_Qc[NSEQ * PROJ];
__device__ __align__(256) float g_Kc[NSEQ * PROJ];
__device__ __align__(256) float g_Vc[NSEQ * PROJ];
__device__ __align__(256) float g_F[NSEQ * PROJ];      // exp(g) written by GEMM epilogue
__device__ __align__(256) float g_GATE[NSEQ * PROJ];
__device__ __align__(256) float g_CORE[NSEQ * PROJ];
__device__ __align__(256) float g_BETA[NSEQ * 32];     // raw beta logits (compact)

__device__ __align__(256) __half g_hsh[NSEQ * HID];
__device__ __align__(256) __half g_hsl[NSEQ * HID];
__device__ __align__(256) __half g_Wqkvh[QKVN * HID];
__device__ __align__(256) __half g_Woh[HID * PROJ];
__device__ __align__(256) __half g_Wfbh[PROJ * DK];
__device__ __align__(256) __half g_Wgbh[PROJ * DK];
__device__ __align__(256) __half g_WSh[NS_PAD * HID];
__device__ __align__(256) __half g_FAh[NSEQ * DK];
__device__ __align__(256) __half g_FAl[NSEQ * DK];
__device__ __align__(256) __half g_GAh[NSEQ * DK];
__device__ __align__(256) __half g_GAl[NSEQ * DK];
__device__ __align__(256) __half g_COREh[NSEQ * PROJ];

// ============================ helpers (sm_80-portable PTX only) ============================
__device__ __forceinline__ uint32_t smem_u32(const void* p) {
  return (uint32_t)__cvta_generic_to_shared(p);
}
__device__ __forceinline__ void cp_async16(uint32_t dst, const void* src) {
  asm volatile("cp.async.cg.shared.global [%0], [%1], 16;" :: "r"(dst), "l"(src) : "memory");
}
__device__ __forceinline__ void cp_async4(uint32_t dst, const void* src) {
  asm volatile("cp.async.ca.shared.global [%0], [%1], 4;" :: "r"(dst), "l"(src) : "memory");
}
__device__ __forceinline__ void cp_commit() {
  asm volatile("cp.async.commit_group;" ::: "memory");
}
template<int N> __device__ __forceinline__ void cp_wait() {
  asm volatile("cp.async.wait_group %0;" :: "n"(N) : "memory");
}
__device__ __forceinline__ void ldm_x4(uint32_t* r, uint32_t addr) {
  asm volatile("ldmatrix.sync.aligned.m8n8.x4.shared.b16 {%0,%1,%2,%3}, [%4];"
               : "=r"(r[0]), "=r"(r[1]), "=r"(r[2]), "=r"(r[3]) : "r"(addr));
}
__device__ __forceinline__ void mma16816(float* c, const uint32_t* a,
                                         uint32_t b0, uint32_t b1) {
  asm volatile(
      "mma.sync.aligned.m16n8k16.row.col.f32.f16.f16.f32 "
      "{%0,%1,%2,%3}, {%4,%5,%6,%7}, {%8,%9}, {%0,%1,%2,%3};"
      : "+f"(c[0]), "+f"(c[1]), "+f"(c[2]), "+f"(c[3])
      : "r"(a[0]), "r"(a[1]), "r"(a[2]), "r"(a[3]), "r"(b0), "r"(b1));
}
__device__ __forceinline__ uint16_t h_bits(__half h) {
  return *reinterpret_cast<uint16_t*>(&h);
}
__device__ __forceinline__ uint32_t pack_f16x2(float a, float b) {
  __half ha = __float2half_rn(a), hb = __float2half_rn(b);
  return (uint32_t)h_bits(ha) | ((uint32_t)h_bits(hb) << 16);
}
// 64B-row swizzle for GEMM smem
__device__ __forceinline__ uint32_t sw64(int row, int kc) {
  return (uint32_t)(row * 64 + ((kc ^ ((row >> 1) & 3)) << 4));
}

// ======================= fp16 GEMM, 1 or 2 passes (mma.sync + ldmatrix) =======================
// C = A*B^T. NPASS=2: Ah*Bh + Al*Bh (A hi/lo split). NPASS=1: Ah*Bh only.
// EPI: 0 plain fp32, 1 decay-gate fp32, 2 fused FA/GA fp16-split + compact beta.
template <int NPASS>
__device__ __forceinline__ void ld_stage(uint32_t sb, int slot, int kt, int tid,
                                         const char* a_h, const char* a_l,
                                         const char* b_h, size_t kbytes) {
  const uint32_t st = sb + (uint32_t)slot * ((NPASS + 1) * MATB);
#pragma unroll
  for (int i = 0; i < 2; i++) {
    const int chunk = i * 256 + tid;
    const int row = chunk >> 2, kc = chunk & 3;
    const uint32_t so = sw64(row, kc);
    const size_t go = (size_t)row * kbytes + (size_t)kt * 64 + (size_t)(kc << 4);
    cp_async16(st + so, a_h + go);
    if (NPASS == 2) cp_async16(st + MATB + so, a_l + go);
    cp_async16(st + NPASS * MATB + so, b_h + go);
  }
  cp_commit();
}

template <int EPI, int NPASS>
__global__ void __launch_bounds__(256, 2) gemm_f16s(
    const __half* __restrict__ Ah, const __half* __restrict__ Al,
    const __half* __restrict__ Bh,
    float* __restrict__ C, int Nn, int K, int ldc,
    const float* __restrict__ dt_bias, const float* __restrict__ A_log,
    __half* __restrict__ h1, __half* __restrict__ l1,
    __half* __restrict__ h2, __half* __restrict__ l2) {
  extern __shared__ char sm[];
  const int tid = threadIdx.x;
  const int bm = blockIdx.y * BM, bn = blockIdx.x * BN;
  const uint32_t sb = smem_u32(sm);

  const int lane = tid & 31, warp = tid >> 5;
  const int l16 = lane & 15, lh = lane >> 4;
  const int wR = warp >> 2;
  const int wC = warp & 3;

  const size_t kbytes = (size_t)K * 2;
  const char* a_h = (const char*)Ah + (size_t)bm * kbytes;
  const char* a_l = (const char*)Al + (size_t)bm * kbytes;
  const char* b_h = (const char*)Bh + (size_t)bn * kbytes;

  float acc[4][4][4];
#pragma unroll
  for (int i = 0; i < 4; i++)
#pragma unroll
    for (int j = 0; j < 4; j++)
#pragma unroll
      for (int r = 0; r < 4; r++) acc[i][j][r] = 0.f;

  const int KT = K / BK;
  for (int s = 0; s < NSTG - 1 && s < KT; s++)
    ld_stage<NPASS>(sb, s, s, tid, a_h, a_l, b_h, kbytes);

#pragma unroll 1
  for (int kt = 0; kt < KT; kt++) {
    const int slot = kt % NSTG;
    int pend = KT - 1 - kt; if (pend > NSTG - 2) pend = NSTG - 2;
    if (pend >= 2) cp_wait<2>(); else if (pend == 1) cp_wait<1>(); else cp_wait<0>();
    __syncthreads();

    const int nk = kt + NSTG - 1;
    if (nk < KT) ld_stage<NPASS>(sb, nk % NSTG, nk, tid, a_h, a_l, b_h, kbytes);

    const uint32_t st = sb + (uint32_t)slot * ((NPASS + 1) * MATB);
#pragma unroll
    for (int kk = 0; kk < 2; kk++) {
      const int kc = kk * 2 + lh;
      uint32_t afh[4][4], afl[4][4];
#pragma unroll
      for (int mt = 0; mt < 4; mt++) {
        const int arow = wR * 64 + mt * 16 + l16;
        const uint32_t ao = st + sw64(arow, kc);
        ldm_x4(afh[mt], ao);
        if (NPASS == 2) ldm_x4(afl[mt], ao + MATB);
      }
      uint32_t bfh[2][4];
#pragma unroll
      for (int p = 0; p < 2; p++) {
        const int brow = wC * 32 + p * 16 + l16;
        ldm_x4(bfh[p], st + NPASS * MATB + sw64(brow, kc));
      }
#pragma unroll
      for (int p = 0; p < 2; p++) {
#pragma unroll
        for (int mt = 0; mt < 4; mt++) {
          mma16816(acc[mt][2 * p],     afh[mt], bfh[p][0], bfh[p][2]);
          mma16816(acc[mt][2 * p + 1], afh[mt], bfh[p][1], bfh[p][3]);
          if (NPASS == 2) {
            mma16816(acc[mt][2 * p],     afl[mt], bfh[p][0], bfh[p][2]);
            mma16816(acc[mt][2 * p + 1], afl[mt], bfh[p][1], bfh[p][3]);
          }
        }
      }
    }
  }

  // epilogue
  const int gid = lane >> 2, tig = lane & 3;
#pragma unroll
  for (int mt = 0; mt < 4; mt++) {
    const int row = bm + wR * 64 + mt * 16 + gid;
#pragma unroll
    for (int nt = 0; nt < 4; nt++) {
      const int col = bn + wC * 32 + nt * 8 + tig * 2;
      if (col >= Nn) continue;
      float v[4] = {acc[mt][nt][0], acc[mt][nt][1], acc[mt][nt][2], acc[mt][nt][3]};
      if (EPI == 1) {
        const float d0 = dt_bias[col], d1 = dt_bias[col + 1];
        const float na = -expf(A_log[col >> 7]);
#pragma unroll
        for (int r = 0; r < 4; r++) {
          float x = v[r] + ((r & 1) ? d1 : d0);
          float sp = (x > 20.f) ? x : log1pf(expf(x));
          v[r] = expf(na * sp);
        }
        *reinterpret_cast<float2*>(C + (size_t)row * ldc + col) = make_float2(v[0], v[1]);
        *reinterpret_cast<float2*>(C + (size_t)(row + 8) * ldc + col) = make_float2(v[2], v[3]);
      } else if (EPI == 2) {
        if (col < 256) {
          __half* hb = (col < 128) ? h1 : h2;
          __half* lb = (col < 128) ? l1 : l2;
          const int cc = col & 127;
#pragma unroll
          for (int r = 0; r < 4; r += 2) {
            const size_t o = (size_t)(row + (r ? 8 : 0)) * 128 + cc;
            float hi0f = __half2float(__float2half_rn(v[r]));
            float hi1f = __half2float(__float2half_rn(v[r + 1]));
            *reinterpret_cast<uint32_t*>(hb + o) = pack_f16x2(v[r], v[r + 1]);
            *reinterpret_cast<uint32_t*>(lb + o) = pack_f16x2(v[r] - hi0f, v[r + 1] - hi1f);
          }
        } else {
          const int cc = col - 256;
          *reinterpret_cast<float2*>(C + (size_t)row * 32 + cc) = make_float2(v[0], v[1]);
          *reinterpret_cast<float2*>(C + (size_t)(row + 8) * 32 + cc) = make_float2(v[2], v[3]);
        }
      } else {
        *reinterpret_cast<float2*>(C + (size_t)row * ldc + col) = make_float2(v[0], v[1]);
        *reinterpret_cast<float2*>(C + (size_t)(row + 8) * ldc + col) = make_float2(v[2], v[3]);
      }
    }
  }
}

// ======================= fp32 -> fp16 hi/lo split (vectorized x4; lo optional) =======================
__global__ void __launch_bounds__(256) split_f16_kernel(
    const float* __restrict__ src,
    __half* __restrict__ hi, __half* __restrict__ lo, int total4) {
  int i = blockIdx.x * 256 + threadIdx.x;
  if (i >= total4) return;
  const int idx = i * 4;
  const float4 x = *reinterpret_cast<const float4*>(src + idx);
  uint2 hw;
  hw.x = pack_f16x2(x.x, x.y);
  hw.y = pack_f16x2(x.z, x.w);
  *reinterpret_cast<uint2*>(hi + idx) = hw;
  if (lo) {
    __half h0 = __float2half_rn(x.x), h1 = __float2half_rn(x.y);
    __half h2 = __float2half_rn(x.z), h3 = __float2half_rn(x.w);
    uint2 lw;
    lw.x = pack_f16x2(x.x - __half2float(h0), x.y - __half2float(h1));
    lw.y = pack_f16x2(x.z - __half2float(h2), x.w - __half2float(h3));
    *reinterpret_cast<uint2*>(lo + idx) = lw;
  }
}

// stacked small-weight matrix [Wfa;Wga;Wb;zeros] -> fp16 hi [384, HID]
__global__ void __launch_bounds__(256) ws_build_kernel(
    const float* __restrict__ Wfa, const float* __restrict__ Wga,
    const float* __restrict__ Wb, __half* __restrict__ hi) {
  int idx = blockIdx.x * 256 + threadIdx.x;
  if (idx >= NS_PAD * HID) return;
  int r = idx / HID, c = idx - r * HID;
  float x = 0.f;
  if (r < 128) x = Wfa[r * HID + c];
  else if (r < 256) x = Wga[(r - 128) * HID + c];
  else if (r < NS_COMB) x = Wb[(r - 256) * HID + c];
  hi[idx] = __float2half_rn(x);
}

// -------- fused depthwise causal conv(K=4) + SiLU for Q,K,V in one launch --------
__global__ void __launch_bounds__(128) conv_silu_fused_kernel(
    const float* __restrict__ QKV,
    const float* __restrict__ Wq, const float* __restrict__ Wk, const float* __restrict__ Wv,
    float* __restrict__ Qc, float* __restrict__ Kc, float* __restrict__ Vc) {
  const int type = blockIdx.x >> 5;
  const int h = blockIdx.x & 31;
  const int n = blockIdx.y;
  const int tid = threadIdx.x;
  const int c = h * DK + tid;
  const float* W = (type == 0) ? Wq : (type == 1) ? Wk : Wv;
  float* Y = (type == 0) ? Qc : (type == 1) ? Kc : Vc;
  const float* X = QKV + type * PROJ;

  float y = 0.f;
#pragma unroll
  for (int i = 0; i < 4; i++) {
    int nn = n - 3 + i;
    if (nn >= 0) y = fmaf(X[(size_t)nn * QKVN + c], W[c * 4 + i], y);
  }
  y = y / (1.f + expf(-y));  // SiLU
  if (type < 2) {
    __shared__ float red[4];
    float ss = y * y;
#pragma unroll
    for (int o = 16; o > 0; o >>= 1) ss += __shfl_xor_sync(0xffffffffu, ss, o);
    if ((tid & 31) == 0) red[tid >> 5] = ss;
    __syncthreads();
    float tot = red[0] + red[1] + red[2] + red[3];
    y *= rsqrtf(tot + 1e-6f) * ((type == 0) ? QSCALE : 1.0f);
  }
  Y[(size_t)n * PROJ + c] = y;
}

// ---------------- sequential delta-rule scan (cp.async staged, depth 16) ----------------
__device__ __forceinline__ void scan_issue(
    float* stg, int t, int warp, int lane,
    const float* K, const float* Q, const float* V, const float* EG,
    const float* BRAW, int bstride, size_t hb, int vbase, int h) {
  const size_t off = (size_t)t * PROJ + hb;
  const int r = lane >> 2, c = lane & 3;
  const int fo = r * 20 + c * 4;
  if (warp == 0) {
    const uint32_t dst = smem_u32(stg + fo);
    cp_async16(dst,               K + off + r * 16 + c * 4);
    cp_async16(dst + SQ_OFF * 4,  Q + off + r * 16 + c * 4);
  } else {
    cp_async16(smem_u32(stg + SE_OFF + fo), EG + off + r * 16 + c * 4);
    if (lane < 2)       cp_async16(smem_u32(stg + SV_OFF + lane * 4), V + off + vbase + lane * 4);
    else if (lane == 2) cp_async4(smem_u32(stg + SB_OFF), BRAW + (size_t)t * bstride + h);
  }
  cp_commit();
}

__global__ void __launch_bounds__(64, 6) scan_kernel(
    const float* __restrict__ Q, const float* __restrict__ K,
    const float* __restrict__ V, const float* __restrict__ EG,
    const float* __restrict__ BRAW, int bstride, float* __restrict__ O) {
  const int h = blockIdx.x >> 4;
  const int vbase = (blockIdx.x & 15) << 3;
  const int tid = threadIdx.x;
  const int vloc = tid >> 3;
  const int kc = tid & 7;
  const int warp = tid >> 5, lane = tid & 31;

  __shared__ __align__(16) float stg[SCAN_STG][SSTRIDE];

  float S[16];
#pragma unroll
  for (int j = 0; j < 16; j++) S[j] = 0.f;

  const size_t hb = (size_t)h * DK;

#pragma unroll
  for (int s = 0; s < SCAN_STG - 1; s++)
    scan_issue(stg[s], s, warp, lane, K, Q, V, EG, BRAW, bstride, hb, vbase, h);

#pragma unroll 1
  for (int t = 0; t < NSEQ; t++) {
    cp_wait<SCAN_STG - 2>();
    __syncthreads();

    const int nt = t + SCAN_STG - 1;
    if (nt < NSEQ)
      scan_issue(stg[nt & (SCAN_STG - 1)], nt, warp, lane, K, Q, V, EG, BRAW, bstride, hb, vbase, h);
    else
      cp_commit();

    const float* base = stg[t & (SCAN_STG - 1)];
    float4 kc4[4], ec4[4], qc4[4];
    const int rb = kc * 20;
#pragma unroll
    for (int c = 0; c < 4; c++) {
      kc4[c] = *reinterpret_cast<const float4*>(base + rb + c * 4);
      ec4[c] = *reinterpret_cast<const float4*>(base + SE_OFF + rb + c * 4);
      qc4[c] = *reinterpret_cast<const float4*>(base + SQ_OFF + rb + c * 4);
    }
    const float* kf = reinterpret_cast<const float*>(kc4);
    const float* ef = reinterpret_cast<const float*>(ec4);
    const float* qf = reinterpret_cast<const float*>(qc4);

    // kv with 4 accumulators (shorter FMA chain on the carry path)
    float kva = 0.f, kvb = 0.f, kvc = 0.f, kvd = 0.f;
    float qs0 = 0.f, qs1 = 0.f, qk0 = 0.f, qk1 = 0.f;
#pragma unroll
    for (int j = 0; j < 16; j++) {
      const float s = S[j] * ef[j];
      S[j] = s;
      switch (j & 3) {
        case 0: kva = fmaf(kf[j], s, kva); break;
        case 1: kvb = fmaf(kf[j], s, kvb); break;
        case 2: kvc = fmaf(kf[j], s, kvc); break;
        default: kvd = fmaf(kf[j], s, kvd); break;
      }
      if (j & 1) { qs1 = fmaf(qf[j], s, qs1); qk1 = fmaf(qf[j], kf[j], qk1); }
      else       { qs0 = fmaf(qf[j], s, qs0); qk0 = fmaf(qf[j], kf[j], qk0); }
    }
    float kv = (kva + kvb) + (kvc + kvd);
    kv += __shfl_xor_sync(0xffffffffu, kv, 1);
    kv += __shfl_xor_sync(0xffffffffu, kv, 2);
    kv += __shfl_xor_sync(0xffffffffu, kv, 4);

    const float b = 1.f / (1.f + expf(-base[SB_OFF]));
    const float delta = (base[SV_OFF + vloc] - kv) * b;
#pragma unroll
    for (int j = 0; j < 16; j++) S[j] = fmaf(kf[j], delta, S[j]);

    float qs = qs0 + qs1, qk = qk0 + qk1;
#pragma unroll
    for (int o = 1; o < 8; o <<= 1) {
      qs += __shfl_xor_sync(0xffffffffu, qs, o);
      qk += __shfl_xor_sync(0xffffffffu, qk, o);
    }
    if (kc == 0) O[(size_t)t * PROJ + hb + vbase + vloc] = fmaf(qk, delta, qs);
  }
}

// -------- gated RMSNorm -> fp16 hi directly (paired 4B stores) --------
__global__ void __launch_bounds__(128) out_gate_kernel(
    const float* __restrict__ CORE, const float* __restrict__ GATE,
    const float* __restrict__ onorm_w, __half* __restrict__ hi) {
  const int h = blockIdx.x;
  const int n = blockIdx.y;
  const int tid = threadIdx.x;
  const size_t idx = (size_t)n * PROJ + h * DK + tid;
  float cv = CORE[idx];
  float ss = cv * cv;
#pragma unroll
  for (int o = 16; o > 0; o >>= 1) ss += __shfl_xor_sync(0xffffffffu, ss, o);
  __shared__ float red[4];
  if ((tid & 31) == 0) red[tid >> 5] = ss;
  __syncthreads();
  float tot = red[0] + red[1] + red[2] + red[3];
  float r = rsqrtf(tot * (1.f / 128.f) + 1e-5f);
  float gt = GATE[idx];
  float v = cv * r * onorm_w[tid] / (1.f + expf(-gt));
  uint32_t hw = h_bits(__float2half_rn(v));
  uint32_t hn = __shfl_down_sync(0xffffffffu, hw, 1);
  if ((tid & 1) == 0)
    *reinterpret_cast<uint32_t*>(hi + idx) = hw | (hn << 16);
}

// ---------------- launch ----------------
extern "C" void kernel_launch(void* const* d_in, const int* in_sizes, int n_in,
                              void* d_out, int out_size) {
  const float* hs      = (const float*)d_in[0];
  const float* Wq      = (const float*)d_in[1];
  const float* Wk      = (const float*)d_in[2];
  const float* Wv      = (const float*)d_in[3];
  const float* conv_q  = (const float*)d_in[4];
  const float* conv_k  = (const float*)d_in[5];
  const float* conv_v  = (const float*)d_in[6];
  const float* Wfa     = (const float*)d_in[7];
  const float* Wfb     = (const float*)d_in[8];
  const float* dt_bias = (const float*)d_in[9];
  const float* Wb      = (const float*)d_in[10];
  const float* A_log   = (const float*)d_in[11];
  const float* Wga     = (const float*)d_in[12];
  const float* Wgb     = (const float*)d_in[13];
  const float* onorm_w = (const float*)d_in[14];
  const float* Wo      = (const float*)d_in[15];
  float* out = (float*)d_out;

  float *QKVp, *Qc, *Kc, *Vc, *F, *GATE, *CORE, *BETA;
  __half *hsh, *hsl, *Wqkvh, *Woh, *Wfbh, *Wgbh, *WSh;
  __half *FAh, *FAl, *GAh, *GAl, *COREh;
  cudaGetSymbolAddress((void**)&QKVp,  g_QKVp);
  cudaGetSymbolAddress((void**)&Qc,    g_Qc);
  cudaGetSymbolAddress((void**)&Kc,    g_Kc);
  cudaGetSymbolAddress((void**)&Vc,    g_Vc);
  cudaGetSymbolAddress((void**)&F,     g_F);
  cudaGetSymbolAddress((void**)&GATE,  g_GATE);
  cudaGetSymbolAddress((void**)&CORE,  g_CORE);
  cudaGetSymbolAddress((void**)&BETA,  g_BETA);
  cudaGetSymbolAddress((void**)&hsh,   g_hsh);
  cudaGetSymbolAddress((void**)&hsl,   g_hsl);
  cudaGetSymbolAddress((void**)&Wqkvh, g_Wqkvh);
  cudaGetSymbolAddress((void**)&Woh,   g_Woh);
  cudaGetSymbolAddress((void**)&Wfbh,  g_Wfbh);
  cudaGetSymbolAddress((void**)&Wgbh,  g_Wgbh);
  cudaGetSymbolAddress((void**)&WSh,   g_WSh);
  cudaGetSymbolAddress((void**)&FAh,   g_FAh);
  cudaGetSymbolAddress((void**)&FAl,   g_FAl);
  cudaGetSymbolAddress((void**)&GAh,   g_GAh);
  cudaGetSymbolAddress((void**)&GAl,   g_GAl);
  cudaGetSymbolAddress((void**)&COREh, g_COREh);

  cudaFuncSetAttribute(gemm_f16s<0, 1>, cudaFuncAttributeMaxDynamicSharedMemorySize, SMEMB1);
  cudaFuncSetAttribute(gemm_f16s<2, 2>, cudaFuncAttributeMaxDynamicSharedMemorySize, SMEMB2);
  cudaFuncSetAttribute(gemm_f16s<1, 2>, cudaFuncAttributeMaxDynamicSharedMemorySize, SMEMB2);
  cudaFuncSetAttribute(gemm_f16s<0, 2>, cudaFuncAttributeMaxDynamicSharedMemorySize, SMEMB2);

  // ---- split conversions (vectorized x4) ----
  int T4;
  T4 = NSEQ * HID / 4;
  split_f16_kernel<<<(T4 + 255) / 256, 256>>>(hs, hsh, hsl, T4);
  T4 = PROJ * HID / 4;
  split_f16_kernel<<<(T4 + 255) / 256, 256>>>(Wq, Wqkvh, nullptr, T4);
  split_f16_kernel<<<(T4 + 255) / 256, 256>>>(Wk, Wqkvh + (size_t)PROJ * HID, nullptr, T4);
  split_f16_kernel<<<(T4 + 255) / 256, 256>>>(Wv, Wqkvh + (size_t)2 * PROJ * HID, nullptr, T4);
  T4 = HID * PROJ / 4;
  split_f16_kernel<<<(T4 + 255) / 256, 256>>>(Wo, Woh, nullptr, T4);
  T4 = PROJ * DK / 4;
  split_f16_kernel<<<(T4 + 255) / 256, 256>>>(Wfb, Wfbh, nullptr, T4);
  split_f16_kernel<<<(T4 + 255) / 256, 256>>>(Wgb, Wgbh, nullptr, T4);
  ws_build_kernel<<<(NS_PAD * HID + 255) / 256, 256>>>(Wfa, Wga, Wb, WSh);

  // ---- QKV: 1-pass fp16; COMB: 2-pass (precision for decay/gate/beta) ----
  gemm_f16s<0, 1><<<dim3(QKVN / 128, NSEQ / 128), 256, SMEMB1>>>(
      hsh, nullptr, Wqkvh, QKVp, QKVN, HID, QKVN, nullptr, nullptr,
      nullptr, nullptr, nullptr, nullptr);
  gemm_f16s<2, 2><<<dim3(3, NSEQ / 128), 256, SMEMB2>>>(
      hsh, hsl, WSh, BETA, NS_COMB, HID, 32, nullptr, nullptr,
      FAh, FAl, GAh, GAl);

  // ---- fused conv + silu (+ l2 norm for q,k) ----
  conv_silu_fused_kernel<<<dim3(3 * NH, NSEQ), 128>>>(QKVp, conv_q, conv_k, conv_v, Qc, Kc, Vc);

  // ---- low-rank second projections (K=128), 2-pass; F with fused decay epilogue ----
  gemm_f16s<1, 2><<<dim3(PROJ / 128, NSEQ / 128), 256, SMEMB2>>>(
      FAh, FAl, Wfbh, F, PROJ, DK, PROJ, dt_bias, A_log,
      nullptr, nullptr, nullptr, nullptr);
  gemm_f16s<0, 2><<<dim3(PROJ / 128, NSEQ / 128), 256, SMEMB2>>>(
      GAh, GAl, Wgbh, GATE, PROJ, DK, PROJ, nullptr, nullptr,
      nullptr, nullptr, nullptr, nullptr);

  // ---- recurrent scan (depth-16 cp.async ring) ----
  scan_kernel<<<NH * 16, 64>>>(Qc, Kc, Vc, F, BETA, 32, CORE);

  // ---- gated rmsnorm -> fp16 hi ----
  dim3 gConv(NH, NSEQ);
  out_gate_kernel<<<gConv, 128>>>(CORE, GATE, onorm_w, COREh);

  // ---- output projection: 1-pass fp16 ----
  gemm_f16s<0, 1><<<dim3(HID / 128, NSEQ / 128), 256, SMEMB1>>>(
      COREh, nullptr, Woh, out, HID, PROJ, HID, nullptr, nullptr,
      nullptr, nullptr, nullptr, nullptr);
}

// round 16
// speedup vs baseline: 1.5149x; 1.0149x over previous
#include <cuda_runtime.h>
#include <cuda_fp16.h>
#include <math.h>
#include <stdint.h>

#define NSEQ 2048
#define HID  2048
#define NH   32
#define DK   128
#define PROJ 4096
#define QKVN (3 * PROJ)
#define QSCALE 0.08838834764831843f     // 128^-0.5

#define NS_COMB   288                    // Wfa(128) + Wga(128) + Wb(32)
#define NS_PAD    384

// ---- 2-pass GEMM tiling (BK=32) ----
#define BM 128
#define BN 128
#define BK 32
#define MATB   (128 * 64)                // 8KB
#define NSTG   4
#define SMEMB2 (NSTG * 3 * MATB)         // 96KB

// ---- 1-pass GEMM tiling (BK=64) ----
#define MATB64 (128 * 128)               // 16KB
#define NSTG64 3
#define SMEMB1 (NSTG64 * 2 * MATB64)     // 96KB -> 2 CTA/SM

// ---- scan staging (128-thread blocks, 16 v-cols each; depth-8 ring) ----
#define SCAN_STG   8
#define SE_OFF     160
#define SQ_OFF     320
#define SV_OFF     480
#define SB_OFF     496
#define SSTRIDE    500

// ---------------- scratch (device globals; no allocation allowed) ----------------
__device__ __align__(256) float g_QKVp[NSEQ * QKVN];
__device__ __align__(256) float g_Qc[NSEQ * PROJ];
__device__ __align__(256) float g_Kc[NSEQ * PROJ];
__device__ __align__(256) float g_Vc[NSEQ * PROJ];
__device__ __align__(256) float g_F[NSEQ * PROJ];      // exp(g) written by GEMM epilogue
__device__ __align__(256) float g_GATE[NSEQ * PROJ];
__device__ __align__(256) float g_CORE[NSEQ * PROJ];
__device__ __align__(256) float g_BETA[NSEQ * 32];     // raw beta logits (compact)

__device__ __align__(256) __half g_hsh[NSEQ * HID];
__device__ __align__(256) __half g_hsl[NSEQ * HID];
__device__ __align__(256) __half g_Wqkvh[QKVN * HID];
__device__ __align__(256) __half g_Woh[HID * PROJ];
__device__ __align__(256) __half g_Wfbh[PROJ * DK];
__device__ __align__(256) __half g_Wgbh[PROJ * DK];
__device__ __align__(256) __half g_WSh[NS_PAD * HID];
__device__ __align__(256) __half g_FAh[NSEQ * DK];
__device__ __align__(256) __half g_FAl[NSEQ * DK];
__device__ __align__(256) __half g_GAh[NSEQ * DK];
__device__ __align__(256) __half g_GAl[NSEQ * DK];
__device__ __align__(256) __half g_COREh[NSEQ * PROJ];

// ============================ helpers (sm_80-portable PTX only) ============================
__device__ __forceinline__ uint32_t smem_u32(const void* p) {
  return (uint32_t)__cvta_generic_to_shared(p);
}
__device__ __forceinline__ void cp_async16(uint32_t dst, const void* src) {
  asm volatile("cp.async.cg.shared.global [%0], [%1], 16;" :: "r"(dst), "l"(src) : "memory");
}
__device__ __forceinline__ void cp_async4(uint32_t dst, const void* src) {
  asm volatile("cp.async.ca.shared.global [%0], [%1], 4;" :: "r"(dst), "l"(src) : "memory");
}
__device__ __forceinline__ void cp_commit() {
  asm volatile("cp.async.commit_group;" ::: "memory");
}
template<int N> __device__ __forceinline__ void cp_wait() {
  asm volatile("cp.async.wait_group %0;" :: "n"(N) : "memory");
}
__device__ __forceinline__ void ldm_x4(uint32_t* r, uint32_t addr) {
  asm volatile("ldmatrix.sync.aligned.m8n8.x4.shared.b16 {%0,%1,%2,%3}, [%4];"
               : "=r"(r[0]), "=r"(r[1]), "=r"(r[2]), "=r"(r[3]) : "r"(addr));
}
__device__ __forceinline__ void mma16816(float* c, const uint32_t* a,
                                         uint32_t b0, uint32_t b1) {
  asm volatile(
      "mma.sync.aligned.m16n8k16.row.col.f32.f16.f16.f32 "
      "{%0,%1,%2,%3}, {%4,%5,%6,%7}, {%8,%9}, {%0,%1,%2,%3};"
      : "+f"(c[0]), "+f"(c[1]), "+f"(c[2]), "+f"(c[3])
      : "r"(a[0]), "r"(a[1]), "r"(a[2]), "r"(a[3]), "r"(b0), "r"(b1));
}
__device__ __forceinline__ uint16_t h_bits(__half h) {
  return *reinterpret_cast<uint16_t*>(&h);
}
__device__ __forceinline__ uint32_t pack_f16x2(float a, float b) {
  __half ha = __float2half_rn(a), hb = __float2half_rn(b);
  return (uint32_t)h_bits(ha) | ((uint32_t)h_bits(hb) << 16);
}
// 64B-row swizzle (BK=32 tiles)
__device__ __forceinline__ uint32_t sw64(int row, int kc) {
  return (uint32_t)(row * 64 + ((kc ^ ((row >> 1) & 3)) << 4));
}
// 128B-row swizzle (BK=64 tiles) — verified conflict-free in rounds 6-7
__device__ __forceinline__ uint32_t sw128(int row, int kc) {
  return (uint32_t)(row * 128 + ((kc ^ (row & 7)) << 4));
}

// ======================= 1-pass fp16 GEMM, BK=64 (mma.sync + ldmatrix) =======================
__device__ __forceinline__ void ld_stage64(uint32_t sb, int slot, int kt, int tid,
                                           const char* a_h, const char* b_h, size_t kbytes) {
  const uint32_t st = sb + (uint32_t)slot * (2 * MATB64);
#pragma unroll
  for (int i = 0; i < 4; i++) {
    const int chunk = i * 256 + tid;          // 0..1023 = 128 rows x 8 kc
    const int row = chunk >> 3, kc = chunk & 7;
    const uint32_t so = sw128(row, kc);
    const size_t go = (size_t)row * kbytes + (size_t)kt * 128 + (size_t)(kc << 4);
    cp_async16(st + so,          a_h + go);
    cp_async16(st + MATB64 + so, b_h + go);
  }
  cp_commit();
}

__global__ void __launch_bounds__(256, 2) gemm_f16_1p(
    const __half* __restrict__ Ah, const __half* __restrict__ Bh,
    float* __restrict__ C, int Nn, int K, int ldc) {
  extern __shared__ char sm[];
  const int tid = threadIdx.x;
  const int bm = blockIdx.y * BM, bn = blockIdx.x * BN;
  const uint32_t sb = smem_u32(sm);

  const int lane = tid & 31, warp = tid >> 5;
  const int l16 = lane & 15, lh = lane >> 4;
  const int wR = warp >> 2;
  const int wC = warp & 3;

  const size_t kbytes = (size_t)K * 2;
  const char* a_h = (const char*)Ah + (size_t)bm * kbytes;
  const char* b_h = (const char*)Bh + (size_t)bn * kbytes;

  float acc[4][4][4];
#pragma unroll
  for (int i = 0; i < 4; i++)
#pragma unroll
    for (int j = 0; j < 4; j++)
#pragma unroll
      for (int r = 0; r < 4; r++) acc[i][j][r] = 0.f;

  const int KT = K >> 6;
  for (int s = 0; s < NSTG64 - 1 && s < KT; s++)
    ld_stage64(sb, s, s, tid, a_h, b_h, kbytes);

#pragma unroll 1
  for (int kt = 0; kt < KT; kt++) {
    const int slot = kt % NSTG64;
    int pend = KT - 1 - kt; if (pend > NSTG64 - 2) pend = NSTG64 - 2;
    if (pend >= 1) cp_wait<1>(); else cp_wait<0>();
    __syncthreads();

    const int nk = kt + NSTG64 - 1;
    if (nk < KT) ld_stage64(sb, nk % NSTG64, nk, tid, a_h, b_h, kbytes);

    const uint32_t st = sb + (uint32_t)slot * (2 * MATB64);
#pragma unroll
    for (int kk = 0; kk < 4; kk++) {
      const int kc = kk * 2 + lh;         // 16B chunk within 128B row
      uint32_t afh[4][4];
#pragma unroll
      for (int mt = 0; mt < 4; mt++) {
        const int arow = wR * 64 + mt * 16 + l16;
        ldm_x4(afh[mt], st + sw128(arow, kc));
      }
      uint32_t bfh[2][4];
#pragma unroll
      for (int p = 0; p < 2; p++) {
        const int brow = wC * 32 + p * 16 + l16;
        ldm_x4(bfh[p], st + MATB64 + sw128(brow, kc));
      }
#pragma unroll
      for (int p = 0; p < 2; p++) {
#pragma unroll
        for (int mt = 0; mt < 4; mt++) {
          mma16816(acc[mt][2 * p],     afh[mt], bfh[p][0], bfh[p][2]);
          mma16816(acc[mt][2 * p + 1], afh[mt], bfh[p][1], bfh[p][3]);
        }
      }
    }
  }

  const int gid = lane >> 2, tig = lane & 3;
#pragma unroll
  for (int mt = 0; mt < 4; mt++) {
    const int row = bm + wR * 64 + mt * 16 + gid;
#pragma unroll
    for (int nt = 0; nt < 4; nt++) {
      const int col = bn + wC * 32 + nt * 8 + tig * 2;
      if (col >= Nn) continue;
      *reinterpret_cast<float2*>(C + (size_t)row * ldc + col) =
          make_float2(acc[mt][nt][0], acc[mt][nt][1]);
      *reinterpret_cast<float2*>(C + (size_t)(row + 8) * ldc + col) =
          make_float2(acc[mt][nt][2], acc[mt][nt][3]);
    }
  }
}

// ======================= 2-pass fp16 hi/lo GEMM, BK=32 =======================
// EPI: 1 decay-gate fp32, 2 fused FA/GA fp16-split + compact beta, 0 plain.
__device__ __forceinline__ void ld_stage32(uint32_t sb, int slot, int kt, int tid,
                                           const char* a_h, const char* a_l,
                                           const char* b_h, size_t kbytes) {
  const uint32_t st = sb + (uint32_t)slot * (3 * MATB);
#pragma unroll
  for (int i = 0; i < 2; i++) {
    const int chunk = i * 256 + tid;
    const int row = chunk >> 2, kc = chunk & 3;
    const uint32_t so = sw64(row, kc);
    const size_t go = (size_t)row * kbytes + (size_t)kt * 64 + (size_t)(kc << 4);
    cp_async16(st + so,            a_h + go);
    cp_async16(st + MATB + so,     a_l + go);
    cp_async16(st + 2 * MATB + so, b_h + go);
  }
  cp_commit();
}

template <int EPI>
__global__ void __launch_bounds__(256, 2) gemm_f16_2p(
    const __half* __restrict__ Ah, const __half* __restrict__ Al,
    const __half* __restrict__ Bh,
    float* __restrict__ C, int Nn, int K, int ldc,
    const float* __restrict__ dt_bias, const float* __restrict__ A_log,
    __half* __restrict__ h1, __half* __restrict__ l1,
    __half* __restrict__ h2, __half* __restrict__ l2) {
  extern __shared__ char sm[];
  const int tid = threadIdx.x;
  const int bm = blockIdx.y * BM, bn = blockIdx.x * BN;
  const uint32_t sb = smem_u32(sm);

  const int lane = tid & 31, warp = tid >> 5;
  const int l16 = lane & 15, lh = lane >> 4;
  const int wR = warp >> 2;
  const int wC = warp & 3;

  const size_t kbytes = (size_t)K * 2;
  const char* a_h = (const char*)Ah + (size_t)bm * kbytes;
  const char* a_l = (const char*)Al + (size_t)bm * kbytes;
  const char* b_h = (const char*)Bh + (size_t)bn * kbytes;

  float acc[4][4][4];
#pragma unroll
  for (int i = 0; i < 4; i++)
#pragma unroll
    for (int j = 0; j < 4; j++)
#pragma unroll
      for (int r = 0; r < 4; r++) acc[i][j][r] = 0.f;

  const int KT = K / BK;
  for (int s = 0; s < NSTG - 1 && s < KT; s++)
    ld_stage32(sb, s, s, tid, a_h, a_l, b_h, kbytes);

#pragma unroll 1
  for (int kt = 0; kt < KT; kt++) {
    const int slot = kt % NSTG;
    int pend = KT - 1 - kt; if (pend > NSTG - 2) pend = NSTG - 2;
    if (pend >= 2) cp_wait<2>(); else if (pend == 1) cp_wait<1>(); else cp_wait<0>();
    __syncthreads();

    const int nk = kt + NSTG - 1;
    if (nk < KT) ld_stage32(sb, nk % NSTG, nk, tid, a_h, a_l, b_h, kbytes);

    const uint32_t st = sb + (uint32_t)slot * (3 * MATB);
#pragma unroll
    for (int kk = 0; kk < 2; kk++) {
      const int kc = kk * 2 + lh;
      uint32_t afh[4][4], afl[4][4];
#pragma unroll
      for (int mt = 0; mt < 4; mt++) {
        const int arow = wR * 64 + mt * 16 + l16;
        const uint32_t ao = st + sw64(arow, kc);
        ldm_x4(afh[mt], ao);
        ldm_x4(afl[mt], ao + MATB);
      }
      uint32_t bfh[2][4];
#pragma unroll
      for (int p = 0; p < 2; p++) {
        const int brow = wC * 32 + p * 16 + l16;
        ldm_x4(bfh[p], st + 2 * MATB + sw64(brow, kc));
      }
#pragma unroll
      for (int p = 0; p < 2; p++) {
#pragma unroll
        for (int mt = 0; mt < 4; mt++) {
          mma16816(acc[mt][2 * p],     afh[mt], bfh[p][0], bfh[p][2]);
          mma16816(acc[mt][2 * p + 1], afh[mt], bfh[p][1], bfh[p][3]);
          mma16816(acc[mt][2 * p],     afl[mt], bfh[p][0], bfh[p][2]);
          mma16816(acc[mt][2 * p + 1], afl[mt], bfh[p][1], bfh[p][3]);
        }
      }
    }
  }

  const int gid = lane >> 2, tig = lane & 3;
#pragma unroll
  for (int mt = 0; mt < 4; mt++) {
    const int row = bm + wR * 64 + mt * 16 + gid;
#pragma unroll
    for (int nt = 0; nt < 4; nt++) {
      const int col = bn + wC * 32 + nt * 8 + tig * 2;
      if (col >= Nn) continue;
      float v[4] = {acc[mt][nt][0], acc[mt][nt][1], acc[mt][nt][2], acc[mt][nt][3]};
      if (EPI == 1) {
        const float d0 = dt_bias[col], d1 = dt_bias[col + 1];
        const float na = -expf(A_log[col >> 7]);
#pragma unroll
        for (int r = 0; r < 4; r++) {
          float x = v[r] + ((r & 1) ? d1 : d0);
          float sp = (x > 20.f) ? x : log1pf(expf(x));
          v[r] = expf(na * sp);
        }
        *reinterpret_cast<float2*>(C + (size_t)row * ldc + col) = make_float2(v[0], v[1]);
        *reinterpret_cast<float2*>(C + (size_t)(row + 8) * ldc + col) = make_float2(v[2], v[3]);
      } else if (EPI == 2) {
        if (col < 256) {
          __half* hb = (col < 128) ? h1 : h2;
          __half* lb = (col < 128) ? l1 : l2;
          const int cc = col & 127;
#pragma unroll
          for (int r = 0; r < 4; r += 2) {
            const size_t o = (size_t)(row + (r ? 8 : 0)) * 128 + cc;
            float hi0f = __half2float(__float2half_rn(v[r]));
            float hi1f = __half2float(__float2half_rn(v[r + 1]));
            *reinterpret_cast<uint32_t*>(hb + o) = pack_f16x2(v[r], v[r + 1]);
            *reinterpret_cast<uint32_t*>(lb + o) = pack_f16x2(v[r] - hi0f, v[r + 1] - hi1f);
          }
        } else {
          const int cc = col - 256;
          *reinterpret_cast<float2*>(C + (size_t)row * 32 + cc) = make_float2(v[0], v[1]);
          *reinterpret_cast<float2*>(C + (size_t)(row + 8) * 32 + cc) = make_float2(v[2], v[3]);
        }
      } else {
        *reinterpret_cast<float2*>(C + (size_t)row * ldc + col) = make_float2(v[0], v[1]);
        *reinterpret_cast<float2*>(C + (size_t)(row + 8) * ldc + col) = make_float2(v[2], v[3]);
      }
    }
  }
}

// ======================= fp32 -> fp16 hi/lo split (vectorized x4; lo optional) =======================
__global__ void __launch_bounds__(256) split_f16_kernel(
    const float* __restrict__ src,
    __half* __restrict__ hi, __half* __restrict__ lo, int total4) {
  int i = blockIdx.x * 256 + threadIdx.x;
  if (i >= total4) return;
  const int idx = i * 4;
  const float4 x = *reinterpret_cast<const float4*>(src + idx);
  uint2 hw;
  hw.x = pack_f16x2(x.x, x.y);
  hw.y = pack_f16x2(x.z, x.w);
  *reinterpret_cast<uint2*>(hi + idx) = hw;
  if (lo) {
    __half h0 = __float2half_rn(x.x), h1 = __float2half_rn(x.y);
    __half h2 = __float2half_rn(x.z), h3 = __float2half_rn(x.w);
    uint2 lw;
    lw.x = pack_f16x2(x.x - __half2float(h0), x.y - __half2float(h1));
    lw.y = pack_f16x2(x.z - __half2float(h2), x.w - __half2float(h3));
    *reinterpret_cast<uint2*>(lo + idx) = lw;
  }
}

// stacked small-weight matrix [Wfa;Wga;Wb;zeros] -> fp16 hi [384, HID]
__global__ void __launch_bounds__(256) ws_build_kernel(
    const float* __restrict__ Wfa, const float* __restrict__ Wga,
    const float* __restrict__ Wb, __half* __restrict__ hi) {
  int idx = blockIdx.x * 256 + threadIdx.x;
  if (idx >= NS_PAD * HID) return;
  int r = idx / HID, c = idx - r * HID;
  float x = 0.f;
  if (r < 128) x = Wfa[r * HID + c];
  else if (r < 256) x = Wga[(r - 128) * HID + c];
  else if (r < NS_COMB) x = Wb[(r - 256) * HID + c];
  hi[idx] = __float2half_rn(x);
}

// -------- fused depthwise causal conv(K=4) + SiLU for Q,K,V in one launch --------
__global__ void __launch_bounds__(128) conv_silu_fused_kernel(
    const float* __restrict__ QKV,
    const float* __restrict__ Wq, const float* __restrict__ Wk, const float* __restrict__ Wv,
    float* __restrict__ Qc, float* __restrict__ Kc, float* __restrict__ Vc) {
  const int type = blockIdx.x >> 5;
  const int h = blockIdx.x & 31;
  const int n = blockIdx.y;
  const int tid = threadIdx.x;
  const int c = h * DK + tid;
  const float* W = (type == 0) ? Wq : (type == 1) ? Wk : Wv;
  float* Y = (type == 0) ? Qc : (type == 1) ? Kc : Vc;
  const float* X = QKV + type * PROJ;

  float y = 0.f;
#pragma unroll
  for (int i = 0; i < 4; i++) {
    int nn = n - 3 + i;
    if (nn >= 0) y = fmaf(X[(size_t)nn * QKVN + c], W[c * 4 + i], y);
  }
  y = y / (1.f + expf(-y));  // SiLU
  if (type < 2) {
    __shared__ float red[4];
    float ss = y * y;
#pragma unroll
    for (int o = 16; o > 0; o >>= 1) ss += __shfl_xor_sync(0xffffffffu, ss, o);
    if ((tid & 31) == 0) red[tid >> 5] = ss;
    __syncthreads();
    float tot = red[0] + red[1] + red[2] + red[3];
    y *= rsqrtf(tot + 1e-6f) * ((type == 0) ? QSCALE : 1.0f);
  }
  Y[(size_t)n * PROJ + c] = y;
}

// ---------------- sequential delta-rule scan (depth-8 ring; 128-thr blocks, 16 v-cols) ----------------
__device__ __forceinline__ void scan_issue(
    float* stg, int t, int warp, int lane,
    const float* K, const float* Q, const float* V, const float* EG,
    const float* BRAW, int bstride, size_t hb, int vbase, int h) {
  const size_t off = (size_t)t * PROJ + hb;
  const int r = lane >> 2, c = lane & 3;
  const int fo = r * 20 + c * 4;                 // stride-20 layout
  if (warp == 0)      cp_async16(smem_u32(stg + fo),          K  + off + r * 16 + c * 4);
  else if (warp == 1) cp_async16(smem_u32(stg + SQ_OFF + fo), Q  + off + r * 16 + c * 4);
  else if (warp == 2) cp_async16(smem_u32(stg + SE_OFF + fo), EG + off + r * 16 + c * 4);
  else {
    if (lane < 4)       cp_async16(smem_u32(stg + SV_OFF + lane * 4), V + off + vbase + lane * 4);
    else if (lane == 4) cp_async4(smem_u32(stg + SB_OFF), BRAW + (size_t)t * bstride + h);
  }
  cp_commit();   // every thread commits once -> uniform group counts
}

__global__ void __launch_bounds__(128, 4) scan_kernel(
    const float* __restrict__ Q, const float* __restrict__ K,
    const float* __restrict__ V, const float* __restrict__ EG,
    const float* __restrict__ BRAW, int bstride, float* __restrict__ O) {
  const int h = blockIdx.x >> 3;
  const int vbase = (blockIdx.x & 7) << 4;     // 16 v-cols per block
  const int tid = threadIdx.x;
  const int vloc = tid >> 3;                   // 0..15
  const int kc = tid & 7;
  const int warp = tid >> 5, lane = tid & 31;

  __shared__ __align__(16) float stg[SCAN_STG][SSTRIDE];

  float S[16];
#pragma unroll
  for (int j = 0; j < 16; j++) S[j] = 0.f;

  const size_t hb = (size_t)h * DK;

#pragma unroll
  for (int s = 0; s < SCAN_STG - 1; s++)
    scan_issue(stg[s], s, warp, lane, K, Q, V, EG, BRAW, bstride, hb, vbase, h);

#pragma unroll 1
  for (int t = 0; t < NSEQ; t++) {
    cp_wait<SCAN_STG - 2>();
    __syncthreads();

    const int nt = t + SCAN_STG - 1;
    if (nt < NSEQ)
      scan_issue(stg[nt & (SCAN_STG - 1)], nt, warp, lane, K, Q, V, EG, BRAW, bstride, hb, vbase, h);
    else
      cp_commit();

    const float* base = stg[t & (SCAN_STG - 1)];
    float4 kc4[4], ec4[4], qc4[4];
    const int rb = kc * 20;
#pragma unroll
    for (int c = 0; c < 4; c++) {
      kc4[c] = *reinterpret_cast<const float4*>(base + rb + c * 4);
      ec4[c] = *reinterpret_cast<const float4*>(base + SE_OFF + rb + c * 4);
      qc4[c] = *reinterpret_cast<const float4*>(base + SQ_OFF + rb + c * 4);
    }
    const float* kf = reinterpret_cast<const float*>(kc4);
    const float* ef = reinterpret_cast<const float*>(ec4);
    const float* qf = reinterpret_cast<const float*>(qc4);

    float kva = 0.f, kvb = 0.f, kvc = 0.f, kvd = 0.f;
    float qs0 = 0.f, qs1 = 0.f, qk0 = 0.f, qk1 = 0.f;
#pragma unroll
    for (int j = 0; j < 16; j++) {
      const float s = S[j] * ef[j];
      S[j] = s;
      switch (j & 3) {
        case 0: kva = fmaf(kf[j], s, kva); break;
        case 1: kvb = fmaf(kf[j], s, kvb); break;
        case 2: kvc = fmaf(kf[j], s, kvc); break;
        default: kvd = fmaf(kf[j], s, kvd); break;
      }
      if (j & 1) { qs1 = fmaf(qf[j], s, qs1); qk1 = fmaf(qf[j], kf[j], qk1); }
      else       { qs0 = fmaf(qf[j], s, qs0); qk0 = fmaf(qf[j], kf[j], qk0); }
    }
    float kv = (kva + kvb) + (kvc + kvd);
    kv += __shfl_xor_sync(0xffffffffu, kv, 1);
    kv += __shfl_xor_sync(0xffffffffu, kv, 2);
    kv += __shfl_xor_sync(0xffffffffu, kv, 4);

    const float b = 1.f / (1.f + expf(-base[SB_OFF]));
    const float delta = (base[SV_OFF + vloc] - kv) * b;
#pragma unroll
    for (int j = 0; j < 16; j++) S[j] = fmaf(kf[j], delta, S[j]);

    float qs = qs0 + qs1, qk = qk0 + qk1;
#pragma unroll
    for (int o = 1; o < 8; o <<= 1) {
      qs += __shfl_xor_sync(0xffffffffu, qs, o);
      qk += __shfl_xor_sync(0xffffffffu, qk, o);
    }
    if (kc == 0) O[(size_t)t * PROJ + hb + vbase + vloc] = fmaf(qk, delta, qs);
  }
}

// -------- gated RMSNorm -> fp16 hi directly (paired 4B stores) --------
__global__ void __launch_bounds__(128) out_gate_kernel(
    const float* __restrict__ CORE, const float* __restrict__ GATE,
    const float* __restrict__ onorm_w, __half* __restrict__ hi) {
  const int h = blockIdx.x;
  const int n = blockIdx.y;
  const int tid = threadIdx.x;
  const size_t idx = (size_t)n * PROJ + h * DK + tid;
  float cv = CORE[idx];
  float ss = cv * cv;
#pragma unroll
  for (int o = 16; o > 0; o >>= 1) ss += __shfl_xor_sync(0xffffffffu, ss, o);
  __shared__ float red[4];
  if ((tid & 31) == 0) red[tid >> 5] = ss;
  __syncthreads();
  float tot = red[0] + red[1] + red[2] + red[3];
  float r = rsqrtf(tot * (1.f / 128.f) + 1e-5f);
  float gt = GATE[idx];
  float v = cv * r * onorm_w[tid] / (1.f + expf(-gt));
  uint32_t hw = h_bits(__float2half_rn(v));
  uint32_t hn = __shfl_down_sync(0xffffffffu, hw, 1);
  if ((tid & 1) == 0)
    *reinterpret_cast<uint32_t*>(hi + idx) = hw | (hn << 16);
}

// ---------------- launch ----------------
extern "C" void kernel_launch(void* const* d_in, const int* in_sizes, int n_in,
                              void* d_out, int out_size) {
  const float* hs      = (const float*)d_in[0];
  const float* Wq      = (const float*)d_in[1];
  const float* Wk      = (const float*)d_in[2];
  const float* Wv      = (const float*)d_in[3];
  const float* conv_q  = (const float*)d_in[4];
  const float* conv_k  = (const float*)d_in[5];
  const float* conv_v  = (const float*)d_in[6];
  const float* Wfa     = (const float*)d_in[7];
  const float* Wfb     = (const float*)d_in[8];
  const float* dt_bias = (const float*)d_in[9];
  const float* Wb      = (const float*)d_in[10];
  const float* A_log   = (const float*)d_in[11];
  const float* Wga     = (const float*)d_in[12];
  const float* Wgb     = (const float*)d_in[13];
  const float* onorm_w = (const float*)d_in[14];
  const float* Wo      = (const float*)d_in[15];
  float* out = (float*)d_out;

  float *QKVp, *Qc, *Kc, *Vc, *F, *GATE, *CORE, *BETA;
  __half *hsh, *hsl, *Wqkvh, *Woh, *Wfbh, *Wgbh, *WSh;
  __half *FAh, *FAl, *GAh, *GAl, *COREh;
  cudaGetSymbolAddress((void**)&QKVp,  g_QKVp);
  cudaGetSymbolAddress((void**)&Qc,    g_Qc);
  cudaGetSymbolAddress((void**)&Kc,    g_Kc);
  cudaGetSymbolAddress((void**)&Vc,    g_Vc);
  cudaGetSymbolAddress((void**)&F,     g_F);
  cudaGetSymbolAddress((void**)&GATE,  g_GATE);
  cudaGetSymbolAddress((void**)&CORE,  g_CORE);
  cudaGetSymbolAddress((void**)&BETA,  g_BETA);
  cudaGetSymbolAddress((void**)&hsh,   g_hsh);
  cudaGetSymbolAddress((void**)&hsl,   g_hsl);
  cudaGetSymbolAddress((void**)&Wqkvh, g_Wqkvh);
  cudaGetSymbolAddress((void**)&Woh,   g_Woh);
  cudaGetSymbolAddress((void**)&Wfbh,  g_Wfbh);
  cudaGetSymbolAddress((void**)&Wgbh,  g_Wgbh);
  cudaGetSymbolAddress((void**)&WSh,   g_WSh);
  cudaGetSymbolAddress((void**)&FAh,   g_FAh);
  cudaGetSymbolAddress((void**)&FAl,   g_FAl);
  cudaGetSymbolAddress((void**)&GAh,   g_GAh);
  cudaGetSymbolAddress((void**)&GAl,   g_GAl);
  cudaGetSymbolAddress((void**)&COREh, g_COREh);

  cudaFuncSetAttribute(gemm_f16_1p,    cudaFuncAttributeMaxDynamicSharedMemorySize, SMEMB1);
  cudaFuncSetAttribute(gemm_f16_2p<2>, cudaFuncAttributeMaxDynamicSharedMemorySize, SMEMB2);
  cudaFuncSetAttribute(gemm_f16_2p<1>, cudaFuncAttributeMaxDynamicSharedMemorySize, SMEMB2);
  cudaFuncSetAttribute(gemm_f16_2p<0>, cudaFuncAttributeMaxDynamicSharedMemorySize, SMEMB2);

  // ---- split conversions (vectorized x4) ----
  int T4;
  T4 = NSEQ * HID / 4;
  split_f16_kernel<<<(T4 + 255) / 256, 256>>>(hs, hsh, hsl, T4);
  T4 = PROJ * HID / 4;
  split_f16_kernel<<<(T4 + 255) / 256, 256>>>(Wq, Wqkvh, nullptr, T4);
  split_f16_kernel<<<(T4 + 255) / 256, 256>>>(Wk, Wqkvh + (size_t)PROJ * HID, nullptr, T4);
  split_f16_kernel<<<(T4 + 255) / 256, 256>>>(Wv, Wqkvh + (size_t)2 * PROJ * HID, nullptr, T4);
  T4 = HID * PROJ / 4;
  split_f16_kernel<<<(T4 + 255) / 256, 256>>>(Wo, Woh, nullptr, T4);
  T4 = PROJ * DK / 4;
  split_f16_kernel<<<(T4 + 255) / 256, 256>>>(Wfb, Wfbh, nullptr, T4);
  split_f16_kernel<<<(T4 + 255) / 256, 256>>>(Wgb, Wgbh, nullptr, T4);
  ws_build_kernel<<<(NS_PAD * HID + 255) / 256, 256>>>(Wfa, Wga, Wb, WSh);

  // ---- QKV: 1-pass BK=64; COMB: 2-pass (precision for decay/gate/beta) ----
  gemm_f16_1p<<<dim3(QKVN / 128, NSEQ / 128), 256, SMEMB1>>>(
      hsh, Wqkvh, QKVp, QKVN, HID, QKVN);
  gemm_f16_2p<2><<<dim3(3, NSEQ / 128), 256, SMEMB2>>>(
      hsh, hsl, WSh, BETA, NS_COMB, HID, 32, nullptr, nullptr,
      FAh, FAl, GAh, GAl);

  // ---- fused conv + silu (+ l2 norm for q,k) ----
  conv_silu_fused_kernel<<<dim3(3 * NH, NSEQ), 128>>>(QKVp, conv_q, conv_k, conv_v, Qc, Kc, Vc);

  // ---- low-rank second projections (K=128), 2-pass; F with fused decay epilogue ----
  gemm_f16_2p<1><<<dim3(PROJ / 128, NSEQ / 128), 256, SMEMB2>>>(
      FAh, FAl, Wfbh, F, PROJ, DK, PROJ, dt_bias, A_log,
      nullptr, nullptr, nullptr, nullptr);
  gemm_f16_2p<0><<<dim3(PROJ / 128, NSEQ / 128), 256, SMEMB2>>>(
      GAh, GAl, Wgbh, GATE, PROJ, DK, PROJ, nullptr, nullptr,
      nullptr, nullptr, nullptr, nullptr);

  // ---- recurrent scan (256 blocks x 128 thr; 2x less load replication) ----
  scan_kernel<<<NH * 8, 128>>>(Qc, Kc, Vc, F, BETA, 32, CORE);

  // ---- gated rmsnorm -> fp16 hi ----
  dim3 gConv(NH, NSEQ);
  out_gate_kernel<<<gConv, 128>>>(CORE, GATE, onorm_w, COREh);

  // ---- output projection: 1-pass BK=64 ----
  gemm_f16_1p<<<dim3(HID / 128, NSEQ / 128), 256, SMEMB1>>>(
      COREh, Woh, out, HID, PROJ, HID);
}

// round 17
// speedup vs baseline: 1.5753x; 1.0399x over previous
#include <cuda_runtime.h>
#include <cuda_fp16.h>
#include <math.h>
#include <stdint.h>

#define NSEQ 2048
#define HID  2048
#define NH   32
#define DK   128
#define PROJ 4096
#define QKVN (3 * PROJ)
#define QSCALE 0.08838834764831843f     // 128^-0.5

#define NS_COMB   288                    // Wfa(128) + Wga(128) + Wb(32)
#define NS_PAD    384

// ---- 2-pass GEMM tiling (BK=32) ----
#define BM 128
#define BN 128
#define BK 32
#define MATB   (128 * 64)                // 8KB
#define NSTG   4
#define SMEMB2 (NSTG * 3 * MATB)         // 96KB

// ---- 1-pass GEMM tiling (BK=64) ----
#define MATB64 (128 * 128)               // 16KB
#define NSTG64 3
#define SMEMB1 (NSTG64 * 2 * MATB64)     // 96KB -> 2 CTA/SM

// ---- scan staging (128-thread blocks, 16 v-cols; 16-slot ring, 4 steps/window) ----
#define SCAN_STG   16
#define SCAN_LEAD  12
#define SE_OFF     160
#define SQ_OFF     320
#define SV_OFF     480
#define SB_OFF     496
#define SSTRIDE    500

// ---------------- scratch (device globals; no allocation allowed) ----------------
__device__ __align__(256) float g_QKVp[NSEQ * QKVN];
__device__ __align__(256) float g_Qc[NSEQ * PROJ];
__device__ __align__(256) float g_Kc[NSEQ * PROJ];
__device__ __align__(256) float g_Vc[NSEQ * PROJ];
__device__ __align__(256) float g_F[NSEQ * PROJ];      // exp(g) written by GEMM epilogue
__device__ __align__(256) float g_GATE[NSEQ * PROJ];
__device__ __align__(256) float g_CORE[NSEQ * PROJ];
__device__ __align__(256) float g_BETA[NSEQ * 32];     // raw beta logits (compact)

__device__ __align__(256) __half g_hsh[NSEQ * HID];
__device__ __align__(256) __half g_hsl[NSEQ * HID];
__device__ __align__(256) __half g_Wqkvh[QKVN * HID];
__device__ __align__(256) __half g_Woh[HID * PROJ];
__device__ __align__(256) __half g_Wfbh[PROJ * DK];
__device__ __align__(256) __half g_Wgbh[PROJ * DK];
__device__ __align__(256) __half g_WSh[NS_PAD * HID];
__device__ __align__(256) __half g_FAh[NSEQ * DK];
__device__ __align__(256) __half g_FAl[NSEQ * DK];
__device__ __align__(256) __half g_GAh[NSEQ * DK];
__device__ __align__(256) __half g_GAl[NSEQ * DK];
__device__ __align__(256) __half g_COREh[NSEQ * PROJ];

// ============================ helpers (sm_80-portable PTX only) ============================
__device__ __forceinline__ uint32_t smem_u32(const void* p) {
  return (uint32_t)__cvta_generic_to_shared(p);
}
__device__ __forceinline__ void cp_async16(uint32_t dst, const void* src) {
  asm volatile("cp.async.cg.shared.global [%0], [%1], 16;" :: "r"(dst), "l"(src) : "memory");
}
__device__ __forceinline__ void cp_async4(uint32_t dst, const void* src) {
  asm volatile("cp.async.ca.shared.global [%0], [%1], 4;" :: "r"(dst), "l"(src) : "memory");
}
__device__ __forceinline__ void cp_commit() {
  asm volatile("cp.async.commit_group;" ::: "memory");
}
template<int N> __device__ __forceinline__ void cp_wait() {
  asm volatile("cp.async.wait_group %0;" :: "n"(N) : "memory");
}
__device__ __forceinline__ void ldm_x4(uint32_t* r, uint32_t addr) {
  asm volatile("ldmatrix.sync.aligned.m8n8.x4.shared.b16 {%0,%1,%2,%3}, [%4];"
               : "=r"(r[0]), "=r"(r[1]), "=r"(r[2]), "=r"(r[3]) : "r"(addr));
}
__device__ __forceinline__ void mma16816(float* c, const uint32_t* a,
                                         uint32_t b0, uint32_t b1) {
  asm volatile(
      "mma.sync.aligned.m16n8k16.row.col.f32.f16.f16.f32 "
      "{%0,%1,%2,%3}, {%4,%5,%6,%7}, {%8,%9}, {%0,%1,%2,%3};"
      : "+f"(c[0]), "+f"(c[1]), "+f"(c[2]), "+f"(c[3])
      : "r"(a[0]), "r"(a[1]), "r"(a[2]), "r"(a[3]), "r"(b0), "r"(b1));
}
__device__ __forceinline__ uint16_t h_bits(__half h) {
  return *reinterpret_cast<uint16_t*>(&h);
}
__device__ __forceinline__ uint32_t pack_f16x2(float a, float b) {
  __half ha = __float2half_rn(a), hb = __float2half_rn(b);
  return (uint32_t)h_bits(ha) | ((uint32_t)h_bits(hb) << 16);
}
// 64B-row swizzle (BK=32 tiles)
__device__ __forceinline__ uint32_t sw64(int row, int kc) {
  return (uint32_t)(row * 64 + ((kc ^ ((row >> 1) & 3)) << 4));
}
// 128B-row swizzle (BK=64 tiles)
__device__ __forceinline__ uint32_t sw128(int row, int kc) {
  return (uint32_t)(row * 128 + ((kc ^ (row & 7)) << 4));
}

// ======================= 1-pass fp16 GEMM, BK=64 (mma.sync + ldmatrix) =======================
__device__ __forceinline__ void ld_stage64(uint32_t sb, int slot, int kt, int tid,
                                           const char* a_h, const char* b_h, size_t kbytes) {
  const uint32_t st = sb + (uint32_t)slot * (2 * MATB64);
#pragma unroll
  for (int i = 0; i < 4; i++) {
    const int chunk = i * 256 + tid;
    const int row = chunk >> 3, kc = chunk & 7;
    const uint32_t so = sw128(row, kc);
    const size_t go = (size_t)row * kbytes + (size_t)kt * 128 + (size_t)(kc << 4);
    cp_async16(st + so,          a_h + go);
    cp_async16(st + MATB64 + so, b_h + go);
  }
  cp_commit();
}

__global__ void __launch_bounds__(256, 2) gemm_f16_1p(
    const __half* __restrict__ Ah, const __half* __restrict__ Bh,
    float* __restrict__ C, int Nn, int K, int ldc) {
  extern __shared__ char sm[];
  const int tid = threadIdx.x;
  const int bm = blockIdx.y * BM, bn = blockIdx.x * BN;
  const uint32_t sb = smem_u32(sm);

  const int lane = tid & 31, warp = tid >> 5;
  const int l16 = lane & 15, lh = lane >> 4;
  const int wR = warp >> 2;
  const int wC = warp & 3;

  const size_t kbytes = (size_t)K * 2;
  const char* a_h = (const char*)Ah + (size_t)bm * kbytes;
  const char* b_h = (const char*)Bh + (size_t)bn * kbytes;

  float acc[4][4][4];
#pragma unroll
  for (int i = 0; i < 4; i++)
#pragma unroll
    for (int j = 0; j < 4; j++)
#pragma unroll
      for (int r = 0; r < 4; r++) acc[i][j][r] = 0.f;

  const int KT = K >> 6;
  for (int s = 0; s < NSTG64 - 1 && s < KT; s++)
    ld_stage64(sb, s, s, tid, a_h, b_h, kbytes);

#pragma unroll 1
  for (int kt = 0; kt < KT; kt++) {
    const int slot = kt % NSTG64;
    int pend = KT - 1 - kt; if (pend > NSTG64 - 2) pend = NSTG64 - 2;
    if (pend >= 1) cp_wait<1>(); else cp_wait<0>();
    __syncthreads();

    const int nk = kt + NSTG64 - 1;
    if (nk < KT) ld_stage64(sb, nk % NSTG64, nk, tid, a_h, b_h, kbytes);

    const uint32_t st = sb + (uint32_t)slot * (2 * MATB64);
#pragma unroll
    for (int kk = 0; kk < 4; kk++) {
      const int kc = kk * 2 + lh;
      uint32_t afh[4][4];
#pragma unroll
      for (int mt = 0; mt < 4; mt++) {
        const int arow = wR * 64 + mt * 16 + l16;
        ldm_x4(afh[mt], st + sw128(arow, kc));
      }
      uint32_t bfh[2][4];
#pragma unroll
      for (int p = 0; p < 2; p++) {
        const int brow = wC * 32 + p * 16 + l16;
        ldm_x4(bfh[p], st + MATB64 + sw128(brow, kc));
      }
#pragma unroll
      for (int p = 0; p < 2; p++) {
#pragma unroll
        for (int mt = 0; mt < 4; mt++) {
          mma16816(acc[mt][2 * p],     afh[mt], bfh[p][0], bfh[p][2]);
          mma16816(acc[mt][2 * p + 1], afh[mt], bfh[p][1], bfh[p][3]);
        }
      }
    }
  }

  const int gid = lane >> 2, tig = lane & 3;
#pragma unroll
  for (int mt = 0; mt < 4; mt++) {
    const int row = bm + wR * 64 + mt * 16 + gid;
#pragma unroll
    for (int nt = 0; nt < 4; nt++) {
      const int col = bn + wC * 32 + nt * 8 + tig * 2;
      if (col >= Nn) continue;
      *reinterpret_cast<float2*>(C + (size_t)row * ldc + col) =
          make_float2(acc[mt][nt][0], acc[mt][nt][1]);
      *reinterpret_cast<float2*>(C + (size_t)(row + 8) * ldc + col) =
          make_float2(acc[mt][nt][2], acc[mt][nt][3]);
    }
  }
}

// ======================= 2-pass fp16 hi/lo GEMM, BK=32 =======================
__device__ __forceinline__ void ld_stage32(uint32_t sb, int slot, int kt, int tid,
                                           const char* a_h, const char* a_l,
                                           const char* b_h, size_t kbytes) {
  const uint32_t st = sb + (uint32_t)slot * (3 * MATB);
#pragma unroll
  for (int i = 0; i < 2; i++) {
    const int chunk = i * 256 + tid;
    const int row = chunk >> 2, kc = chunk & 3;
    const uint32_t so = sw64(row, kc);
    const size_t go = (size_t)row * kbytes + (size_t)kt * 64 + (size_t)(kc << 4);
    cp_async16(st + so,            a_h + go);
    cp_async16(st + MATB + so,     a_l + go);
    cp_async16(st + 2 * MATB + so, b_h + go);
  }
  cp_commit();
}

template <int EPI>
__global__ void __launch_bounds__(256, 2) gemm_f16_2p(
    const __half* __restrict__ Ah, const __half* __restrict__ Al,
    const __half* __restrict__ Bh,
    float* __restrict__ C, int Nn, int K, int ldc,
    const float* __restrict__ dt_bias, const float* __restrict__ A_log,
    __half* __restrict__ h1, __half* __restrict__ l1,
    __half* __restrict__ h2, __half* __restrict__ l2) {
  extern __shared__ char sm[];
  const int tid = threadIdx.x;
  const int bm = blockIdx.y * BM, bn = blockIdx.x * BN;
  const uint32_t sb = smem_u32(sm);

  const int lane = tid & 31, warp = tid >> 5;
  const int l16 = lane & 15, lh = lane >> 4;
  const int wR = warp >> 2;
  const int wC = warp & 3;

  const size_t kbytes = (size_t)K * 2;
  const char* a_h = (const char*)Ah + (size_t)bm * kbytes;
  const char* a_l = (const char*)Al + (size_t)bm * kbytes;
  const char* b_h = (const char*)Bh + (size_t)bn * kbytes;

  float acc[4][4][4];
#pragma unroll
  for (int i = 0; i < 4; i++)
#pragma unroll
    for (int j = 0; j < 4; j++)
#pragma unroll
      for (int r = 0; r < 4; r++) acc[i][j][r] = 0.f;

  const int KT = K / BK;
  for (int s = 0; s < NSTG - 1 && s < KT; s++)
    ld_stage32(sb, s, s, tid, a_h, a_l, b_h, kbytes);

#pragma unroll 1
  for (int kt = 0; kt < KT; kt++) {
    const int slot = kt % NSTG;
    int pend = KT - 1 - kt; if (pend > NSTG - 2) pend = NSTG - 2;
    if (pend >= 2) cp_wait<2>(); else if (pend == 1) cp_wait<1>(); else cp_wait<0>();
    __syncthreads();

    const int nk = kt + NSTG - 1;
    if (nk < KT) ld_stage32(sb, nk % NSTG, nk, tid, a_h, a_l, b_h, kbytes);

    const uint32_t st = sb + (uint32_t)slot * (3 * MATB);
#pragma unroll
    for (int kk = 0; kk < 2; kk++) {
      const int kc = kk * 2 + lh;
      uint32_t afh[4][4], afl[4][4];
#pragma unroll
      for (int mt = 0; mt < 4; mt++) {
        const int arow = wR * 64 + mt * 16 + l16;
        const uint32_t ao = st + sw64(arow, kc);
        ldm_x4(afh[mt], ao);
        ldm_x4(afl[mt], ao + MATB);
      }
      uint32_t bfh[2][4];
#pragma unroll
      for (int p = 0; p < 2; p++) {
        const int brow = wC * 32 + p * 16 + l16;
        ldm_x4(bfh[p], st + 2 * MATB + sw64(brow, kc));
      }
#pragma unroll
      for (int p = 0; p < 2; p++) {
#pragma unroll
        for (int mt = 0; mt < 4; mt++) {
          mma16816(acc[mt][2 * p],     afh[mt], bfh[p][0], bfh[p][2]);
          mma16816(acc[mt][2 * p + 1], afh[mt], bfh[p][1], bfh[p][3]);
          mma16816(acc[mt][2 * p],     afl[mt], bfh[p][0], bfh[p][2]);
          mma16816(acc[mt][2 * p + 1], afl[mt], bfh[p][1], bfh[p][3]);
        }
      }
    }
  }

  const int gid = lane >> 2, tig = lane & 3;
#pragma unroll
  for (int mt = 0; mt < 4; mt++) {
    const int row = bm + wR * 64 + mt * 16 + gid;
#pragma unroll
    for (int nt = 0; nt < 4; nt++) {
      const int col = bn + wC * 32 + nt * 8 + tig * 2;
      if (col >= Nn) continue;
      float v[4] = {acc[mt][nt][0], acc[mt][nt][1], acc[mt][nt][2], acc[mt][nt][3]};
      if (EPI == 1) {
        const float d0 = dt_bias[col], d1 = dt_bias[col + 1];
        const float na = -expf(A_log[col >> 7]);
#pragma unroll
        for (int r = 0; r < 4; r++) {
          float x = v[r] + ((r & 1) ? d1 : d0);
          float sp = (x > 20.f) ? x : log1pf(expf(x));
          v[r] = expf(na * sp);
        }
        *reinterpret_cast<float2*>(C + (size_t)row * ldc + col) = make_float2(v[0], v[1]);
        *reinterpret_cast<float2*>(C + (size_t)(row + 8) * ldc + col) = make_float2(v[2], v[3]);
      } else if (EPI == 2) {
        if (col < 256) {
          __half* hb = (col < 128) ? h1 : h2;
          __half* lb = (col < 128) ? l1 : l2;
          const int cc = col & 127;
#pragma unroll
          for (int r = 0; r < 4; r += 2) {
            const size_t o = (size_t)(row + (r ? 8 : 0)) * 128 + cc;
            float hi0f = __half2float(__float2half_rn(v[r]));
            float hi1f = __half2float(__float2half_rn(v[r + 1]));
            *reinterpret_cast<uint32_t*>(hb + o) = pack_f16x2(v[r], v[r + 1]);
            *reinterpret_cast<uint32_t*>(lb + o) = pack_f16x2(v[r] - hi0f, v[r + 1] - hi1f);
          }
        } else {
          const int cc = col - 256;
          *reinterpret_cast<float2*>(C + (size_t)row * 32 + cc) = make_float2(v[0], v[1]);
          *reinterpret_cast<float2*>(C + (size_t)(row + 8) * 32 + cc) = make_float2(v[2], v[3]);
        }
      } else {
        *reinterpret_cast<float2*>(C + (size_t)row * ldc + col) = make_float2(v[0], v[1]);
        *reinterpret_cast<float2*>(C + (size_t)(row + 8) * ldc + col) = make_float2(v[2], v[3]);
      }
    }
  }
}

// ======================= fp32 -> fp16 hi/lo split (vectorized x4; lo optional) =======================
__global__ void __launch_bounds__(256) split_f16_kernel(
    const float* __restrict__ src,
    __half* __restrict__ hi, __half* __restrict__ lo, int total4) {
  int i = blockIdx.x * 256 + threadIdx.x;
  if (i >= total4) return;
  const int idx = i * 4;
  const float4 x = *reinterpret_cast<const float4*>(src + idx);
  uint2 hw;
  hw.x = pack_f16x2(x.x, x.y);
  hw.y = pack_f16x2(x.z, x.w);
  *reinterpret_cast<uint2*>(hi + idx) = hw;
  if (lo) {
    __half h0 = __float2half_rn(x.x), h1 = __float2half_rn(x.y);
    __half h2 = __float2half_rn(x.z), h3 = __float2half_rn(x.w);
    uint2 lw;
    lw.x = pack_f16x2(x.x - __half2float(h0), x.y - __half2float(h1));
    lw.y = pack_f16x2(x.z - __half2float(h2), x.w - __half2float(h3));
    *reinterpret_cast<uint2*>(lo + idx) = lw;
  }
}

// stacked small-weight matrix [Wfa;Wga;Wb;zeros] -> fp16 hi [384, HID]
__global__ void __launch_bounds__(256) ws_build_kernel(
    const float* __restrict__ Wfa, const float* __restrict__ Wga,
    const float* __restrict__ Wb, __half* __restrict__ hi) {
  int idx = blockIdx.x * 256 + threadIdx.x;
  if (idx >= NS_PAD * HID) return;
  int r = idx / HID, c = idx - r * HID;
  float x = 0.f;
  if (r < 128) x = Wfa[r * HID + c];
  else if (r < 256) x = Wga[(r - 128) * HID + c];
  else if (r < NS_COMB) x = Wb[(r - 256) * HID + c];
  hi[idx] = __float2half_rn(x);
}

// -------- fused depthwise causal conv(K=4) + SiLU for Q,K,V in one launch --------
__global__ void __launch_bounds__(128) conv_silu_fused_kernel(
    const float* __restrict__ QKV,
    const float* __restrict__ Wq, const float* __restrict__ Wk, const float* __restrict__ Wv,
    float* __restrict__ Qc, float* __restrict__ Kc, float* __restrict__ Vc) {
  const int type = blockIdx.x >> 5;
  const int h = blockIdx.x & 31;
  const int n = blockIdx.y;
  const int tid = threadIdx.x;
  const int c = h * DK + tid;
  const float* W = (type == 0) ? Wq : (type == 1) ? Wk : Wv;
  float* Y = (type == 0) ? Qc : (type == 1) ? Kc : Vc;
  const float* X = QKV + type * PROJ;

  float y = 0.f;
#pragma unroll
  for (int i = 0; i < 4; i++) {
    int nn = n - 3 + i;
    if (nn >= 0) y = fmaf(X[(size_t)nn * QKVN + c], W[c * 4 + i], y);
  }
  y = y / (1.f + expf(-y));  // SiLU
  if (type < 2) {
    __shared__ float red[4];
    float ss = y * y;
#pragma unroll
    for (int o = 16; o > 0; o >>= 1) ss += __shfl_xor_sync(0xffffffffu, ss, o);
    if ((tid & 31) == 0) red[tid >> 5] = ss;
    __syncthreads();
    float tot = red[0] + red[1] + red[2] + red[3];
    y *= rsqrtf(tot + 1e-6f) * ((type == 0) ? QSCALE : 1.0f);
  }
  Y[(size_t)n * PROJ + c] = y;
}

// ---------------- sequential delta-rule scan (16-slot ring, 4 steps per barrier) ----------------
__device__ __forceinline__ void scan_issue(
    float* stg, int t, int warp, int lane,
    const float* K, const float* Q, const float* V, const float* EG,
    const float* BRAW, int bstride, size_t hb, int vbase, int h) {
  const size_t off = (size_t)t * PROJ + hb;
  const int r = lane >> 2, c = lane & 3;
  const int fo = r * 20 + c * 4;
  if (warp == 0)      cp_async16(smem_u32(stg + fo),          K  + off + r * 16 + c * 4);
  else if (warp == 1) cp_async16(smem_u32(stg + SQ_OFF + fo), Q  + off + r * 16 + c * 4);
  else if (warp == 2) cp_async16(smem_u32(stg + SE_OFF + fo), EG + off + r * 16 + c * 4);
  else {
    if (lane < 4)       cp_async16(smem_u32(stg + SV_OFF + lane * 4), V + off + vbase + lane * 4);
    else if (lane == 4) cp_async4(smem_u32(stg + SB_OFF), BRAW + (size_t)t * bstride + h);
  }
  cp_commit();   // every thread commits once -> uniform group counts
}

__global__ void __launch_bounds__(128, 4) scan_kernel(
    const float* __restrict__ Q, const float* __restrict__ K,
    const float* __restrict__ V, const float* __restrict__ EG,
    const float* __restrict__ BRAW, int bstride, float* __restrict__ O) {
  const int h = blockIdx.x >> 3;
  const int vbase = (blockIdx.x & 7) << 4;     // 16 v-cols per block
  const int tid = threadIdx.x;
  const int vloc = tid >> 3;                   // 0..15
  const int kc = tid & 7;
  const int warp = tid >> 5, lane = tid & 31;

  __shared__ __align__(16) float stg[SCAN_STG][SSTRIDE];

  float S[16];
#pragma unroll
  for (int j = 0; j < 16; j++) S[j] = 0.f;

  const size_t hb = (size_t)h * DK;

  // prologue: stages 0..11 in flight
#pragma unroll
  for (int s = 0; s < SCAN_LEAD; s++)
    scan_issue(stg[s], s, warp, lane, K, Q, V, EG, BRAW, bstride, hb, vbase, h);

#pragma unroll 1
  for (int t = 0; t < NSEQ; t += 4) {
    cp_wait<SCAN_LEAD - 4>();   // 4 oldest stages (t..t+3) complete
    __syncthreads();            // visibility + guards ring reuse

    // issue stages t+12..t+15 (slots (t-4..t-1)&15: consumed last window)
#pragma unroll
    for (int d = 0; d < 4; d++) {
      const int nt = t + SCAN_LEAD + d;
      if (nt < NSEQ)
        scan_issue(stg[nt & (SCAN_STG - 1)], nt, warp, lane, K, Q, V, EG, BRAW, bstride, hb, vbase, h);
      else
        cp_commit();
    }

    // compute steps t..t+3, no barriers between (inter-step ILP)
#pragma unroll
    for (int d = 0; d < 4; d++) {
      const int tt = t + d;
      const float* base = stg[tt & (SCAN_STG - 1)];
      float4 kc4[4], ec4[4], qc4[4];
      const int rb = kc * 20;
#pragma unroll
      for (int c = 0; c < 4; c++) {
        kc4[c] = *reinterpret_cast<const float4*>(base + rb + c * 4);
        ec4[c] = *reinterpret_cast<const float4*>(base + SE_OFF + rb + c * 4);
        qc4[c] = *reinterpret_cast<const float4*>(base + SQ_OFF + rb + c * 4);
      }
      const float* kf = reinterpret_cast<const float*>(kc4);
      const float* ef = reinterpret_cast<const float*>(ec4);
      const float* qf = reinterpret_cast<const float*>(qc4);

      float kva = 0.f, kvb = 0.f, kvc = 0.f, kvd = 0.f;
      float qs0 = 0.f, qs1 = 0.f, qk0 = 0.f, qk1 = 0.f;
#pragma unroll
      for (int j = 0; j < 16; j++) {
        const float s = S[j] * ef[j];
        S[j] = s;
        switch (j & 3) {
          case 0: kva = fmaf(kf[j], s, kva); break;
          case 1: kvb = fmaf(kf[j], s, kvb); break;
          case 2: kvc = fmaf(kf[j], s, kvc); break;
          default: kvd = fmaf(kf[j], s, kvd); break;
        }
        if (j & 1) { qs1 = fmaf(qf[j], s, qs1); qk1 = fmaf(qf[j], kf[j], qk1); }
        else       { qs0 = fmaf(qf[j], s, qs0); qk0 = fmaf(qf[j], kf[j], qk0); }
      }
      float kv = (kva + kvb) + (kvc + kvd);
      kv += __shfl_xor_sync(0xffffffffu, kv, 1);
      kv += __shfl_xor_sync(0xffffffffu, kv, 2);
      kv += __shfl_xor_sync(0xffffffffu, kv, 4);

      const float b = 1.f / (1.f + expf(-base[SB_OFF]));
      const float delta = (base[SV_OFF + vloc] - kv) * b;
#pragma unroll
      for (int j = 0; j < 16; j++) S[j] = fmaf(kf[j], delta, S[j]);

      float qs = qs0 + qs1, qk = qk0 + qk1;
#pragma unroll
      for (int o = 1; o < 8; o <<= 1) {
        qs += __shfl_xor_sync(0xffffffffu, qs, o);
        qk += __shfl_xor_sync(0xffffffffu, qk, o);
      }
      if (kc == 0) O[(size_t)tt * PROJ + hb + vbase + vloc] = fmaf(qk, delta, qs);
    }
  }
}

// -------- gated RMSNorm -> fp16 hi directly (paired 4B stores) --------
__global__ void __launch_bounds__(128) out_gate_kernel(
    const float* __restrict__ CORE, const float* __restrict__ GATE,
    const float* __restrict__ onorm_w, __half* __restrict__ hi) {
  const int h = blockIdx.x;
  const int n = blockIdx.y;
  const int tid = threadIdx.x;
  const size_t idx = (size_t)n * PROJ + h * DK + tid;
  float cv = CORE[idx];
  float ss = cv * cv;
#pragma unroll
  for (int o = 16; o > 0; o >>= 1) ss += __shfl_xor_sync(0xffffffffu, ss, o);
  __shared__ float red[4];
  if ((tid & 31) == 0) red[tid >> 5] = ss;
  __syncthreads();
  float tot = red[0] + red[1] + red[2] + red[3];
  float r = rsqrtf(tot * (1.f / 128.f) + 1e-5f);
  float gt = GATE[idx];
  float v = cv * r * onorm_w[tid] / (1.f + expf(-gt));
  uint32_t hw = h_bits(__float2half_rn(v));
  uint32_t hn = __shfl_down_sync(0xffffffffu, hw, 1);
  if ((tid & 1) == 0)
    *reinterpret_cast<uint32_t*>(hi + idx) = hw | (hn << 16);
}

// ---------------- launch ----------------
extern "C" void kernel_launch(void* const* d_in, const int* in_sizes, int n_in,
                              void* d_out, int out_size) {
  const float* hs      = (const float*)d_in[0];
  const float* Wq      = (const float*)d_in[1];
  const float* Wk      = (const float*)d_in[2];
  const float* Wv      = (const float*)d_in[3];
  const float* conv_q  = (const float*)d_in[4];
  const float* conv_k  = (const float*)d_in[5];
  const float* conv_v  = (const float*)d_in[6];
  const float* Wfa     = (const float*)d_in[7];
  const float* Wfb     = (const float*)d_in[8];
  const float* dt_bias = (const float*)d_in[9];
  const float* Wb      = (const float*)d_in[10];
  const float* A_log   = (const float*)d_in[11];
  const float* Wga     = (const float*)d_in[12];
  const float* Wgb     = (const float*)d_in[13];
  const float* onorm_w = (const float*)d_in[14];
  const float* Wo      = (const float*)d_in[15];
  float* out = (float*)d_out;

  float *QKVp, *Qc, *Kc, *Vc, *F, *GATE, *CORE, *BETA;
  __half *hsh, *hsl, *Wqkvh, *Woh, *Wfbh, *Wgbh, *WSh;
  __half *FAh, *FAl, *GAh, *GAl, *COREh;
  cudaGetSymbolAddress((void**)&QKVp,  g_QKVp);
  cudaGetSymbolAddress((void**)&Qc,    g_Qc);
  cudaGetSymbolAddress((void**)&Kc,    g_Kc);
  cudaGetSymbolAddress((void**)&Vc,    g_Vc);
  cudaGetSymbolAddress((void**)&F,     g_F);
  cudaGetSymbolAddress((void**)&GATE,  g_GATE);
  cudaGetSymbolAddress((void**)&CORE,  g_CORE);
  cudaGetSymbolAddress((void**)&BETA,  g_BETA);
  cudaGetSymbolAddress((void**)&hsh,   g_hsh);
  cudaGetSymbolAddress((void**)&hsl,   g_hsl);
  cudaGetSymbolAddress((void**)&Wqkvh, g_Wqkvh);
  cudaGetSymbolAddress((void**)&Woh,   g_Woh);
  cudaGetSymbolAddress((void**)&Wfbh,  g_Wfbh);
  cudaGetSymbolAddress((void**)&Wgbh,  g_Wgbh);
  cudaGetSymbolAddress((void**)&WSh,   g_WSh);
  cudaGetSymbolAddress((void**)&FAh,   g_FAh);
  cudaGetSymbolAddress((void**)&FAl,   g_FAl);
  cudaGetSymbolAddress((void**)&GAh,   g_GAh);
  cudaGetSymbolAddress((void**)&GAl,   g_GAl);
  cudaGetSymbolAddress((void**)&COREh, g_COREh);

  cudaFuncSetAttribute(gemm_f16_1p,    cudaFuncAttributeMaxDynamicSharedMemorySize, SMEMB1);
  cudaFuncSetAttribute(gemm_f16_2p<2>, cudaFuncAttributeMaxDynamicSharedMemorySize, SMEMB2);
  cudaFuncSetAttribute(gemm_f16_2p<1>, cudaFuncAttributeMaxDynamicSharedMemorySize, SMEMB2);
  cudaFuncSetAttribute(gemm_f16_2p<0>, cudaFuncAttributeMaxDynamicSharedMemorySize, SMEMB2);

  // ---- split conversions (vectorized x4) ----
  int T4;
  T4 = NSEQ * HID / 4;
  split_f16_kernel<<<(T4 + 255) / 256, 256>>>(hs, hsh, hsl, T4);
  T4 = PROJ * HID / 4;
  split_f16_kernel<<<(T4 + 255) / 256, 256>>>(Wq, Wqkvh, nullptr, T4);
  split_f16_kernel<<<(T4 + 255) / 256, 256>>>(Wk, Wqkvh + (size_t)PROJ * HID, nullptr, T4);
  split_f16_kernel<<<(T4 + 255) / 256, 256>>>(Wv, Wqkvh + (size_t)2 * PROJ * HID, nullptr, T4);
  T4 = HID * PROJ / 4;
  split_f16_kernel<<<(T4 + 255) / 256, 256>>>(Wo, Woh, nullptr, T4);
  T4 = PROJ * DK / 4;
  split_f16_kernel<<<(T4 + 255) / 256, 256>>>(Wfb, Wfbh, nullptr, T4);
  split_f16_kernel<<<(T4 + 255) / 256, 256>>>(Wgb, Wgbh, nullptr, T4);
  ws_build_kernel<<<(NS_PAD * HID + 255) / 256, 256>>>(Wfa, Wga, Wb, WSh);

  // ---- QKV: 1-pass BK=64; COMB: 2-pass (precision for decay/gate/beta) ----
  gemm_f16_1p<<<dim3(QKVN / 128, NSEQ / 128), 256, SMEMB1>>>(
      hsh, Wqkvh, QKVp, QKVN, HID, QKVN);
  gemm_f16_2p<2><<<dim3(3, NSEQ / 128), 256, SMEMB2>>>(
      hsh, hsl, WSh, BETA, NS_COMB, HID, 32, nullptr, nullptr,
      FAh, FAl, GAh, GAl);

  // ---- fused conv + silu (+ l2 norm for q,k) ----
  conv_silu_fused_kernel<<<dim3(3 * NH, NSEQ), 128>>>(QKVp, conv_q, conv_k, conv_v, Qc, Kc, Vc);

  // ---- low-rank second projections (K=128), 2-pass; F with fused decay epilogue ----
  gemm_f16_2p<1><<<dim3(PROJ / 128, NSEQ / 128), 256, SMEMB2>>>(
      FAh, FAl, Wfbh, F, PROJ, DK, PROJ, dt_bias, A_log,
      nullptr, nullptr, nullptr, nullptr);
  gemm_f16_2p<0><<<dim3(PROJ / 128, NSEQ / 128), 256, SMEMB2>>>(
      GAh, GAl, Wgbh, GATE, PROJ, DK, PROJ, nullptr, nullptr,
      nullptr, nullptr, nullptr, nullptr);

  // ---- recurrent scan (4 steps per barrier window) ----
  scan_kernel<<<NH * 8, 128>>>(Qc, Kc, Vc, F, BETA, 32, CORE);

  // ---- gated rmsnorm -> fp16 hi ----
  dim3 gConv(NH, NSEQ);
  out_gate_kernel<<<gConv, 128>>>(CORE, GATE, onorm_w, COREh);

  // ---- output projection: 1-pass BK=64 ----
  gemm_f16_1p<<<dim3(HID / 128, NSEQ / 128), 256, SMEMB1>>>(
      COREh, Woh, out, HID, PROJ, HID);
}